// round 1
// baseline (speedup 1.0000x reference)
#include <cuda_runtime.h>
#include <math.h>

#define EMBED 1024
#define NHEAD 16
#define HDIM  64
#define BATCH 2
#define SEQQ  2048
#define SEQK  2048
#define MROWS (BATCH*SEQQ)   // 4096 rows for all projections

// Scratch (allocation-free rule: __device__ globals)
__device__ float g_Q[MROWS*EMBED];
__device__ float g_K[MROWS*EMBED];
__device__ float g_V[MROWS*EMBED];
__device__ float g_A[MROWS*EMBED];

// ---------------------------------------------------------------------------
// C[M,1024] = A[M,1024] @ W^T + bias      (W is [1024,1024] row-major, torch Linear)
// 128x128 block tile, BK=8, 256 threads, 8x8 per thread.
// ---------------------------------------------------------------------------
__global__ void __launch_bounds__(256) gemm_bias_kernel(
    const float* __restrict__ A, const float* __restrict__ W,
    const float* __restrict__ bias, float* __restrict__ C, int M)
{
    const int N = 1024, KD = 1024;
    __shared__ float As[8][128];
    __shared__ float Bs[8][128];

    const int bm = blockIdx.y * 128;
    const int bn = blockIdx.x * 128;
    const int tid = threadIdx.x;
    const int tx = tid & 15;       // 0..15  -> n
    const int ty = tid >> 4;       // 0..15  -> m

    // loader: each thread loads one float4 of A and one of W per k-step
    const int lrow = tid >> 1;          // 0..127
    const int lseg = (tid & 1) * 4;     // 0 or 4
    const float* Aptr = A + (size_t)(bm + lrow) * KD + lseg;
    const float* Wptr = W + (size_t)(bn + lrow) * KD + lseg;

    float acc[8][8];
#pragma unroll
    for (int i = 0; i < 8; i++)
#pragma unroll
        for (int j = 0; j < 8; j++) acc[i][j] = 0.f;

    for (int k0 = 0; k0 < KD; k0 += 8) {
        float4 a4 = *(const float4*)(Aptr + k0);
        float4 w4 = *(const float4*)(Wptr + k0);
        __syncthreads();   // previous iteration's reads complete
        As[lseg + 0][lrow] = a4.x; As[lseg + 1][lrow] = a4.y;
        As[lseg + 2][lrow] = a4.z; As[lseg + 3][lrow] = a4.w;
        Bs[lseg + 0][lrow] = w4.x; Bs[lseg + 1][lrow] = w4.y;
        Bs[lseg + 2][lrow] = w4.z; Bs[lseg + 3][lrow] = w4.w;
        __syncthreads();

#pragma unroll
        for (int kk = 0; kk < 8; kk++) {
            float ra[8], rb[8];
#pragma unroll
            for (int i = 0; i < 8; i++) ra[i] = As[kk][ty * 8 + i];
#pragma unroll
            for (int j = 0; j < 8; j++) rb[j] = Bs[kk][tx * 8 + j];
#pragma unroll
            for (int i = 0; i < 8; i++)
#pragma unroll
                for (int j = 0; j < 8; j++) acc[i][j] += ra[i] * rb[j];
        }
    }

#pragma unroll
    for (int i = 0; i < 8; i++) {
        const int row = bm + ty * 8 + i;
        float* crow = C + (size_t)row * N + bn + tx * 8;
#pragma unroll
        for (int j = 0; j < 8; j += 4) {
            float4 v;
            v.x = acc[i][j + 0] + bias[bn + tx * 8 + j + 0];
            v.y = acc[i][j + 1] + bias[bn + tx * 8 + j + 1];
            v.z = acc[i][j + 2] + bias[bn + tx * 8 + j + 2];
            v.w = acc[i][j + 3] + bias[bn + tx * 8 + j + 3];
            *(float4*)(crow + j) = v;
        }
    }
}

// ---------------------------------------------------------------------------
// Flash attention, fp32. One block = 128 query rows of one (b,h).
// Thread t owns query row q0+t: Q row (scaled) + O accumulator in registers.
// K/V tiles (64x64) in SMEM (broadcast reads); scores staged in SMEM [64][128].
// Dynamic smem: Ks(16KB) + Vs(16KB) + Ss(32KB) = 64KB.
// ---------------------------------------------------------------------------
__global__ void __launch_bounds__(128) attn_kernel(
    const float* __restrict__ Q, const float* __restrict__ K,
    const float* __restrict__ V, float* __restrict__ O)
{
    extern __shared__ float sm[];
    float* Ks = sm;                 // [64][64]
    float* Vs = sm + 64 * 64;       // [64][64]
    float* Ss = sm + 2 * 64 * 64;   // [64][128]  (also Q staging: 128*64)

    const int tid = threadIdx.x;
    const int b = blockIdx.z, h = blockIdx.y;
    const int q0 = blockIdx.x * 128;
    const float scale = 0.125f;     // 1/sqrt(64)

    // --- stage Q tile (coalesced), then copy own row to regs ---
    const float* Qg = Q + ((size_t)b * SEQQ + q0) * EMBED + h * HDIM;
#pragma unroll
    for (int i = 0; i < 16; i++) {
        int f4 = i * 128 + tid;
        int row = f4 >> 4, c4 = f4 & 15;
        ((float4*)Ss)[f4] = *(const float4*)(Qg + (size_t)row * EMBED + c4 * 4);
    }
    __syncthreads();

    float q[HDIM], o[HDIM];
#pragma unroll
    for (int d = 0; d < HDIM; d++) { q[d] = Ss[tid * 64 + d] * scale; o[d] = 0.f; }
    float m = -1e30f, l = 0.f;

    const float* Kg = K + (size_t)b * SEQK * EMBED + h * HDIM;
    const float* Vg = V + (size_t)b * SEQK * EMBED + h * HDIM;

    for (int kt = 0; kt < SEQK; kt += 64) {
        __syncthreads();
        // load K and V tiles (64x64 each), coalesced float4
#pragma unroll
        for (int i = 0; i < 8; i++) {
            int f4 = i * 128 + tid;
            int row = f4 >> 4, c4 = f4 & 15;
            ((float4*)Ks)[f4] = *(const float4*)(Kg + (size_t)(kt + row) * EMBED + c4 * 4);
            ((float4*)Vs)[f4] = *(const float4*)(Vg + (size_t)(kt + row) * EMBED + c4 * 4);
        }
        __syncthreads();

        // scores: s_j = (q . K_j)   (q already scaled)
        for (int j = 0; j < 64; j++) {
            float acc = 0.f;
            const float* kr = &Ks[j * 64];
#pragma unroll
            for (int d = 0; d < HDIM; d++) acc += q[d] * kr[d];
            Ss[j * 128 + tid] = acc;
        }

        // online softmax
        float mt = m;
        for (int j = 0; j < 64; j++) mt = fmaxf(mt, Ss[j * 128 + tid]);
        const float alpha = __expf(m - mt);
        float lsum = 0.f;
        for (int j = 0; j < 64; j++) {
            float p = __expf(Ss[j * 128 + tid] - mt);
            Ss[j * 128 + tid] = p;
            lsum += p;
        }
        l = l * alpha + lsum;
        m = mt;

#pragma unroll
        for (int d = 0; d < HDIM; d++) o[d] *= alpha;

        // O += P @ V
        for (int j = 0; j < 64; j++) {
            const float p = Ss[j * 128 + tid];
            const float* vr = &Vs[j * 64];
#pragma unroll
            for (int d = 0; d < HDIM; d++) o[d] += p * vr[d];
        }
    }

    const float inv = 1.f / l;
    float* Og = O + ((size_t)b * SEQQ + q0 + tid) * EMBED + h * HDIM;
#pragma unroll
    for (int d = 0; d < HDIM; d += 4) {
        float4 v;
        v.x = o[d + 0] * inv; v.y = o[d + 1] * inv;
        v.z = o[d + 2] * inv; v.w = o[d + 3] * inv;
        *(float4*)(Og + d) = v;
    }
}

// ---------------------------------------------------------------------------
extern "C" void kernel_launch(void* const* d_in, const int* in_sizes, int n_in,
                              void* d_out, int out_size)
{
    const float* Qin = (const float*)d_in[0];
    const float* Kin = (const float*)d_in[1];
    const float* Vin = (const float*)d_in[2];
    const float* Wq  = (const float*)d_in[3];
    const float* bq  = (const float*)d_in[4];
    const float* Wk  = (const float*)d_in[5];
    const float* bk  = (const float*)d_in[6];
    const float* Wv  = (const float*)d_in[7];
    const float* bv  = (const float*)d_in[8];
    const float* Wo  = (const float*)d_in[9];
    const float* bo  = (const float*)d_in[10];
    float* out = (float*)d_out;

    float *gQ, *gK, *gV, *gA;
    cudaGetSymbolAddress((void**)&gQ, g_Q);
    cudaGetSymbolAddress((void**)&gK, g_K);
    cudaGetSymbolAddress((void**)&gV, g_V);
    cudaGetSymbolAddress((void**)&gA, g_A);

    const int ATTN_SMEM = (2 * 64 * 64 + 64 * 128) * sizeof(float); // 64KB
    cudaFuncSetAttribute(attn_kernel, cudaFuncAttributeMaxDynamicSharedMemorySize, ATTN_SMEM);

    dim3 gemm_grid(EMBED / 128, MROWS / 128);   // (8, 32)
    gemm_bias_kernel<<<gemm_grid, 256>>>(Qin, Wq, bq, gQ, MROWS);
    gemm_bias_kernel<<<gemm_grid, 256>>>(Kin, Wk, bk, gK, MROWS);
    gemm_bias_kernel<<<gemm_grid, 256>>>(Vin, Wv, bv, gV, MROWS);

    dim3 attn_grid(SEQQ / 128, NHEAD, BATCH);   // (16, 16, 2)
    attn_kernel<<<attn_grid, 128, ATTN_SMEM>>>(gQ, gK, gV, gA);

    gemm_bias_kernel<<<gemm_grid, 256>>>(gA, Wo, bo, out, MROWS);
}

// round 4
// speedup vs baseline: 1.3851x; 1.3851x over previous
#include <cuda_runtime.h>
#include <cuda_bf16.h>
#include <cstdint>
#include <math.h>

#define EMBED 1024
#define NHEAD 16
#define HDIM  64
#define BATCH 2
#define SEQQ  2048
#define SEQK  2048
#define MROWS (BATCH*SEQQ)   // 4096

// ----------------------------- scratch (no allocs allowed) -----------------
__device__ float g_Q[MROWS*EMBED];
__device__ float g_K[MROWS*EMBED];
__device__ float g_V[MROWS*EMBED];
__device__ float g_A[MROWS*EMBED];

__device__ __nv_bfloat16 g_QiH[MROWS*EMBED], g_QiL[MROWS*EMBED];
__device__ __nv_bfloat16 g_KiH[MROWS*EMBED], g_KiL[MROWS*EMBED];
__device__ __nv_bfloat16 g_ViH[MROWS*EMBED], g_ViL[MROWS*EMBED];
__device__ __nv_bfloat16 g_AH [MROWS*EMBED], g_AL [MROWS*EMBED];
__device__ __nv_bfloat16 g_WqH[EMBED*EMBED], g_WqL[EMBED*EMBED];
__device__ __nv_bfloat16 g_WkH[EMBED*EMBED], g_WkL[EMBED*EMBED];
__device__ __nv_bfloat16 g_WvH[EMBED*EMBED], g_WvL[EMBED*EMBED];
__device__ __nv_bfloat16 g_WoH[EMBED*EMBED], g_WoL[EMBED*EMBED];

// ----------------------------- helpers -------------------------------------
__device__ __forceinline__ uint32_t smem_u32(const void* p) {
    uint32_t a;
    asm("{ .reg .u64 t; cvta.to.shared.u64 t, %1; cvt.u32.u64 %0, t; }" : "=r"(a) : "l"(p));
    return a;
}
#define CP_ASYNC16(dst, src) \
    asm volatile("cp.async.cg.shared.global [%0], [%1], 16;" :: "r"(dst), "l"(src))
#define CP_COMMIT() asm volatile("cp.async.commit_group;" ::: "memory")
#define CP_WAIT(n)  asm volatile("cp.async.wait_group %0;" :: "n"(n) : "memory")

__device__ __forceinline__ void ldsm_x4(uint32_t* r, uint32_t addr) {
    asm volatile("ldmatrix.sync.aligned.m8n8.x4.shared.b16 {%0,%1,%2,%3}, [%4];"
        : "=r"(r[0]), "=r"(r[1]), "=r"(r[2]), "=r"(r[3]) : "r"(addr));
}
__device__ __forceinline__ void mma_bf16(float* c, const uint32_t* a, const uint32_t* b) {
    asm volatile(
        "mma.sync.aligned.m16n8k16.row.col.f32.bf16.bf16.f32 "
        "{%0,%1,%2,%3}, {%4,%5,%6,%7}, {%8,%9}, {%0,%1,%2,%3};"
        : "+f"(c[0]), "+f"(c[1]), "+f"(c[2]), "+f"(c[3])
        : "r"(a[0]), "r"(a[1]), "r"(a[2]), "r"(a[3]), "r"(b[0]), "r"(b[1]));
}

// ----------------------------- fp32 -> bf16 hi/lo split --------------------
__global__ void split_kernel(const float* __restrict__ x,
                             __nv_bfloat16* __restrict__ hi,
                             __nv_bfloat16* __restrict__ lo, int n4)
{
    int i = blockIdx.x * blockDim.x + threadIdx.x;
    if (i >= n4) return;
    float4 v = ((const float4*)x)[i];
    __nv_bfloat16 h0 = __float2bfloat16(v.x), h1 = __float2bfloat16(v.y);
    __nv_bfloat16 h2 = __float2bfloat16(v.z), h3 = __float2bfloat16(v.w);
    __nv_bfloat16 l0 = __float2bfloat16(v.x - __bfloat162float(h0));
    __nv_bfloat16 l1 = __float2bfloat16(v.y - __bfloat162float(h1));
    __nv_bfloat16 l2 = __float2bfloat16(v.z - __bfloat162float(h2));
    __nv_bfloat16 l3 = __float2bfloat16(v.w - __bfloat162float(h3));
    __nv_bfloat162* hp = (__nv_bfloat162*)hi;
    __nv_bfloat162* lp = (__nv_bfloat162*)lo;
    hp[2*i]   = __nv_bfloat162{h0, h1};
    hp[2*i+1] = __nv_bfloat162{h2, h3};
    lp[2*i]   = __nv_bfloat162{l0, l1};
    lp[2*i+1] = __nv_bfloat162{l2, l3};
}

// ----------------------------- HMMA GEMM -----------------------------------
// C[M,1024] = A @ W^T + bias.  A[M,1024], W[1024,1024] both K-major, split
// into bf16 hi/lo.  3-term compensated MMA: AhBh + AhBl + AlBh (fp32 acc).
// Block 128x128, 8 warps (2x4), warp tile 64x32, BK=64, cp.async double-buffer.
#define GS_TILE  16384                  // one 128x64 bf16 tile
#define GS_STAGE (4*GS_TILE)            // Ah Al Bh Bl
#define GS_SMEM  (2*GS_STAGE)           // 131072

__global__ void __launch_bounds__(256, 1) gemm_mma_kernel(
    const __nv_bfloat16* __restrict__ Ah, const __nv_bfloat16* __restrict__ Al,
    const __nv_bfloat16* __restrict__ Bh, const __nv_bfloat16* __restrict__ Bl,
    const float* __restrict__ bias, float* __restrict__ C)
{
    extern __shared__ char sm[];
    const uint32_t sbase = smem_u32(sm);
    const int tid = threadIdx.x;
    const int lane = tid & 31, wid = tid >> 5;
    const int wm = wid & 1, wn = wid >> 1;          // 2 x 4 warp grid
    const int m0 = blockIdx.y * 128, n0 = blockIdx.x * 128;

    float acc[4][4][4];
#pragma unroll
    for (int i = 0; i < 4; i++)
#pragma unroll
        for (int j = 0; j < 4; j++)
#pragma unroll
            for (int k = 0; k < 4; k++) acc[i][j][k] = 0.f;

#define ISSUE_STAGE(buf, k0)                                                   \
    do {                                                                       \
        const uint32_t st = sbase + (buf) * GS_STAGE;                          \
        _Pragma("unroll")                                                      \
        for (int c = 0; c < 4; c++) {                                          \
            const int idx = c * 256 + tid;                                     \
            const int row = idx >> 3, seg = idx & 7;                           \
            uint32_t off = (uint32_t)(row * 128 + seg * 16);                   \
            off ^= ((off >> 3) & 0x70);                                        \
            const size_t ga = (size_t)(m0 + row) * 1024 + (k0) + seg * 8;      \
            const size_t gb = (size_t)(n0 + row) * 1024 + (k0) + seg * 8;      \
            CP_ASYNC16(st + off,               (const char*)(Ah + ga));        \
            CP_ASYNC16(st + GS_TILE + off,     (const char*)(Al + ga));        \
            CP_ASYNC16(st + 2 * GS_TILE + off, (const char*)(Bh + gb));        \
            CP_ASYNC16(st + 3 * GS_TILE + off, (const char*)(Bl + gb));        \
        }                                                                      \
    } while (0)

    ISSUE_STAGE(0, 0);
    CP_COMMIT();

    for (int s = 0; s < 16; s++) {
        if (s < 15) {
            ISSUE_STAGE((s + 1) & 1, (s + 1) * 64);
            CP_COMMIT();
            CP_WAIT(1);
        } else {
            CP_WAIT(0);
        }
        __syncthreads();

        const uint32_t st = sbase + (s & 1) * GS_STAGE;
#pragma unroll
        for (int ks = 0; ks < 4; ks++) {
            uint32_t ah[4][4], al[4][4], bh[2][4], bl[2][4];
            // A fragments: rows wm*64 + mt*16, k = ks*16
            const int ar = (lane & 7) + ((lane >> 3) & 1) * 8;   // lane%16
            const int ak = ks * 16 + ((lane >> 4) & 1) * 8;
#pragma unroll
            for (int mt = 0; mt < 4; mt++) {
                uint32_t off = (uint32_t)((wm * 64 + mt * 16 + ar) * 128 + ak * 2);
                off ^= ((off >> 3) & 0x70);
                ldsm_x4(ah[mt], st + off);
                ldsm_x4(al[mt], st + GS_TILE + off);
            }
            // B fragments: W stored [n][k] k-contiguous -> NON-trans ldmatrix.
            // matrices: (n0-7,k0-7) (n0-7,k8-15) (n8-15,k0-7) (n8-15,k8-15)
            const int bn = (lane & 7) + ((lane >> 4) & 1) * 8;
            const int bk = ks * 16 + ((lane >> 3) & 1) * 8;
#pragma unroll
            for (int np = 0; np < 2; np++) {
                uint32_t off = (uint32_t)((wn * 32 + np * 16 + bn) * 128 + bk * 2);
                off ^= ((off >> 3) & 0x70);
                ldsm_x4(bh[np], st + 2 * GS_TILE + off);
                ldsm_x4(bl[np], st + 3 * GS_TILE + off);
            }
#pragma unroll
            for (int mt = 0; mt < 4; mt++) {
#pragma unroll
                for (int nt = 0; nt < 4; nt++) {
                    const uint32_t* bhf = &bh[nt >> 1][(nt & 1) * 2];
                    const uint32_t* blf = &bl[nt >> 1][(nt & 1) * 2];
                    mma_bf16(acc[mt][nt], ah[mt], bhf);
                    mma_bf16(acc[mt][nt], ah[mt], blf);
                    mma_bf16(acc[mt][nt], al[mt], bhf);
                }
            }
        }
        __syncthreads();
    }
#undef ISSUE_STAGE

    // epilogue: c0,c1 -> (row, col..col+1); c2,c3 -> (row+8, ...)
#pragma unroll
    for (int mt = 0; mt < 4; mt++) {
        const int row = m0 + wm * 64 + mt * 16 + (lane >> 2);
#pragma unroll
        for (int nt = 0; nt < 4; nt++) {
            const int col = n0 + wn * 32 + nt * 8 + (lane & 3) * 2;
            const float bx = __ldg(bias + col), by = __ldg(bias + col + 1);
            float2 v0 = { acc[mt][nt][0] + bx, acc[mt][nt][1] + by };
            float2 v1 = { acc[mt][nt][2] + bx, acc[mt][nt][3] + by };
            *(float2*)(C + (size_t)row * 1024 + col)       = v0;
            *(float2*)(C + (size_t)(row + 8) * 1024 + col) = v1;
        }
    }
}

// ----------------------------- flash attention (fp32, proven) --------------
__global__ void __launch_bounds__(128) attn_kernel(
    const float* __restrict__ Q, const float* __restrict__ K,
    const float* __restrict__ V, float* __restrict__ O)
{
    extern __shared__ float smf[];
    float* Ks = smf;
    float* Vs = smf + 64 * 64;
    float* Ss = smf + 2 * 64 * 64;   // [64][128]

    const int tid = threadIdx.x;
    const int b = blockIdx.z, h = blockIdx.y;
    const int q0 = blockIdx.x * 128;
    const float scale = 0.125f;

    const float* Qg = Q + ((size_t)b * SEQQ + q0) * EMBED + h * HDIM;
#pragma unroll
    for (int i = 0; i < 16; i++) {
        int f4 = i * 128 + tid;
        int row = f4 >> 4, c4 = f4 & 15;
        ((float4*)Ss)[f4] = *(const float4*)(Qg + (size_t)row * EMBED + c4 * 4);
    }
    __syncthreads();

    float q[HDIM], o[HDIM];
#pragma unroll
    for (int d = 0; d < HDIM; d++) { q[d] = Ss[tid * 64 + d] * scale; o[d] = 0.f; }
    float m = -1e30f, l = 0.f;

    const float* Kg = K + (size_t)b * SEQK * EMBED + h * HDIM;
    const float* Vg = V + (size_t)b * SEQK * EMBED + h * HDIM;

    for (int kt = 0; kt < SEQK; kt += 64) {
        __syncthreads();
#pragma unroll
        for (int i = 0; i < 8; i++) {
            int f4 = i * 128 + tid;
            int row = f4 >> 4, c4 = f4 & 15;
            ((float4*)Ks)[f4] = *(const float4*)(Kg + (size_t)(kt + row) * EMBED + c4 * 4);
            ((float4*)Vs)[f4] = *(const float4*)(Vg + (size_t)(kt + row) * EMBED + c4 * 4);
        }
        __syncthreads();

        for (int j = 0; j < 64; j++) {
            float acc2 = 0.f;
            const float* kr = &Ks[j * 64];
#pragma unroll
            for (int d = 0; d < HDIM; d++) acc2 += q[d] * kr[d];
            Ss[j * 128 + tid] = acc2;
        }

        float mt = m;
        for (int j = 0; j < 64; j++) mt = fmaxf(mt, Ss[j * 128 + tid]);
        const float alpha = __expf(m - mt);
        float lsum = 0.f;
        for (int j = 0; j < 64; j++) {
            float p = __expf(Ss[j * 128 + tid] - mt);
            Ss[j * 128 + tid] = p;
            lsum += p;
        }
        l = l * alpha + lsum;
        m = mt;

#pragma unroll
        for (int d = 0; d < HDIM; d++) o[d] *= alpha;

        for (int j = 0; j < 64; j++) {
            const float p = Ss[j * 128 + tid];
            const float* vr = &Vs[j * 64];
#pragma unroll
            for (int d = 0; d < HDIM; d++) o[d] += p * vr[d];
        }
    }

    const float inv = 1.f / l;
    float* Og = O + ((size_t)b * SEQQ + q0 + tid) * EMBED + h * HDIM;
#pragma unroll
    for (int d = 0; d < HDIM; d += 4) {
        float4 v;
        v.x = o[d + 0] * inv; v.y = o[d + 1] * inv;
        v.z = o[d + 2] * inv; v.w = o[d + 3] * inv;
        *(float4*)(Og + d) = v;
    }
}

// ---------------------------------------------------------------------------
extern "C" void kernel_launch(void* const* d_in, const int* in_sizes, int n_in,
                              void* d_out, int out_size)
{
    const float* Qin = (const float*)d_in[0];
    const float* Kin = (const float*)d_in[1];
    const float* Vin = (const float*)d_in[2];
    const float* Wq  = (const float*)d_in[3];
    const float* bq  = (const float*)d_in[4];
    const float* Wk  = (const float*)d_in[5];
    const float* bk  = (const float*)d_in[6];
    const float* Wv  = (const float*)d_in[7];
    const float* bv  = (const float*)d_in[8];
    const float* Wo  = (const float*)d_in[9];
    const float* bo  = (const float*)d_in[10];
    float* out = (float*)d_out;

    float *gQ, *gK, *gV, *gA;
    cudaGetSymbolAddress((void**)&gQ, g_Q);
    cudaGetSymbolAddress((void**)&gK, g_K);
    cudaGetSymbolAddress((void**)&gV, g_V);
    cudaGetSymbolAddress((void**)&gA, g_A);

    __nv_bfloat16 *qiH,*qiL,*kiH,*kiL,*viH,*viL,*aH,*aL;
    __nv_bfloat16 *wqH,*wqL,*wkH,*wkL,*wvH,*wvL,*woH,*woL;
    cudaGetSymbolAddress((void**)&qiH, g_QiH); cudaGetSymbolAddress((void**)&qiL, g_QiL);
    cudaGetSymbolAddress((void**)&kiH, g_KiH); cudaGetSymbolAddress((void**)&kiL, g_KiL);
    cudaGetSymbolAddress((void**)&viH, g_ViH); cudaGetSymbolAddress((void**)&viL, g_ViL);
    cudaGetSymbolAddress((void**)&aH,  g_AH);  cudaGetSymbolAddress((void**)&aL,  g_AL);
    cudaGetSymbolAddress((void**)&wqH, g_WqH); cudaGetSymbolAddress((void**)&wqL, g_WqL);
    cudaGetSymbolAddress((void**)&wkH, g_WkH); cudaGetSymbolAddress((void**)&wkL, g_WkL);
    cudaGetSymbolAddress((void**)&wvH, g_WvH); cudaGetSymbolAddress((void**)&wvL, g_WvL);
    cudaGetSymbolAddress((void**)&woH, g_WoH); cudaGetSymbolAddress((void**)&woL, g_WoL);

    cudaFuncSetAttribute(gemm_mma_kernel, cudaFuncAttributeMaxDynamicSharedMemorySize, GS_SMEM);
    const int ATTN_SMEM = (2 * 64 * 64 + 64 * 128) * sizeof(float);
    cudaFuncSetAttribute(attn_kernel, cudaFuncAttributeMaxDynamicSharedMemorySize, ATTN_SMEM);

    const int nAct4 = MROWS * EMBED / 4;
    const int nW4   = EMBED * EMBED / 4;
    split_kernel<<<(nAct4 + 255) / 256, 256>>>(Qin, qiH, qiL, nAct4);
    split_kernel<<<(nAct4 + 255) / 256, 256>>>(Kin, kiH, kiL, nAct4);
    split_kernel<<<(nAct4 + 255) / 256, 256>>>(Vin, viH, viL, nAct4);
    split_kernel<<<(nW4   + 255) / 256, 256>>>(Wq, wqH, wqL, nW4);
    split_kernel<<<(nW4   + 255) / 256, 256>>>(Wk, wkH, wkL, nW4);
    split_kernel<<<(nW4   + 255) / 256, 256>>>(Wv, wvH, wvL, nW4);
    split_kernel<<<(nW4   + 255) / 256, 256>>>(Wo, woH, woL, nW4);

    dim3 gemm_grid(EMBED / 128, MROWS / 128);   // (8, 32)
    gemm_mma_kernel<<<gemm_grid, 256, GS_SMEM>>>(qiH, qiL, wqH, wqL, bq, gQ);
    gemm_mma_kernel<<<gemm_grid, 256, GS_SMEM>>>(kiH, kiL, wkH, wkL, bk, gK);
    gemm_mma_kernel<<<gemm_grid, 256, GS_SMEM>>>(viH, viL, wvH, wvL, bv, gV);

    dim3 attn_grid(SEQQ / 128, NHEAD, BATCH);
    attn_kernel<<<attn_grid, 128, ATTN_SMEM>>>(gQ, gK, gV, gA);

    split_kernel<<<(nAct4 + 255) / 256, 256>>>(gA, aH, aL, nAct4);
    gemm_mma_kernel<<<gemm_grid, 256, GS_SMEM>>>(aH, aL, woH, woL, bo, out);
}

// round 6
// speedup vs baseline: 4.1457x; 2.9931x over previous
#include <cuda_runtime.h>
#include <cuda_bf16.h>
#include <cstdint>
#include <math.h>

#define EMBED 1024
#define NHEAD 16
#define HDIM  64
#define BATCH 2
#define SEQQ  2048
#define SEQK  2048
#define MROWS (BATCH*SEQQ)   // 4096

// ----------------------------- scratch (no allocs allowed) -----------------
__device__ __nv_bfloat16 g_QiH[MROWS*EMBED], g_QiL[MROWS*EMBED];
__device__ __nv_bfloat16 g_KiH[MROWS*EMBED], g_KiL[MROWS*EMBED];
__device__ __nv_bfloat16 g_ViH[MROWS*EMBED], g_ViL[MROWS*EMBED];
__device__ __nv_bfloat16 g_WqH[EMBED*EMBED], g_WqL[EMBED*EMBED];
__device__ __nv_bfloat16 g_WkH[EMBED*EMBED], g_WkL[EMBED*EMBED];
__device__ __nv_bfloat16 g_WvH[EMBED*EMBED], g_WvL[EMBED*EMBED];
__device__ __nv_bfloat16 g_WoH[EMBED*EMBED], g_WoL[EMBED*EMBED];
__device__ __nv_bfloat16 g_QH [MROWS*EMBED], g_QL [MROWS*EMBED];
__device__ __nv_bfloat16 g_KH [MROWS*EMBED], g_KL [MROWS*EMBED];
__device__ __nv_bfloat16 g_VH [MROWS*EMBED], g_VL [MROWS*EMBED];
__device__ __nv_bfloat16 g_AH [MROWS*EMBED], g_AL [MROWS*EMBED];

// ----------------------------- helpers -------------------------------------
__device__ __forceinline__ uint32_t smem_u32(const void* p) {
    uint32_t a;
    asm("{ .reg .u64 t; cvta.to.shared.u64 t, %1; cvt.u32.u64 %0, t; }" : "=r"(a) : "l"(p));
    return a;
}
#define CP_ASYNC16(dst, src) \
    asm volatile("cp.async.cg.shared.global [%0], [%1], 16;" :: "r"(dst), "l"(src))
#define CP_COMMIT() asm volatile("cp.async.commit_group;" ::: "memory")
#define CP_WAIT(n)  asm volatile("cp.async.wait_group %0;" :: "n"(n) : "memory")

__device__ __forceinline__ void ldsm_x4(uint32_t* r, uint32_t addr) {
    asm volatile("ldmatrix.sync.aligned.m8n8.x4.shared.b16 {%0,%1,%2,%3}, [%4];"
        : "=r"(r[0]), "=r"(r[1]), "=r"(r[2]), "=r"(r[3]) : "r"(addr));
}
__device__ __forceinline__ void ldsm_x4_t(uint32_t* r, uint32_t addr) {
    asm volatile("ldmatrix.sync.aligned.m8n8.x4.trans.shared.b16 {%0,%1,%2,%3}, [%4];"
        : "=r"(r[0]), "=r"(r[1]), "=r"(r[2]), "=r"(r[3]) : "r"(addr));
}
__device__ __forceinline__ void mma_bf16(float* c, const uint32_t* a, const uint32_t* b) {
    asm volatile(
        "mma.sync.aligned.m16n8k16.row.col.f32.bf16.bf16.f32 "
        "{%0,%1,%2,%3}, {%4,%5,%6,%7}, {%8,%9}, {%0,%1,%2,%3};"
        : "+f"(c[0]), "+f"(c[1]), "+f"(c[2]), "+f"(c[3])
        : "r"(a[0]), "r"(a[1]), "r"(a[2]), "r"(a[3]), "r"(b[0]), "r"(b[1]));
}
__device__ __forceinline__ float ex2f(float x) {
    float y; asm("ex2.approx.f32 %0, %1;" : "=f"(y) : "f"(x)); return y;
}
__device__ __forceinline__ void split_pair(float x, float y, uint32_t& hi, uint32_t& lo) {
    __nv_bfloat162 h = __float22bfloat162_rn(make_float2(x, y));
    float hx = __bfloat162float(h.x), hy = __bfloat162float(h.y);
    __nv_bfloat162 l = __float22bfloat162_rn(make_float2(x - hx, y - hy));
    hi = *reinterpret_cast<uint32_t*>(&h);
    lo = *reinterpret_cast<uint32_t*>(&l);
}

// ----------------------------- fp32 -> bf16 hi/lo split --------------------
__global__ void split_kernel(const float* __restrict__ x,
                             __nv_bfloat16* __restrict__ hi,
                             __nv_bfloat16* __restrict__ lo, int n4)
{
    int i = blockIdx.x * blockDim.x + threadIdx.x;
    if (i >= n4) return;
    float4 v = ((const float4*)x)[i];
    uint32_t h0, l0, h1, l1;
    split_pair(v.x, v.y, h0, l0);
    split_pair(v.z, v.w, h1, l1);
    ((uint32_t*)hi)[2*i] = h0; ((uint32_t*)hi)[2*i+1] = h1;
    ((uint32_t*)lo)[2*i] = l0; ((uint32_t*)lo)[2*i+1] = l1;
}

// ----------------------------- HMMA GEMM -----------------------------------
#define GS_TILE  16384
#define GS_STAGE (4*GS_TILE)
#define GS_SMEM  (2*GS_STAGE)   // 131072

__global__ void __launch_bounds__(256, 1) gemm_mma_kernel(
    const __nv_bfloat16* __restrict__ Ah, const __nv_bfloat16* __restrict__ Al,
    const __nv_bfloat16* __restrict__ Bh, const __nv_bfloat16* __restrict__ Bl,
    const float* __restrict__ bias,
    float* __restrict__ Cf,
    __nv_bfloat16* __restrict__ Ch, __nv_bfloat16* __restrict__ Cl,
    float scale)
{
    extern __shared__ char sm[];
    const uint32_t sbase = smem_u32(sm);
    const int tid = threadIdx.x;
    const int lane = tid & 31, wid = tid >> 5;
    const int wm = wid & 1, wn = wid >> 1;
    const int m0 = blockIdx.y * 128, n0 = blockIdx.x * 128;

    float acc[4][4][4];
#pragma unroll
    for (int i = 0; i < 4; i++)
#pragma unroll
        for (int j = 0; j < 4; j++)
#pragma unroll
            for (int k = 0; k < 4; k++) acc[i][j][k] = 0.f;

#define ISSUE_STAGE(buf, k0)                                                   \
    do {                                                                       \
        const uint32_t st = sbase + (buf) * GS_STAGE;                          \
        _Pragma("unroll")                                                      \
        for (int c = 0; c < 4; c++) {                                          \
            const int idx = c * 256 + tid;                                     \
            const int row = idx >> 3, seg = idx & 7;                           \
            uint32_t off = (uint32_t)(row * 128 + seg * 16);                   \
            off ^= ((off >> 3) & 0x70);                                        \
            const size_t ga = (size_t)(m0 + row) * 1024 + (k0) + seg * 8;      \
            const size_t gb = (size_t)(n0 + row) * 1024 + (k0) + seg * 8;      \
            CP_ASYNC16(st + off,               (const char*)(Ah + ga));        \
            CP_ASYNC16(st + GS_TILE + off,     (const char*)(Al + ga));        \
            CP_ASYNC16(st + 2 * GS_TILE + off, (const char*)(Bh + gb));        \
            CP_ASYNC16(st + 3 * GS_TILE + off, (const char*)(Bl + gb));        \
        }                                                                      \
    } while (0)

    ISSUE_STAGE(0, 0);
    CP_COMMIT();

    for (int s = 0; s < 16; s++) {
        if (s < 15) {
            ISSUE_STAGE((s + 1) & 1, (s + 1) * 64);
            CP_COMMIT();
            CP_WAIT(1);
        } else {
            CP_WAIT(0);
        }
        __syncthreads();

        const uint32_t st = sbase + (s & 1) * GS_STAGE;
#pragma unroll
        for (int ks = 0; ks < 4; ks++) {
            uint32_t ah[4][4], al[4][4], bh[2][4], bl[2][4];
            const int ar = (lane & 7) + ((lane >> 3) & 1) * 8;
            const int ak = ks * 16 + ((lane >> 4) & 1) * 8;
#pragma unroll
            for (int mt = 0; mt < 4; mt++) {
                uint32_t off = (uint32_t)((wm * 64 + mt * 16 + ar) * 128 + ak * 2);
                off ^= ((off >> 3) & 0x70);
                ldsm_x4(ah[mt], st + off);
                ldsm_x4(al[mt], st + GS_TILE + off);
            }
            const int bn = (lane & 7) + ((lane >> 4) & 1) * 8;
            const int bk = ks * 16 + ((lane >> 3) & 1) * 8;
#pragma unroll
            for (int np = 0; np < 2; np++) {
                uint32_t off = (uint32_t)((wn * 32 + np * 16 + bn) * 128 + bk * 2);
                off ^= ((off >> 3) & 0x70);
                ldsm_x4(bh[np], st + 2 * GS_TILE + off);
                ldsm_x4(bl[np], st + 3 * GS_TILE + off);
            }
#pragma unroll
            for (int mt = 0; mt < 4; mt++) {
#pragma unroll
                for (int nt = 0; nt < 4; nt++) {
                    const uint32_t* bhf = &bh[nt >> 1][(nt & 1) * 2];
                    const uint32_t* blf = &bl[nt >> 1][(nt & 1) * 2];
                    mma_bf16(acc[mt][nt], ah[mt], bhf);
                    mma_bf16(acc[mt][nt], ah[mt], blf);
                    mma_bf16(acc[mt][nt], al[mt], bhf);
                }
            }
        }
        __syncthreads();
    }
#undef ISSUE_STAGE

#pragma unroll
    for (int mt = 0; mt < 4; mt++) {
        const int row = m0 + wm * 64 + mt * 16 + (lane >> 2);
#pragma unroll
        for (int nt = 0; nt < 4; nt++) {
            const int col = n0 + wn * 32 + nt * 8 + (lane & 3) * 2;
            const float bx = __ldg(bias + col), by = __ldg(bias + col + 1);
            float v0 = (acc[mt][nt][0] + bx) * scale;
            float v1 = (acc[mt][nt][1] + by) * scale;
            float v2 = (acc[mt][nt][2] + bx) * scale;
            float v3 = (acc[mt][nt][3] + by) * scale;
            if (Cf) {
                *(float2*)(Cf + (size_t)row * 1024 + col)       = make_float2(v0, v1);
                *(float2*)(Cf + (size_t)(row + 8) * 1024 + col) = make_float2(v2, v3);
            } else {
                uint32_t h0, l0, h1, l1;
                split_pair(v0, v1, h0, l0);
                split_pair(v2, v3, h1, l1);
                *(uint32_t*)(Ch + (size_t)row * 1024 + col)       = h0;
                *(uint32_t*)(Cl + (size_t)row * 1024 + col)       = l0;
                *(uint32_t*)(Ch + (size_t)(row + 8) * 1024 + col) = h1;
                *(uint32_t*)(Cl + (size_t)(row + 8) * 1024 + col) = l1;
            }
        }
    }
}

// ----------------------------- MMA flash attention -------------------------
#define ATT_STAGE 32768
#define ATT_QOFF  (2*ATT_STAGE)
#define ATT_SMEM  (ATT_QOFF + 32768)   // 98304

__global__ void __launch_bounds__(256, 1) attn_mma_kernel(
    const __nv_bfloat16* __restrict__ QH, const __nv_bfloat16* __restrict__ QL,
    const __nv_bfloat16* __restrict__ KH, const __nv_bfloat16* __restrict__ KL,
    const __nv_bfloat16* __restrict__ VH, const __nv_bfloat16* __restrict__ VL,
    __nv_bfloat16* __restrict__ AH, __nv_bfloat16* __restrict__ AL)
{
    extern __shared__ char sm[];
    const uint32_t sb = smem_u32(sm);
    const int tid = threadIdx.x;
    const int lane = tid & 31, wid = tid >> 5;
    const int b = blockIdx.z, h = blockIdx.y;
    const int q0 = blockIdx.x * 128;

    const size_t qbase = ((size_t)(b * SEQQ + q0)) * EMBED + h * HDIM;
#pragma unroll
    for (int c = 0; c < 4; c++) {
        const int idx = c * 256 + tid;
        const int row = idx >> 3, seg = idx & 7;
        uint32_t off = (uint32_t)(row * 128 + seg * 16);
        off ^= ((off >> 3) & 0x70);
        const size_t g = qbase + (size_t)row * 1024 + seg * 8;
        CP_ASYNC16(sb + ATT_QOFF + off,         (const char*)(QH + g));
        CP_ASYNC16(sb + ATT_QOFF + 16384 + off, (const char*)(QL + g));
    }
    CP_COMMIT();

#define ISSUE_KV(buf, kt)                                                      \
    do {                                                                       \
        const uint32_t st_ = sb + (buf) * ATT_STAGE;                           \
        const size_t kb = ((size_t)(b * SEQK + (kt) * 64)) * EMBED + h * HDIM; \
        _Pragma("unroll")                                                      \
        for (int c = 0; c < 2; c++) {                                          \
            const int idx = c * 256 + tid;                                     \
            const int row = idx >> 3, seg = idx & 7;                           \
            uint32_t off = (uint32_t)(row * 128 + seg * 16);                   \
            off ^= ((off >> 3) & 0x70);                                        \
            const size_t g = kb + (size_t)row * 1024 + seg * 8;                \
            CP_ASYNC16(st_ + off,         (const char*)(KH + g));              \
            CP_ASYNC16(st_ + 8192 + off,  (const char*)(KL + g));              \
            CP_ASYNC16(st_ + 16384 + off, (const char*)(VH + g));              \
            CP_ASYNC16(st_ + 24576 + off, (const char*)(VL + g));              \
        }                                                                      \
    } while (0)

    ISSUE_KV(0, 0);
    CP_COMMIT();
    CP_WAIT(1);            // Q tile complete
    __syncthreads();

    uint32_t qh[4][4], ql[4][4];
    {
        const int ar = (lane & 7) + ((lane >> 3) & 1) * 8;
#pragma unroll
        for (int ks = 0; ks < 4; ks++) {
            const int ak = ks * 16 + ((lane >> 4) & 1) * 8;
            uint32_t off = (uint32_t)((wid * 16 + ar) * 128 + ak * 2);
            off ^= ((off >> 3) & 0x70);
            ldsm_x4(qh[ks], sb + ATT_QOFF + off);
            ldsm_x4(ql[ks], sb + ATT_QOFF + 16384 + off);
        }
    }

    float m0 = -1e30f, m1 = -1e30f, l0 = 0.f, l1 = 0.f;
    float oacc[8][4];
#pragma unroll
    for (int nt = 0; nt < 8; nt++)
#pragma unroll
        for (int k = 0; k < 4; k++) oacc[nt][k] = 0.f;

    for (int kt = 0; kt < 32; kt++) {
        if (kt < 31) {
            ISSUE_KV((kt + 1) & 1, kt + 1);
            CP_COMMIT();
            CP_WAIT(1);
        } else {
            CP_WAIT(0);
        }
        __syncthreads();
        const uint32_t st = sb + (kt & 1) * ATT_STAGE;

        // ---- S = Qc K^T (3-term) ----
        float sacc[8][4];
#pragma unroll
        for (int nt = 0; nt < 8; nt++)
#pragma unroll
            for (int k = 0; k < 4; k++) sacc[nt][k] = 0.f;

#pragma unroll
        for (int ks = 0; ks < 4; ks++) {
            uint32_t bh[4][4], bl[4][4];
            const int bn = (lane & 7) + ((lane >> 4) & 1) * 8;
            const int bk = ks * 16 + ((lane >> 3) & 1) * 8;
#pragma unroll
            for (int g = 0; g < 4; g++) {
                uint32_t off = (uint32_t)((g * 16 + bn) * 128 + bk * 2);
                off ^= ((off >> 3) & 0x70);
                ldsm_x4(bh[g], st + off);
                ldsm_x4(bl[g], st + 8192 + off);
            }
#pragma unroll
            for (int nt = 0; nt < 8; nt++) {
                const uint32_t* bhf = &bh[nt >> 1][(nt & 1) * 2];
                const uint32_t* blf = &bl[nt >> 1][(nt & 1) * 2];
                mma_bf16(sacc[nt], qh[ks], bhf);
                mma_bf16(sacc[nt], qh[ks], blf);
                mma_bf16(sacc[nt], ql[ks], bhf);
            }
        }

        // ---- online softmax (base 2) ----
        float mx0 = sacc[0][0], mx1 = sacc[0][2];
#pragma unroll
        for (int nt = 0; nt < 8; nt++) {
            mx0 = fmaxf(mx0, fmaxf(sacc[nt][0], sacc[nt][1]));
            mx1 = fmaxf(mx1, fmaxf(sacc[nt][2], sacc[nt][3]));
        }
        mx0 = fmaxf(mx0, __shfl_xor_sync(0xffffffffu, mx0, 1));
        mx0 = fmaxf(mx0, __shfl_xor_sync(0xffffffffu, mx0, 2));
        mx1 = fmaxf(mx1, __shfl_xor_sync(0xffffffffu, mx1, 1));
        mx1 = fmaxf(mx1, __shfl_xor_sync(0xffffffffu, mx1, 2));
        const float mn0 = fmaxf(m0, mx0), mn1 = fmaxf(m1, mx1);
        const float a0 = ex2f(m0 - mn0), a1 = ex2f(m1 - mn1);
        m0 = mn0; m1 = mn1;
        float s0 = 0.f, s1 = 0.f;
#pragma unroll
        for (int nt = 0; nt < 8; nt++) {
            sacc[nt][0] = ex2f(sacc[nt][0] - m0);
            sacc[nt][1] = ex2f(sacc[nt][1] - m0);
            sacc[nt][2] = ex2f(sacc[nt][2] - m1);
            sacc[nt][3] = ex2f(sacc[nt][3] - m1);
            s0 += sacc[nt][0] + sacc[nt][1];
            s1 += sacc[nt][2] + sacc[nt][3];
        }
        l0 = l0 * a0 + s0;        // per-thread partial (16 of 64 keys);
        l1 = l1 * a1 + s1;        // quad-reduced once at the epilogue
#pragma unroll
        for (int nt = 0; nt < 8; nt++) {
            oacc[nt][0] *= a0; oacc[nt][1] *= a0;
            oacc[nt][2] *= a1; oacc[nt][3] *= a1;
        }

        // ---- P (C-frag) -> A-frags, hi/lo ----
        uint32_t ph[4][4], pl[4][4];
#pragma unroll
        for (int kf = 0; kf < 4; kf++) {
            split_pair(sacc[2*kf][0],   sacc[2*kf][1],   ph[kf][0], pl[kf][0]);
            split_pair(sacc[2*kf][2],   sacc[2*kf][3],   ph[kf][1], pl[kf][1]);
            split_pair(sacc[2*kf+1][0], sacc[2*kf+1][1], ph[kf][2], pl[kf][2]);
            split_pair(sacc[2*kf+1][2], sacc[2*kf+1][3], ph[kf][3], pl[kf][3]);
        }

        // ---- O += P V (3-term), V via trans ldmatrix ----
#pragma unroll
        for (int ks = 0; ks < 4; ks++) {
            uint32_t vh[4][4], vl[4][4];
            const int vk = ((lane >> 3) & 1) * 8 + (lane & 7);
            const int vd = ((lane >> 4) & 1) * 8;
#pragma unroll
            for (int dp = 0; dp < 4; dp++) {
                uint32_t off = (uint32_t)((ks * 16 + vk) * 128 + (dp * 16 + vd) * 2);
                off ^= ((off >> 3) & 0x70);
                ldsm_x4_t(vh[dp], st + 16384 + off);
                ldsm_x4_t(vl[dp], st + 24576 + off);
            }
#pragma unroll
            for (int nt = 0; nt < 8; nt++) {
                const uint32_t* vhf = &vh[nt >> 1][(nt & 1) * 2];
                const uint32_t* vlf = &vl[nt >> 1][(nt & 1) * 2];
                mma_bf16(oacc[nt], ph[ks], vhf);
                mma_bf16(oacc[nt], ph[ks], vlf);
                mma_bf16(oacc[nt], pl[ks], vhf);
            }
        }
        __syncthreads();
    }
#undef ISSUE_KV

    // ---- FIX: reduce softmax denominator across the quad owning each row ----
    l0 += __shfl_xor_sync(0xffffffffu, l0, 1);
    l0 += __shfl_xor_sync(0xffffffffu, l0, 2);
    l1 += __shfl_xor_sync(0xffffffffu, l1, 1);
    l1 += __shfl_xor_sync(0xffffffffu, l1, 2);

    // ---- epilogue: normalize, write bf16 hi/lo ----
    const float inv0 = 1.f / l0, inv1 = 1.f / l1;
    const size_t row0 = (size_t)(b * SEQQ + q0 + wid * 16 + (lane >> 2));
    const size_t row1 = row0 + 8;
    const int colb = h * HDIM + (lane & 3) * 2;
#pragma unroll
    for (int nt = 0; nt < 8; nt++) {
        const int col = colb + nt * 8;
        uint32_t h0, l0u, h1, l1u;
        split_pair(oacc[nt][0] * inv0, oacc[nt][1] * inv0, h0, l0u);
        split_pair(oacc[nt][2] * inv1, oacc[nt][3] * inv1, h1, l1u);
        *(uint32_t*)(AH + row0 * 1024 + col) = h0;
        *(uint32_t*)(AL + row0 * 1024 + col) = l0u;
        *(uint32_t*)(AH + row1 * 1024 + col) = h1;
        *(uint32_t*)(AL + row1 * 1024 + col) = l1u;
    }
}

// ---------------------------------------------------------------------------
extern "C" void kernel_launch(void* const* d_in, const int* in_sizes, int n_in,
                              void* d_out, int out_size)
{
    const float* Qin = (const float*)d_in[0];
    const float* Kin = (const float*)d_in[1];
    const float* Vin = (const float*)d_in[2];
    const float* Wq  = (const float*)d_in[3];
    const float* bq  = (const float*)d_in[4];
    const float* Wk  = (const float*)d_in[5];
    const float* bk  = (const float*)d_in[6];
    const float* Wv  = (const float*)d_in[7];
    const float* bv  = (const float*)d_in[8];
    const float* Wo  = (const float*)d_in[9];
    const float* bo  = (const float*)d_in[10];
    float* out = (float*)d_out;

    __nv_bfloat16 *qiH,*qiL,*kiH,*kiL,*viH,*viL;
    __nv_bfloat16 *wqH,*wqL,*wkH,*wkL,*wvH,*wvL,*woH,*woL;
    __nv_bfloat16 *qH,*qL,*kH,*kL,*vH,*vL,*aH,*aL;
    cudaGetSymbolAddress((void**)&qiH, g_QiH); cudaGetSymbolAddress((void**)&qiL, g_QiL);
    cudaGetSymbolAddress((void**)&kiH, g_KiH); cudaGetSymbolAddress((void**)&kiL, g_KiL);
    cudaGetSymbolAddress((void**)&viH, g_ViH); cudaGetSymbolAddress((void**)&viL, g_ViL);
    cudaGetSymbolAddress((void**)&wqH, g_WqH); cudaGetSymbolAddress((void**)&wqL, g_WqL);
    cudaGetSymbolAddress((void**)&wkH, g_WkH); cudaGetSymbolAddress((void**)&wkL, g_WkL);
    cudaGetSymbolAddress((void**)&wvH, g_WvH); cudaGetSymbolAddress((void**)&wvL, g_WvL);
    cudaGetSymbolAddress((void**)&woH, g_WoH); cudaGetSymbolAddress((void**)&woL, g_WoL);
    cudaGetSymbolAddress((void**)&qH,  g_QH);  cudaGetSymbolAddress((void**)&qL,  g_QL);
    cudaGetSymbolAddress((void**)&kH,  g_KH);  cudaGetSymbolAddress((void**)&kL,  g_KL);
    cudaGetSymbolAddress((void**)&vH,  g_VH);  cudaGetSymbolAddress((void**)&vL,  g_VL);
    cudaGetSymbolAddress((void**)&aH,  g_AH);  cudaGetSymbolAddress((void**)&aL,  g_AL);

    cudaFuncSetAttribute(gemm_mma_kernel, cudaFuncAttributeMaxDynamicSharedMemorySize, GS_SMEM);
    cudaFuncSetAttribute(attn_mma_kernel, cudaFuncAttributeMaxDynamicSharedMemorySize, ATT_SMEM);

    const int nAct4 = MROWS * EMBED / 4;
    const int nW4   = EMBED * EMBED / 4;
    split_kernel<<<(nAct4 + 255) / 256, 256>>>(Qin, qiH, qiL, nAct4);
    split_kernel<<<(nAct4 + 255) / 256, 256>>>(Kin, kiH, kiL, nAct4);
    split_kernel<<<(nAct4 + 255) / 256, 256>>>(Vin, viH, viL, nAct4);
    split_kernel<<<(nW4   + 255) / 256, 256>>>(Wq, wqH, wqL, nW4);
    split_kernel<<<(nW4   + 255) / 256, 256>>>(Wk, wkH, wkL, nW4);
    split_kernel<<<(nW4   + 255) / 256, 256>>>(Wv, wvH, wvL, nW4);
    split_kernel<<<(nW4   + 255) / 256, 256>>>(Wo, woH, woL, nW4);

    // 0.125 (1/sqrt(64)) * log2(e) folded into Q
    const float qscale = 0.125f * 1.4426950408889634f;

    dim3 gemm_grid(EMBED / 128, MROWS / 128);   // (8, 32)
    gemm_mma_kernel<<<gemm_grid, 256, GS_SMEM>>>(qiH, qiL, wqH, wqL, bq,
                                                 nullptr, qH, qL, qscale);
    gemm_mma_kernel<<<gemm_grid, 256, GS_SMEM>>>(kiH, kiL, wkH, wkL, bk,
                                                 nullptr, kH, kL, 1.0f);
    gemm_mma_kernel<<<gemm_grid, 256, GS_SMEM>>>(viH, viL, wvH, wvL, bv,
                                                 nullptr, vH, vL, 1.0f);

    dim3 attn_grid(SEQQ / 128, NHEAD, BATCH);   // (16, 16, 2)
    attn_mma_kernel<<<attn_grid, 256, ATT_SMEM>>>(qH, qL, kH, kL, vH, vL, aH, aL);

    gemm_mma_kernel<<<gemm_grid, 256, GS_SMEM>>>(aH, aL, woH, woL, bo,
                                                 out, nullptr, nullptr, 1.0f);
}

// round 7
// speedup vs baseline: 4.1792x; 1.0081x over previous
#include <cuda_runtime.h>
#include <cuda_bf16.h>
#include <cstdint>
#include <math.h>

#define EMBED 1024
#define NHEAD 16
#define HDIM  64
#define BATCH 2
#define SEQQ  2048
#define SEQK  2048
#define MROWS (BATCH*SEQQ)   // 4096

// ----------------------------- scratch (no allocs allowed) -----------------
__device__ __nv_bfloat16 g_QiH[MROWS*EMBED], g_QiL[MROWS*EMBED];
__device__ __nv_bfloat16 g_KiH[MROWS*EMBED], g_KiL[MROWS*EMBED];
__device__ __nv_bfloat16 g_ViH[MROWS*EMBED], g_ViL[MROWS*EMBED];
__device__ __nv_bfloat16 g_WqH[EMBED*EMBED], g_WqL[EMBED*EMBED];
__device__ __nv_bfloat16 g_WkH[EMBED*EMBED], g_WkL[EMBED*EMBED];
__device__ __nv_bfloat16 g_WvH[EMBED*EMBED], g_WvL[EMBED*EMBED];
__device__ __nv_bfloat16 g_WoH[EMBED*EMBED], g_WoL[EMBED*EMBED];
__device__ __nv_bfloat16 g_QH [MROWS*EMBED], g_QL [MROWS*EMBED];
__device__ __nv_bfloat16 g_KH [MROWS*EMBED], g_KL [MROWS*EMBED];
__device__ __nv_bfloat16 g_VH [MROWS*EMBED], g_VL [MROWS*EMBED];
__device__ __nv_bfloat16 g_AH [MROWS*EMBED], g_AL [MROWS*EMBED];

// ----------------------------- helpers -------------------------------------
__device__ __forceinline__ uint32_t smem_u32(const void* p) {
    uint32_t a;
    asm("{ .reg .u64 t; cvta.to.shared.u64 t, %1; cvt.u32.u64 %0, t; }" : "=r"(a) : "l"(p));
    return a;
}
#define CP_ASYNC16(dst, src) \
    asm volatile("cp.async.cg.shared.global [%0], [%1], 16;" :: "r"(dst), "l"(src))
#define CP_COMMIT() asm volatile("cp.async.commit_group;" ::: "memory")
#define CP_WAIT(n)  asm volatile("cp.async.wait_group %0;" :: "n"(n) : "memory")

__device__ __forceinline__ void ldsm_x4(uint32_t* r, uint32_t addr) {
    asm volatile("ldmatrix.sync.aligned.m8n8.x4.shared.b16 {%0,%1,%2,%3}, [%4];"
        : "=r"(r[0]), "=r"(r[1]), "=r"(r[2]), "=r"(r[3]) : "r"(addr));
}
__device__ __forceinline__ void ldsm_x4_t(uint32_t* r, uint32_t addr) {
    asm volatile("ldmatrix.sync.aligned.m8n8.x4.trans.shared.b16 {%0,%1,%2,%3}, [%4];"
        : "=r"(r[0]), "=r"(r[1]), "=r"(r[2]), "=r"(r[3]) : "r"(addr));
}
__device__ __forceinline__ void mma_bf16(float* c, const uint32_t* a, const uint32_t* b) {
    asm volatile(
        "mma.sync.aligned.m16n8k16.row.col.f32.bf16.bf16.f32 "
        "{%0,%1,%2,%3}, {%4,%5,%6,%7}, {%8,%9}, {%0,%1,%2,%3};"
        : "+f"(c[0]), "+f"(c[1]), "+f"(c[2]), "+f"(c[3])
        : "r"(a[0]), "r"(a[1]), "r"(a[2]), "r"(a[3]), "r"(b[0]), "r"(b[1]));
}
__device__ __forceinline__ float ex2f(float x) {
    float y; asm("ex2.approx.f32 %0, %1;" : "=f"(y) : "f"(x)); return y;
}
__device__ __forceinline__ void split_pair(float x, float y, uint32_t& hi, uint32_t& lo) {
    __nv_bfloat162 h = __float22bfloat162_rn(make_float2(x, y));
    float hx = __bfloat162float(h.x), hy = __bfloat162float(h.y);
    __nv_bfloat162 l = __float22bfloat162_rn(make_float2(x - hx, y - hy));
    hi = *reinterpret_cast<uint32_t*>(&h);
    lo = *reinterpret_cast<uint32_t*>(&l);
}

// ----------------------------- fp32 -> bf16 hi/lo split --------------------
__global__ void split_kernel(const float* __restrict__ x,
                             __nv_bfloat16* __restrict__ hi,
                             __nv_bfloat16* __restrict__ lo, int n4)
{
    int i = blockIdx.x * blockDim.x + threadIdx.x;
    if (i >= n4) return;
    float4 v = ((const float4*)x)[i];
    uint32_t h0, l0, h1, l1;
    split_pair(v.x, v.y, h0, l0);
    split_pair(v.z, v.w, h1, l1);
    ((uint32_t*)hi)[2*i] = h0; ((uint32_t*)hi)[2*i+1] = h1;
    ((uint32_t*)lo)[2*i] = l0; ((uint32_t*)lo)[2*i+1] = l1;
}

// ----------------------------- HMMA GEMM (128x256 block, 64x64 warp) -------
// C = A @ W^T + bias (then *scale). 3-term compensated bf16 hi/lo.
// Stage: Ah(16K) Al(16K) Bh(32K) Bl(32K) = 96KB. Double-buffered = 192KB.
struct GemmArgs {
    const __nv_bfloat16 *Ah, *Al, *Bh, *Bl;
    const float* bias;
    float* Cf;                       // fp32 out (or null)
    __nv_bfloat16 *Ch, *Cl;          // bf16 hi/lo out (or null)
    float scale;
};

#define GB_AOFF  0
#define GB_ALOFF 16384
#define GB_BOFF  32768
#define GB_BLOFF 65536
#define GB_STAGE 98304
#define GB_SMEM  (2*GB_STAGE)        // 196608

__global__ void __launch_bounds__(256, 1) gemm_mma_kernel(
    GemmArgs ga0, GemmArgs ga1, GemmArgs ga2)
{
    const GemmArgs g = (blockIdx.z == 0) ? ga0 : (blockIdx.z == 1) ? ga1 : ga2;

    extern __shared__ char sm[];
    const uint32_t sbase = smem_u32(sm);
    const int tid = threadIdx.x;
    const int lane = tid & 31, wid = tid >> 5;
    const int wm = wid & 1, wn = wid >> 1;          // 2 x 4 warps, 64x64 tiles
    const int m0 = blockIdx.y * 128, n0 = blockIdx.x * 256;

    float acc[4][8][4];
#pragma unroll
    for (int i = 0; i < 4; i++)
#pragma unroll
        for (int j = 0; j < 8; j++)
#pragma unroll
            for (int k = 0; k < 4; k++) acc[i][j][k] = 0.f;

#define ISSUE_STAGE(buf, k0)                                                   \
    do {                                                                       \
        const uint32_t st = sbase + (buf) * GB_STAGE;                          \
        _Pragma("unroll")                                                      \
        for (int c = 0; c < 4; c++) {                                          \
            const int idx = c * 256 + tid;                                     \
            const int row = idx >> 3, seg = idx & 7;                           \
            uint32_t off = (uint32_t)(row * 128 + seg * 16);                   \
            off ^= ((off >> 3) & 0x70);                                        \
            const size_t gaa = (size_t)(m0 + row) * 1024 + (k0) + seg * 8;     \
            CP_ASYNC16(st + GB_AOFF + off,  (const char*)(g.Ah + gaa));        \
            CP_ASYNC16(st + GB_ALOFF + off, (const char*)(g.Al + gaa));        \
        }                                                                      \
        _Pragma("unroll")                                                      \
        for (int c = 0; c < 8; c++) {                                          \
            const int idx = c * 256 + tid;                                     \
            const int row = idx >> 3, seg = idx & 7;                           \
            uint32_t off = (uint32_t)(row * 128 + seg * 16);                   \
            off ^= ((off >> 3) & 0x70);                                        \
            const size_t gbb = (size_t)(n0 + row) * 1024 + (k0) + seg * 8;     \
            CP_ASYNC16(st + GB_BOFF + off,  (const char*)(g.Bh + gbb));        \
            CP_ASYNC16(st + GB_BLOFF + off, (const char*)(g.Bl + gbb));        \
        }                                                                      \
    } while (0)

    ISSUE_STAGE(0, 0);
    CP_COMMIT();

    for (int s = 0; s < 16; s++) {
        if (s < 15) {
            ISSUE_STAGE((s + 1) & 1, (s + 1) * 64);
            CP_COMMIT();
            CP_WAIT(1);
        } else {
            CP_WAIT(0);
        }
        __syncthreads();

        const uint32_t st = sbase + (s & 1) * GB_STAGE;
#pragma unroll
        for (int ks = 0; ks < 4; ks++) {
            uint32_t ah[4][4], al[4][4], bh[4][4], bl[4][4];
            const int ar = (lane & 7) + ((lane >> 3) & 1) * 8;
            const int ak = ks * 16 + ((lane >> 4) & 1) * 8;
#pragma unroll
            for (int mt = 0; mt < 4; mt++) {
                uint32_t off = (uint32_t)((wm * 64 + mt * 16 + ar) * 128 + ak * 2);
                off ^= ((off >> 3) & 0x70);
                ldsm_x4(ah[mt], st + GB_AOFF + off);
                ldsm_x4(al[mt], st + GB_ALOFF + off);
            }
            const int bn = (lane & 7) + ((lane >> 4) & 1) * 8;
            const int bk = ks * 16 + ((lane >> 3) & 1) * 8;
#pragma unroll
            for (int gg = 0; gg < 4; gg++) {
                uint32_t off = (uint32_t)((wn * 64 + gg * 16 + bn) * 128 + bk * 2);
                off ^= ((off >> 3) & 0x70);
                ldsm_x4(bh[gg], st + GB_BOFF + off);
                ldsm_x4(bl[gg], st + GB_BLOFF + off);
            }
#pragma unroll
            for (int mt = 0; mt < 4; mt++) {
#pragma unroll
                for (int nt = 0; nt < 8; nt++) {
                    const uint32_t* bhf = &bh[nt >> 1][(nt & 1) * 2];
                    const uint32_t* blf = &bl[nt >> 1][(nt & 1) * 2];
                    mma_bf16(acc[mt][nt], ah[mt], bhf);
                    mma_bf16(acc[mt][nt], ah[mt], blf);
                    mma_bf16(acc[mt][nt], al[mt], bhf);
                }
            }
        }
        __syncthreads();
    }
#undef ISSUE_STAGE

#pragma unroll
    for (int mt = 0; mt < 4; mt++) {
        const int row = m0 + wm * 64 + mt * 16 + (lane >> 2);
#pragma unroll
        for (int nt = 0; nt < 8; nt++) {
            const int col = n0 + wn * 64 + nt * 8 + (lane & 3) * 2;
            const float bx = __ldg(g.bias + col), by = __ldg(g.bias + col + 1);
            float v0 = (acc[mt][nt][0] + bx) * g.scale;
            float v1 = (acc[mt][nt][1] + by) * g.scale;
            float v2 = (acc[mt][nt][2] + bx) * g.scale;
            float v3 = (acc[mt][nt][3] + by) * g.scale;
            if (g.Cf) {
                *(float2*)(g.Cf + (size_t)row * 1024 + col)       = make_float2(v0, v1);
                *(float2*)(g.Cf + (size_t)(row + 8) * 1024 + col) = make_float2(v2, v3);
            } else {
                uint32_t h0, l0, h1, l1;
                split_pair(v0, v1, h0, l0);
                split_pair(v2, v3, h1, l1);
                *(uint32_t*)(g.Ch + (size_t)row * 1024 + col)       = h0;
                *(uint32_t*)(g.Cl + (size_t)row * 1024 + col)       = l0;
                *(uint32_t*)(g.Ch + (size_t)(row + 8) * 1024 + col) = h1;
                *(uint32_t*)(g.Cl + (size_t)(row + 8) * 1024 + col) = l1;
            }
        }
    }
}

// ----------------------------- MMA flash attention (unchanged, proven) -----
#define ATT_STAGE 32768
#define ATT_QOFF  (2*ATT_STAGE)
#define ATT_SMEM  (ATT_QOFF + 32768)   // 98304

__global__ void __launch_bounds__(256, 1) attn_mma_kernel(
    const __nv_bfloat16* __restrict__ QH, const __nv_bfloat16* __restrict__ QL,
    const __nv_bfloat16* __restrict__ KH, const __nv_bfloat16* __restrict__ KL,
    const __nv_bfloat16* __restrict__ VH, const __nv_bfloat16* __restrict__ VL,
    __nv_bfloat16* __restrict__ AH, __nv_bfloat16* __restrict__ AL)
{
    extern __shared__ char sm[];
    const uint32_t sb = smem_u32(sm);
    const int tid = threadIdx.x;
    const int lane = tid & 31, wid = tid >> 5;
    const int b = blockIdx.z, h = blockIdx.y;
    const int q0 = blockIdx.x * 128;

    const size_t qbase = ((size_t)(b * SEQQ + q0)) * EMBED + h * HDIM;
#pragma unroll
    for (int c = 0; c < 4; c++) {
        const int idx = c * 256 + tid;
        const int row = idx >> 3, seg = idx & 7;
        uint32_t off = (uint32_t)(row * 128 + seg * 16);
        off ^= ((off >> 3) & 0x70);
        const size_t g = qbase + (size_t)row * 1024 + seg * 8;
        CP_ASYNC16(sb + ATT_QOFF + off,         (const char*)(QH + g));
        CP_ASYNC16(sb + ATT_QOFF + 16384 + off, (const char*)(QL + g));
    }
    CP_COMMIT();

#define ISSUE_KV(buf, kt)                                                      \
    do {                                                                       \
        const uint32_t st_ = sb + (buf) * ATT_STAGE;                           \
        const size_t kb = ((size_t)(b * SEQK + (kt) * 64)) * EMBED + h * HDIM; \
        _Pragma("unroll")                                                      \
        for (int c = 0; c < 2; c++) {                                          \
            const int idx = c * 256 + tid;                                     \
            const int row = idx >> 3, seg = idx & 7;                           \
            uint32_t off = (uint32_t)(row * 128 + seg * 16);                   \
            off ^= ((off >> 3) & 0x70);                                        \
            const size_t g = kb + (size_t)row * 1024 + seg * 8;                \
            CP_ASYNC16(st_ + off,         (const char*)(KH + g));              \
            CP_ASYNC16(st_ + 8192 + off,  (const char*)(KL + g));              \
            CP_ASYNC16(st_ + 16384 + off, (const char*)(VH + g));              \
            CP_ASYNC16(st_ + 24576 + off, (const char*)(VL + g));              \
        }                                                                      \
    } while (0)

    ISSUE_KV(0, 0);
    CP_COMMIT();
    CP_WAIT(1);
    __syncthreads();

    uint32_t qh[4][4], ql[4][4];
    {
        const int ar = (lane & 7) + ((lane >> 3) & 1) * 8;
#pragma unroll
        for (int ks = 0; ks < 4; ks++) {
            const int ak = ks * 16 + ((lane >> 4) & 1) * 8;
            uint32_t off = (uint32_t)((wid * 16 + ar) * 128 + ak * 2);
            off ^= ((off >> 3) & 0x70);
            ldsm_x4(qh[ks], sb + ATT_QOFF + off);
            ldsm_x4(ql[ks], sb + ATT_QOFF + 16384 + off);
        }
    }

    float m0 = -1e30f, m1 = -1e30f, l0 = 0.f, l1 = 0.f;
    float oacc[8][4];
#pragma unroll
    for (int nt = 0; nt < 8; nt++)
#pragma unroll
        for (int k = 0; k < 4; k++) oacc[nt][k] = 0.f;

    for (int kt = 0; kt < 32; kt++) {
        if (kt < 31) {
            ISSUE_KV((kt + 1) & 1, kt + 1);
            CP_COMMIT();
            CP_WAIT(1);
        } else {
            CP_WAIT(0);
        }
        __syncthreads();
        const uint32_t st = sb + (kt & 1) * ATT_STAGE;

        float sacc[8][4];
#pragma unroll
        for (int nt = 0; nt < 8; nt++)
#pragma unroll
            for (int k = 0; k < 4; k++) sacc[nt][k] = 0.f;

#pragma unroll
        for (int ks = 0; ks < 4; ks++) {
            uint32_t bh[4][4], bl[4][4];
            const int bn = (lane & 7) + ((lane >> 4) & 1) * 8;
            const int bk = ks * 16 + ((lane >> 3) & 1) * 8;
#pragma unroll
            for (int g = 0; g < 4; g++) {
                uint32_t off = (uint32_t)((g * 16 + bn) * 128 + bk * 2);
                off ^= ((off >> 3) & 0x70);
                ldsm_x4(bh[g], st + off);
                ldsm_x4(bl[g], st + 8192 + off);
            }
#pragma unroll
            for (int nt = 0; nt < 8; nt++) {
                const uint32_t* bhf = &bh[nt >> 1][(nt & 1) * 2];
                const uint32_t* blf = &bl[nt >> 1][(nt & 1) * 2];
                mma_bf16(sacc[nt], qh[ks], bhf);
                mma_bf16(sacc[nt], qh[ks], blf);
                mma_bf16(sacc[nt], ql[ks], bhf);
            }
        }

        float mx0 = sacc[0][0], mx1 = sacc[0][2];
#pragma unroll
        for (int nt = 0; nt < 8; nt++) {
            mx0 = fmaxf(mx0, fmaxf(sacc[nt][0], sacc[nt][1]));
            mx1 = fmaxf(mx1, fmaxf(sacc[nt][2], sacc[nt][3]));
        }
        mx0 = fmaxf(mx0, __shfl_xor_sync(0xffffffffu, mx0, 1));
        mx0 = fmaxf(mx0, __shfl_xor_sync(0xffffffffu, mx0, 2));
        mx1 = fmaxf(mx1, __shfl_xor_sync(0xffffffffu, mx1, 1));
        mx1 = fmaxf(mx1, __shfl_xor_sync(0xffffffffu, mx1, 2));
        const float mn0 = fmaxf(m0, mx0), mn1 = fmaxf(m1, mx1);
        const float a0 = ex2f(m0 - mn0), a1 = ex2f(m1 - mn1);
        m0 = mn0; m1 = mn1;
        float s0 = 0.f, s1 = 0.f;
#pragma unroll
        for (int nt = 0; nt < 8; nt++) {
            sacc[nt][0] = ex2f(sacc[nt][0] - m0);
            sacc[nt][1] = ex2f(sacc[nt][1] - m0);
            sacc[nt][2] = ex2f(sacc[nt][2] - m1);
            sacc[nt][3] = ex2f(sacc[nt][3] - m1);
            s0 += sacc[nt][0] + sacc[nt][1];
            s1 += sacc[nt][2] + sacc[nt][3];
        }
        l0 = l0 * a0 + s0;
        l1 = l1 * a1 + s1;
#pragma unroll
        for (int nt = 0; nt < 8; nt++) {
            oacc[nt][0] *= a0; oacc[nt][1] *= a0;
            oacc[nt][2] *= a1; oacc[nt][3] *= a1;
        }

        uint32_t ph[4][4], pl[4][4];
#pragma unroll
        for (int kf = 0; kf < 4; kf++) {
            split_pair(sacc[2*kf][0],   sacc[2*kf][1],   ph[kf][0], pl[kf][0]);
            split_pair(sacc[2*kf][2],   sacc[2*kf][3],   ph[kf][1], pl[kf][1]);
            split_pair(sacc[2*kf+1][0], sacc[2*kf+1][1], ph[kf][2], pl[kf][2]);
            split_pair(sacc[2*kf+1][2], sacc[2*kf+1][3], ph[kf][3], pl[kf][3]);
        }

#pragma unroll
        for (int ks = 0; ks < 4; ks++) {
            uint32_t vh[4][4], vl[4][4];
            const int vk = ((lane >> 3) & 1) * 8 + (lane & 7);
            const int vd = ((lane >> 4) & 1) * 8;
#pragma unroll
            for (int dp = 0; dp < 4; dp++) {
                uint32_t off = (uint32_t)((ks * 16 + vk) * 128 + (dp * 16 + vd) * 2);
                off ^= ((off >> 3) & 0x70);
                ldsm_x4_t(vh[dp], st + 16384 + off);
                ldsm_x4_t(vl[dp], st + 24576 + off);
            }
#pragma unroll
            for (int nt = 0; nt < 8; nt++) {
                const uint32_t* vhf = &vh[nt >> 1][(nt & 1) * 2];
                const uint32_t* vlf = &vl[nt >> 1][(nt & 1) * 2];
                mma_bf16(oacc[nt], ph[ks], vhf);
                mma_bf16(oacc[nt], ph[ks], vlf);
                mma_bf16(oacc[nt], pl[ks], vhf);
            }
        }
        __syncthreads();
    }
#undef ISSUE_KV

    l0 += __shfl_xor_sync(0xffffffffu, l0, 1);
    l0 += __shfl_xor_sync(0xffffffffu, l0, 2);
    l1 += __shfl_xor_sync(0xffffffffu, l1, 1);
    l1 += __shfl_xor_sync(0xffffffffu, l1, 2);

    const float inv0 = 1.f / l0, inv1 = 1.f / l1;
    const size_t row0 = (size_t)(b * SEQQ + q0 + wid * 16 + (lane >> 2));
    const size_t row1 = row0 + 8;
    const int colb = h * HDIM + (lane & 3) * 2;
#pragma unroll
    for (int nt = 0; nt < 8; nt++) {
        const int col = colb + nt * 8;
        uint32_t h0, l0u, h1, l1u;
        split_pair(oacc[nt][0] * inv0, oacc[nt][1] * inv0, h0, l0u);
        split_pair(oacc[nt][2] * inv1, oacc[nt][3] * inv1, h1, l1u);
        *(uint32_t*)(AH + row0 * 1024 + col) = h0;
        *(uint32_t*)(AL + row0 * 1024 + col) = l0u;
        *(uint32_t*)(AH + row1 * 1024 + col) = h1;
        *(uint32_t*)(AL + row1 * 1024 + col) = l1u;
    }
}

// ---------------------------------------------------------------------------
extern "C" void kernel_launch(void* const* d_in, const int* in_sizes, int n_in,
                              void* d_out, int out_size)
{
    const float* Qin = (const float*)d_in[0];
    const float* Kin = (const float*)d_in[1];
    const float* Vin = (const float*)d_in[2];
    const float* Wq  = (const float*)d_in[3];
    const float* bq  = (const float*)d_in[4];
    const float* Wk  = (const float*)d_in[5];
    const float* bk  = (const float*)d_in[6];
    const float* Wv  = (const float*)d_in[7];
    const float* bv  = (const float*)d_in[8];
    const float* Wo  = (const float*)d_in[9];
    const float* bo  = (const float*)d_in[10];
    float* out = (float*)d_out;

    __nv_bfloat16 *qiH,*qiL,*kiH,*kiL,*viH,*viL;
    __nv_bfloat16 *wqH,*wqL,*wkH,*wkL,*wvH,*wvL,*woH,*woL;
    __nv_bfloat16 *qH,*qL,*kH,*kL,*vH,*vL,*aH,*aL;
    cudaGetSymbolAddress((void**)&qiH, g_QiH); cudaGetSymbolAddress((void**)&qiL, g_QiL);
    cudaGetSymbolAddress((void**)&kiH, g_KiH); cudaGetSymbolAddress((void**)&kiL, g_KiL);
    cudaGetSymbolAddress((void**)&viH, g_ViH); cudaGetSymbolAddress((void**)&viL, g_ViL);
    cudaGetSymbolAddress((void**)&wqH, g_WqH); cudaGetSymbolAddress((void**)&wqL, g_WqL);
    cudaGetSymbolAddress((void**)&wkH, g_WkH); cudaGetSymbolAddress((void**)&wkL, g_WkL);
    cudaGetSymbolAddress((void**)&wvH, g_WvH); cudaGetSymbolAddress((void**)&wvL, g_WvL);
    cudaGetSymbolAddress((void**)&woH, g_WoH); cudaGetSymbolAddress((void**)&woL, g_WoL);
    cudaGetSymbolAddress((void**)&qH,  g_QH);  cudaGetSymbolAddress((void**)&qL,  g_QL);
    cudaGetSymbolAddress((void**)&kH,  g_KH);  cudaGetSymbolAddress((void**)&kL,  g_KL);
    cudaGetSymbolAddress((void**)&vH,  g_VH);  cudaGetSymbolAddress((void**)&vL,  g_VL);
    cudaGetSymbolAddress((void**)&aH,  g_AH);  cudaGetSymbolAddress((void**)&aL,  g_AL);

    cudaFuncSetAttribute(gemm_mma_kernel, cudaFuncAttributeMaxDynamicSharedMemorySize, GB_SMEM);
    cudaFuncSetAttribute(attn_mma_kernel, cudaFuncAttributeMaxDynamicSharedMemorySize, ATT_SMEM);

    const int nAct4 = MROWS * EMBED / 4;
    const int nW4   = EMBED * EMBED / 4;
    split_kernel<<<(nAct4 + 255) / 256, 256>>>(Qin, qiH, qiL, nAct4);
    split_kernel<<<(nAct4 + 255) / 256, 256>>>(Kin, kiH, kiL, nAct4);
    split_kernel<<<(nAct4 + 255) / 256, 256>>>(Vin, viH, viL, nAct4);
    split_kernel<<<(nW4   + 255) / 256, 256>>>(Wq, wqH, wqL, nW4);
    split_kernel<<<(nW4   + 255) / 256, 256>>>(Wk, wkH, wkL, nW4);
    split_kernel<<<(nW4   + 255) / 256, 256>>>(Wv, wvH, wvL, nW4);
    split_kernel<<<(nW4   + 255) / 256, 256>>>(Wo, woH, woL, nW4);

    const float qscale = 0.125f * 1.4426950408889634f;   // 1/sqrt(64) * log2(e)

    GemmArgs argQ = { qiH, qiL, wqH, wqL, bq, nullptr, qH, qL, qscale };
    GemmArgs argK = { kiH, kiL, wkH, wkL, bk, nullptr, kH, kL, 1.0f };
    GemmArgs argV = { viH, viL, wvH, wvL, bv, nullptr, vH, vL, 1.0f };
    GemmArgs argO = { aH,  aL,  woH, woL, bo, out, nullptr, nullptr, 1.0f };

    dim3 qkv_grid(EMBED / 256, MROWS / 128, 3);   // (4, 32, 3) = 384 blocks
    gemm_mma_kernel<<<qkv_grid, 256, GB_SMEM>>>(argQ, argK, argV);

    dim3 attn_grid(SEQQ / 128, NHEAD, BATCH);     // (16, 16, 2)
    attn_mma_kernel<<<attn_grid, 256, ATT_SMEM>>>(qH, qL, kH, kL, vH, vL, aH, aL);

    dim3 o_grid(EMBED / 256, MROWS / 128, 1);     // (4, 32, 1)
    gemm_mma_kernel<<<o_grid, 256, GB_SMEM>>>(argO, argO, argO);
}

// round 8
// speedup vs baseline: 6.4006x; 1.5315x over previous
#include <cuda_runtime.h>
#include <cuda_fp16.h>
#include <cstdint>
#include <math.h>

#define EMBED 1024
#define NHEAD 16
#define HDIM  64
#define BATCH 2
#define SEQQ  2048
#define SEQK  2048
#define MROWS (BATCH*SEQQ)   // 4096

// ----------------------------- scratch (no allocs allowed) -----------------
__device__ __half g_XqH[MROWS*EMBED], g_XqL[MROWS*EMBED];   // input splits
__device__ __half g_XkH[MROWS*EMBED], g_XkL[MROWS*EMBED];
__device__ __half g_XvH[MROWS*EMBED], g_XvL[MROWS*EMBED];
__device__ __half g_Wq[EMBED*EMBED], g_Wk[EMBED*EMBED];     // plain fp16 weights
__device__ __half g_Wv[EMBED*EMBED], g_Wo[EMBED*EMBED];
__device__ __half g_Q [MROWS*EMBED];                        // plain fp16 activations
__device__ __half g_K [MROWS*EMBED];
__device__ __half g_VH[MROWS*EMBED], g_VL[MROWS*EMBED];     // V split
__device__ __half g_AH[MROWS*EMBED], g_AL[MROWS*EMBED];     // attn out split

// ----------------------------- helpers -------------------------------------
__device__ __forceinline__ uint32_t smem_u32(const void* p) {
    uint32_t a;
    asm("{ .reg .u64 t; cvta.to.shared.u64 t, %1; cvt.u32.u64 %0, t; }" : "=r"(a) : "l"(p));
    return a;
}
#define CP_ASYNC16(dst, src) \
    asm volatile("cp.async.cg.shared.global [%0], [%1], 16;" :: "r"(dst), "l"(src))
#define CP_COMMIT() asm volatile("cp.async.commit_group;" ::: "memory")
#define CP_WAIT(n)  asm volatile("cp.async.wait_group %0;" :: "n"(n) : "memory")

__device__ __forceinline__ void ldsm_x4(uint32_t* r, uint32_t addr) {
    asm volatile("ldmatrix.sync.aligned.m8n8.x4.shared.b16 {%0,%1,%2,%3}, [%4];"
        : "=r"(r[0]), "=r"(r[1]), "=r"(r[2]), "=r"(r[3]) : "r"(addr));
}
__device__ __forceinline__ void ldsm_x4_t(uint32_t* r, uint32_t addr) {
    asm volatile("ldmatrix.sync.aligned.m8n8.x4.trans.shared.b16 {%0,%1,%2,%3}, [%4];"
        : "=r"(r[0]), "=r"(r[1]), "=r"(r[2]), "=r"(r[3]) : "r"(addr));
}
__device__ __forceinline__ void mma_f16(float* c, const uint32_t* a, const uint32_t* b) {
    asm volatile(
        "mma.sync.aligned.m16n8k16.row.col.f32.f16.f16.f32 "
        "{%0,%1,%2,%3}, {%4,%5,%6,%7}, {%8,%9}, {%0,%1,%2,%3};"
        : "+f"(c[0]), "+f"(c[1]), "+f"(c[2]), "+f"(c[3])
        : "r"(a[0]), "r"(a[1]), "r"(a[2]), "r"(a[3]), "r"(b[0]), "r"(b[1]));
}
__device__ __forceinline__ float ex2f(float x) {
    float y; asm("ex2.approx.f32 %0, %1;" : "=f"(y) : "f"(x)); return y;
}
__device__ __forceinline__ uint32_t pack_h2(float x, float y) {
    __half2 h = __float22half2_rn(make_float2(x, y));
    return *reinterpret_cast<uint32_t*>(&h);
}
__device__ __forceinline__ void split_pair_h(float x, float y, uint32_t& hi, uint32_t& lo) {
    __half2 h = __float22half2_rn(make_float2(x, y));
    float hx = __low2float(h), hy = __high2float(h);
    __half2 l = __float22half2_rn(make_float2(x - hx, y - hy));
    hi = *reinterpret_cast<uint32_t*>(&h);
    lo = *reinterpret_cast<uint32_t*>(&l);
}

// ----------------------------- fp32 -> fp16 conversions --------------------
__global__ void split_f16_kernel(const float* __restrict__ x,
                                 __half* __restrict__ hi,
                                 __half* __restrict__ lo, int n4)
{
    int i = blockIdx.x * blockDim.x + threadIdx.x;
    if (i >= n4) return;
    float4 v = ((const float4*)x)[i];
    uint32_t h0, l0, h1, l1;
    split_pair_h(v.x, v.y, h0, l0);
    split_pair_h(v.z, v.w, h1, l1);
    ((uint32_t*)hi)[2*i] = h0; ((uint32_t*)hi)[2*i+1] = h1;
    ((uint32_t*)lo)[2*i] = l0; ((uint32_t*)lo)[2*i+1] = l1;
}
__global__ void conv_f16_kernel(const float* __restrict__ x,
                                __half* __restrict__ h, int n4)
{
    int i = blockIdx.x * blockDim.x + threadIdx.x;
    if (i >= n4) return;
    float4 v = ((const float4*)x)[i];
    ((uint32_t*)h)[2*i]   = pack_h2(v.x, v.y);
    ((uint32_t*)h)[2*i+1] = pack_h2(v.z, v.w);
}

// ----------------------------- HMMA GEMM (128x256 block, 64x64 warp) -------
// C = (Ah+Al) @ Wh^T + bias (then *scale). A-side 2-term fp16, weights plain.
struct GemmArgs {
    const __half *Ah, *Al, *Bh;
    const float* bias;
    float* Cf;                 // fp32 out (or null)
    __half *Ch, *Cl;           // fp16 out: Ch plain, or Ch+Cl split (Cl nullable)
    float scale;
};

#define GB_AOFF  0
#define GB_ALOFF 16384
#define GB_BOFF  32768
#define GB_STAGE 65536        // Ah 16K + Al 16K + B 32K
#define GB_SMEM  (2*GB_STAGE) // 131072

__global__ void __launch_bounds__(256, 1) gemm_mma_kernel(
    GemmArgs ga0, GemmArgs ga1, GemmArgs ga2)
{
    const GemmArgs g = (blockIdx.z == 0) ? ga0 : (blockIdx.z == 1) ? ga1 : ga2;

    extern __shared__ char sm[];
    const uint32_t sbase = smem_u32(sm);
    const int tid = threadIdx.x;
    const int lane = tid & 31, wid = tid >> 5;
    const int wm = wid & 1, wn = wid >> 1;          // 2x4 warps, 64x64 tiles
    const int m0 = blockIdx.y * 128, n0 = blockIdx.x * 256;

    float acc[4][8][4];
#pragma unroll
    for (int i = 0; i < 4; i++)
#pragma unroll
        for (int j = 0; j < 8; j++)
#pragma unroll
            for (int k = 0; k < 4; k++) acc[i][j][k] = 0.f;

#define ISSUE_STAGE(buf, k0)                                                   \
    do {                                                                       \
        const uint32_t st = sbase + (buf) * GB_STAGE;                          \
        _Pragma("unroll")                                                      \
        for (int c = 0; c < 4; c++) {                                          \
            const int idx = c * 256 + tid;                                     \
            const int row = idx >> 3, seg = idx & 7;                           \
            uint32_t off = (uint32_t)(row * 128 + seg * 16);                   \
            off ^= ((off >> 3) & 0x70);                                        \
            const size_t gaa = (size_t)(m0 + row) * 1024 + (k0) + seg * 8;     \
            CP_ASYNC16(st + GB_AOFF + off,  (const char*)(g.Ah + gaa));        \
            CP_ASYNC16(st + GB_ALOFF + off, (const char*)(g.Al + gaa));        \
        }                                                                      \
        _Pragma("unroll")                                                      \
        for (int c = 0; c < 8; c++) {                                          \
            const int idx = c * 256 + tid;                                     \
            const int row = idx >> 3, seg = idx & 7;                           \
            uint32_t off = (uint32_t)(row * 128 + seg * 16);                   \
            off ^= ((off >> 3) & 0x70);                                        \
            const size_t gbb = (size_t)(n0 + row) * 1024 + (k0) + seg * 8;     \
            CP_ASYNC16(st + GB_BOFF + off, (const char*)(g.Bh + gbb));         \
        }                                                                      \
    } while (0)

    ISSUE_STAGE(0, 0);
    CP_COMMIT();

    for (int s = 0; s < 16; s++) {
        if (s < 15) {
            ISSUE_STAGE((s + 1) & 1, (s + 1) * 64);
            CP_COMMIT();
            CP_WAIT(1);
        } else {
            CP_WAIT(0);
        }
        __syncthreads();

        const uint32_t st = sbase + (s & 1) * GB_STAGE;
#pragma unroll
        for (int ks = 0; ks < 4; ks++) {
            uint32_t ah[4][4], al[4][4], bh[4][4];
            const int ar = (lane & 7) + ((lane >> 3) & 1) * 8;
            const int ak = ks * 16 + ((lane >> 4) & 1) * 8;
#pragma unroll
            for (int mt = 0; mt < 4; mt++) {
                uint32_t off = (uint32_t)((wm * 64 + mt * 16 + ar) * 128 + ak * 2);
                off ^= ((off >> 3) & 0x70);
                ldsm_x4(ah[mt], st + GB_AOFF + off);
                ldsm_x4(al[mt], st + GB_ALOFF + off);
            }
            const int bn = (lane & 7) + ((lane >> 4) & 1) * 8;
            const int bk = ks * 16 + ((lane >> 3) & 1) * 8;
#pragma unroll
            for (int gg = 0; gg < 4; gg++) {
                uint32_t off = (uint32_t)((wn * 64 + gg * 16 + bn) * 128 + bk * 2);
                off ^= ((off >> 3) & 0x70);
                ldsm_x4(bh[gg], st + GB_BOFF + off);
            }
#pragma unroll
            for (int mt = 0; mt < 4; mt++) {
#pragma unroll
                for (int nt = 0; nt < 8; nt++) {
                    const uint32_t* bhf = &bh[nt >> 1][(nt & 1) * 2];
                    mma_f16(acc[mt][nt], ah[mt], bhf);
                    mma_f16(acc[mt][nt], al[mt], bhf);
                }
            }
        }
        __syncthreads();
    }
#undef ISSUE_STAGE

#pragma unroll
    for (int mt = 0; mt < 4; mt++) {
        const int row = m0 + wm * 64 + mt * 16 + (lane >> 2);
#pragma unroll
        for (int nt = 0; nt < 8; nt++) {
            const int col = n0 + wn * 64 + nt * 8 + (lane & 3) * 2;
            const float bx = __ldg(g.bias + col), by = __ldg(g.bias + col + 1);
            float v0 = (acc[mt][nt][0] + bx) * g.scale;
            float v1 = (acc[mt][nt][1] + by) * g.scale;
            float v2 = (acc[mt][nt][2] + bx) * g.scale;
            float v3 = (acc[mt][nt][3] + by) * g.scale;
            if (g.Cf) {
                *(float2*)(g.Cf + (size_t)row * 1024 + col)       = make_float2(v0, v1);
                *(float2*)(g.Cf + (size_t)(row + 8) * 1024 + col) = make_float2(v2, v3);
            } else if (g.Cl) {
                uint32_t h0, l0, h1, l1;
                split_pair_h(v0, v1, h0, l0);
                split_pair_h(v2, v3, h1, l1);
                *(uint32_t*)(g.Ch + (size_t)row * 1024 + col)       = h0;
                *(uint32_t*)(g.Cl + (size_t)row * 1024 + col)       = l0;
                *(uint32_t*)(g.Ch + (size_t)(row + 8) * 1024 + col) = h1;
                *(uint32_t*)(g.Cl + (size_t)(row + 8) * 1024 + col) = l1;
            } else {
                *(uint32_t*)(g.Ch + (size_t)row * 1024 + col)       = pack_h2(v0, v1);
                *(uint32_t*)(g.Ch + (size_t)(row + 8) * 1024 + col) = pack_h2(v2, v3);
            }
        }
    }
}

// ----------------------------- MMA flash attention (fp16) ------------------
// Q plain, K plain (QK = 1 MMA pass); V hi/lo, P plain (PV = 2 passes).
#define ATT_KOFF  0
#define ATT_VHOFF 8192
#define ATT_VLOFF 16384
#define ATT_STAGE 24576
#define ATT_QOFF  (2*ATT_STAGE)          // 49152
#define ATT_SMEM  (ATT_QOFF + 16384)     // 65536

__global__ void __launch_bounds__(256, 1) attn_mma_kernel(
    const __half* __restrict__ Q,
    const __half* __restrict__ K,
    const __half* __restrict__ VH, const __half* __restrict__ VL,
    __half* __restrict__ AH, __half* __restrict__ AL)
{
    extern __shared__ char sm[];
    const uint32_t sb = smem_u32(sm);
    const int tid = threadIdx.x;
    const int lane = tid & 31, wid = tid >> 5;
    const int b = blockIdx.z, h = blockIdx.y;
    const int q0 = blockIdx.x * 128;

    const size_t qbase = ((size_t)(b * SEQQ + q0)) * EMBED + h * HDIM;
#pragma unroll
    for (int c = 0; c < 4; c++) {
        const int idx = c * 256 + tid;
        const int row = idx >> 3, seg = idx & 7;
        uint32_t off = (uint32_t)(row * 128 + seg * 16);
        off ^= ((off >> 3) & 0x70);
        CP_ASYNC16(sb + ATT_QOFF + off,
                   (const char*)(Q + qbase + (size_t)row * 1024 + seg * 8));
    }
    CP_COMMIT();

#define ISSUE_KV(buf, kt)                                                      \
    do {                                                                       \
        const uint32_t st_ = sb + (buf) * ATT_STAGE;                           \
        const size_t kb = ((size_t)(b * SEQK + (kt) * 64)) * EMBED + h * HDIM; \
        _Pragma("unroll")                                                      \
        for (int c = 0; c < 2; c++) {                                          \
            const int idx = c * 256 + tid;                                     \
            const int row = idx >> 3, seg = idx & 7;                           \
            uint32_t off = (uint32_t)(row * 128 + seg * 16);                   \
            off ^= ((off >> 3) & 0x70);                                        \
            const size_t g = kb + (size_t)row * 1024 + seg * 8;                \
            CP_ASYNC16(st_ + ATT_KOFF + off,  (const char*)(K + g));           \
            CP_ASYNC16(st_ + ATT_VHOFF + off, (const char*)(VH + g));          \
            CP_ASYNC16(st_ + ATT_VLOFF + off, (const char*)(VL + g));          \
        }                                                                      \
    } while (0)

    ISSUE_KV(0, 0);
    CP_COMMIT();
    CP_WAIT(1);
    __syncthreads();

    // Q fragments (plain)
    uint32_t qh[4][4];
    {
        const int ar = (lane & 7) + ((lane >> 3) & 1) * 8;
#pragma unroll
        for (int ks = 0; ks < 4; ks++) {
            const int ak = ks * 16 + ((lane >> 4) & 1) * 8;
            uint32_t off = (uint32_t)((wid * 16 + ar) * 128 + ak * 2);
            off ^= ((off >> 3) & 0x70);
            ldsm_x4(qh[ks], sb + ATT_QOFF + off);
        }
    }

    float m0 = -1e30f, m1 = -1e30f, l0 = 0.f, l1 = 0.f;
    float oacc[8][4];
#pragma unroll
    for (int nt = 0; nt < 8; nt++)
#pragma unroll
        for (int k = 0; k < 4; k++) oacc[nt][k] = 0.f;

    for (int kt = 0; kt < 32; kt++) {
        if (kt < 31) {
            ISSUE_KV((kt + 1) & 1, kt + 1);
            CP_COMMIT();
            CP_WAIT(1);
        } else {
            CP_WAIT(0);
        }
        __syncthreads();
        const uint32_t st = sb + (kt & 1) * ATT_STAGE;

        // ---- S = Q K^T (1 pass) ----
        float sacc[8][4];
#pragma unroll
        for (int nt = 0; nt < 8; nt++)
#pragma unroll
            for (int k = 0; k < 4; k++) sacc[nt][k] = 0.f;

#pragma unroll
        for (int ks = 0; ks < 4; ks++) {
            uint32_t kh[4][4];
            const int bn = (lane & 7) + ((lane >> 4) & 1) * 8;
            const int bk = ks * 16 + ((lane >> 3) & 1) * 8;
#pragma unroll
            for (int g = 0; g < 4; g++) {
                uint32_t off = (uint32_t)((g * 16 + bn) * 128 + bk * 2);
                off ^= ((off >> 3) & 0x70);
                ldsm_x4(kh[g], st + ATT_KOFF + off);
            }
#pragma unroll
            for (int nt = 0; nt < 8; nt++)
                mma_f16(sacc[nt], qh[ks], &kh[nt >> 1][(nt & 1) * 2]);
        }

        // ---- online softmax (base 2) ----
        float mx0 = sacc[0][0], mx1 = sacc[0][2];
#pragma unroll
        for (int nt = 0; nt < 8; nt++) {
            mx0 = fmaxf(mx0, fmaxf(sacc[nt][0], sacc[nt][1]));
            mx1 = fmaxf(mx1, fmaxf(sacc[nt][2], sacc[nt][3]));
        }
        mx0 = fmaxf(mx0, __shfl_xor_sync(0xffffffffu, mx0, 1));
        mx0 = fmaxf(mx0, __shfl_xor_sync(0xffffffffu, mx0, 2));
        mx1 = fmaxf(mx1, __shfl_xor_sync(0xffffffffu, mx1, 1));
        mx1 = fmaxf(mx1, __shfl_xor_sync(0xffffffffu, mx1, 2));
        const float mn0 = fmaxf(m0, mx0), mn1 = fmaxf(m1, mx1);
        const float a0 = ex2f(m0 - mn0), a1 = ex2f(m1 - mn1);
        m0 = mn0; m1 = mn1;
        float s0 = 0.f, s1 = 0.f;
#pragma unroll
        for (int nt = 0; nt < 8; nt++) {
            sacc[nt][0] = ex2f(sacc[nt][0] - m0);
            sacc[nt][1] = ex2f(sacc[nt][1] - m0);
            sacc[nt][2] = ex2f(sacc[nt][2] - m1);
            sacc[nt][3] = ex2f(sacc[nt][3] - m1);
            s0 += sacc[nt][0] + sacc[nt][1];
            s1 += sacc[nt][2] + sacc[nt][3];
        }
        l0 = l0 * a0 + s0;        // per-thread partial; quad-reduced at epilogue
        l1 = l1 * a1 + s1;
#pragma unroll
        for (int nt = 0; nt < 8; nt++) {
            oacc[nt][0] *= a0; oacc[nt][1] *= a0;
            oacc[nt][2] *= a1; oacc[nt][3] *= a1;
        }

        // ---- P (C-frag) -> A-frags, plain fp16 ----
        uint32_t ph[4][4];
#pragma unroll
        for (int kf = 0; kf < 4; kf++) {
            ph[kf][0] = pack_h2(sacc[2*kf][0],   sacc[2*kf][1]);
            ph[kf][1] = pack_h2(sacc[2*kf][2],   sacc[2*kf][3]);
            ph[kf][2] = pack_h2(sacc[2*kf+1][0], sacc[2*kf+1][1]);
            ph[kf][3] = pack_h2(sacc[2*kf+1][2], sacc[2*kf+1][3]);
        }

        // ---- O += P (Vh + Vl)  (2 passes) ----
#pragma unroll
        for (int ks = 0; ks < 4; ks++) {
            uint32_t vh[4][4], vl[4][4];
            const int vk = ((lane >> 3) & 1) * 8 + (lane & 7);
            const int vd = ((lane >> 4) & 1) * 8;
#pragma unroll
            for (int dp = 0; dp < 4; dp++) {
                uint32_t off = (uint32_t)((ks * 16 + vk) * 128 + (dp * 16 + vd) * 2);
                off ^= ((off >> 3) & 0x70);
                ldsm_x4_t(vh[dp], st + ATT_VHOFF + off);
                ldsm_x4_t(vl[dp], st + ATT_VLOFF + off);
            }
#pragma unroll
            for (int nt = 0; nt < 8; nt++) {
                mma_f16(oacc[nt], ph[ks], &vh[nt >> 1][(nt & 1) * 2]);
                mma_f16(oacc[nt], ph[ks], &vl[nt >> 1][(nt & 1) * 2]);
            }
        }
        __syncthreads();
    }
#undef ISSUE_KV

    // quad-reduce softmax denominator
    l0 += __shfl_xor_sync(0xffffffffu, l0, 1);
    l0 += __shfl_xor_sync(0xffffffffu, l0, 2);
    l1 += __shfl_xor_sync(0xffffffffu, l1, 1);
    l1 += __shfl_xor_sync(0xffffffffu, l1, 2);

    const float inv0 = 1.f / l0, inv1 = 1.f / l1;
    const size_t row0 = (size_t)(b * SEQQ + q0 + wid * 16 + (lane >> 2));
    const size_t row1 = row0 + 8;
    const int colb = h * HDIM + (lane & 3) * 2;
#pragma unroll
    for (int nt = 0; nt < 8; nt++) {
        const int col = colb + nt * 8;
        uint32_t h0, l0u, h1, l1u;
        split_pair_h(oacc[nt][0] * inv0, oacc[nt][1] * inv0, h0, l0u);
        split_pair_h(oacc[nt][2] * inv1, oacc[nt][3] * inv1, h1, l1u);
        *(uint32_t*)(AH + row0 * 1024 + col) = h0;
        *(uint32_t*)(AL + row0 * 1024 + col) = l0u;
        *(uint32_t*)(AH + row1 * 1024 + col) = h1;
        *(uint32_t*)(AL + row1 * 1024 + col) = l1u;
    }
}

// ---------------------------------------------------------------------------
extern "C" void kernel_launch(void* const* d_in, const int* in_sizes, int n_in,
                              void* d_out, int out_size)
{
    const float* Qin = (const float*)d_in[0];
    const float* Kin = (const float*)d_in[1];
    const float* Vin = (const float*)d_in[2];
    const float* Wq  = (const float*)d_in[3];
    const float* bq  = (const float*)d_in[4];
    const float* Wk  = (const float*)d_in[5];
    const float* bk  = (const float*)d_in[6];
    const float* Wv  = (const float*)d_in[7];
    const float* bv  = (const float*)d_in[8];
    const float* Wo  = (const float*)d_in[9];
    const float* bo  = (const float*)d_in[10];
    float* out = (float*)d_out;

    __half *xqH,*xqL,*xkH,*xkL,*xvH,*xvL;
    __half *wq,*wk,*wv,*wo;
    __half *q,*k,*vH,*vL,*aH,*aL;
    cudaGetSymbolAddress((void**)&xqH, g_XqH); cudaGetSymbolAddress((void**)&xqL, g_XqL);
    cudaGetSymbolAddress((void**)&xkH, g_XkH); cudaGetSymbolAddress((void**)&xkL, g_XkL);
    cudaGetSymbolAddress((void**)&xvH, g_XvH); cudaGetSymbolAddress((void**)&xvL, g_XvL);
    cudaGetSymbolAddress((void**)&wq, g_Wq); cudaGetSymbolAddress((void**)&wk, g_Wk);
    cudaGetSymbolAddress((void**)&wv, g_Wv); cudaGetSymbolAddress((void**)&wo, g_Wo);
    cudaGetSymbolAddress((void**)&q,  g_Q);  cudaGetSymbolAddress((void**)&k,  g_K);
    cudaGetSymbolAddress((void**)&vH, g_VH); cudaGetSymbolAddress((void**)&vL, g_VL);
    cudaGetSymbolAddress((void**)&aH, g_AH); cudaGetSymbolAddress((void**)&aL, g_AL);

    cudaFuncSetAttribute(gemm_mma_kernel, cudaFuncAttributeMaxDynamicSharedMemorySize, GB_SMEM);
    cudaFuncSetAttribute(attn_mma_kernel, cudaFuncAttributeMaxDynamicSharedMemorySize, ATT_SMEM);

    const int nAct4 = MROWS * EMBED / 4;
    const int nW4   = EMBED * EMBED / 4;
    split_f16_kernel<<<(nAct4 + 255) / 256, 256>>>(Qin, xqH, xqL, nAct4);
    split_f16_kernel<<<(nAct4 + 255) / 256, 256>>>(Kin, xkH, xkL, nAct4);
    split_f16_kernel<<<(nAct4 + 255) / 256, 256>>>(Vin, xvH, xvL, nAct4);
    conv_f16_kernel<<<(nW4 + 255) / 256, 256>>>(Wq, wq, nW4);
    conv_f16_kernel<<<(nW4 + 255) / 256, 256>>>(Wk, wk, nW4);
    conv_f16_kernel<<<(nW4 + 255) / 256, 256>>>(Wv, wv, nW4);
    conv_f16_kernel<<<(nW4 + 255) / 256, 256>>>(Wo, wo, nW4);

    const float qscale = 0.125f * 1.4426950408889634f;   // 1/sqrt(64) * log2(e)

    GemmArgs argQ = { xqH, xqL, wq, bq, nullptr, q,  nullptr, qscale }; // plain out
    GemmArgs argK = { xkH, xkL, wk, bk, nullptr, k,  nullptr, 1.0f };   // plain out
    GemmArgs argV = { xvH, xvL, wv, bv, nullptr, vH, vL,      1.0f };   // split out
    GemmArgs argO = { aH,  aL,  wo, bo, out,     nullptr, nullptr, 1.0f };

    dim3 qkv_grid(EMBED / 256, MROWS / 128, 3);   // (4, 32, 3)
    gemm_mma_kernel<<<qkv_grid, 256, GB_SMEM>>>(argQ, argK, argV);

    dim3 attn_grid(SEQQ / 128, NHEAD, BATCH);     // (16, 16, 2)
    attn_mma_kernel<<<attn_grid, 256, ATT_SMEM>>>(q, k, vH, vL, aH, aL);

    dim3 o_grid(EMBED / 256, MROWS / 128, 1);
    gemm_mma_kernel<<<o_grid, 256, GB_SMEM>>>(argO, argO, argO);
}

// round 9
// speedup vs baseline: 6.4447x; 1.0069x over previous
#include <cuda_runtime.h>
#include <cuda_fp16.h>
#include <cstdint>
#include <math.h>

#define EMBED 1024
#define NHEAD 16
#define HDIM  64
#define BATCH 2
#define SEQQ  2048
#define SEQK  2048
#define MROWS (BATCH*SEQQ)   // 4096

// ----------------------------- scratch (no allocs allowed) -----------------
__device__ __half g_XqH[MROWS*EMBED], g_XqL[MROWS*EMBED];   // input splits
__device__ __half g_XkH[MROWS*EMBED], g_XkL[MROWS*EMBED];
__device__ __half g_XvH[MROWS*EMBED], g_XvL[MROWS*EMBED];
__device__ __half g_Wq[EMBED*EMBED], g_Wk[EMBED*EMBED];     // plain fp16 weights
__device__ __half g_Wv[EMBED*EMBED], g_Wo[EMBED*EMBED];
__device__ __half g_Q [MROWS*EMBED];                        // plain fp16 activations
__device__ __half g_K [MROWS*EMBED];
__device__ __half g_VH[MROWS*EMBED], g_VL[MROWS*EMBED];     // V split
__device__ __half g_AH[MROWS*EMBED], g_AL[MROWS*EMBED];     // attn out split

// ----------------------------- helpers -------------------------------------
__device__ __forceinline__ uint32_t smem_u32(const void* p) {
    uint32_t a;
    asm("{ .reg .u64 t; cvta.to.shared.u64 t, %1; cvt.u32.u64 %0, t; }" : "=r"(a) : "l"(p));
    return a;
}
#define CP_ASYNC16(dst, src) \
    asm volatile("cp.async.cg.shared.global [%0], [%1], 16;" :: "r"(dst), "l"(src))
#define CP_COMMIT() asm volatile("cp.async.commit_group;" ::: "memory")
#define CP_WAIT(n)  asm volatile("cp.async.wait_group %0;" :: "n"(n) : "memory")

__device__ __forceinline__ void ldsm_x4(uint32_t* r, uint32_t addr) {
    asm volatile("ldmatrix.sync.aligned.m8n8.x4.shared.b16 {%0,%1,%2,%3}, [%4];"
        : "=r"(r[0]), "=r"(r[1]), "=r"(r[2]), "=r"(r[3]) : "r"(addr));
}
__device__ __forceinline__ void ldsm_x4_t(uint32_t* r, uint32_t addr) {
    asm volatile("ldmatrix.sync.aligned.m8n8.x4.trans.shared.b16 {%0,%1,%2,%3}, [%4];"
        : "=r"(r[0]), "=r"(r[1]), "=r"(r[2]), "=r"(r[3]) : "r"(addr));
}
__device__ __forceinline__ void mma_f16(float* c, const uint32_t* a, const uint32_t* b) {
    asm volatile(
        "mma.sync.aligned.m16n8k16.row.col.f32.f16.f16.f32 "
        "{%0,%1,%2,%3}, {%4,%5,%6,%7}, {%8,%9}, {%0,%1,%2,%3};"
        : "+f"(c[0]), "+f"(c[1]), "+f"(c[2]), "+f"(c[3])
        : "r"(a[0]), "r"(a[1]), "r"(a[2]), "r"(a[3]), "r"(b[0]), "r"(b[1]));
}
__device__ __forceinline__ float ex2f(float x) {
    float y; asm("ex2.approx.f32 %0, %1;" : "=f"(y) : "f"(x)); return y;
}
__device__ __forceinline__ uint32_t pack_h2(float x, float y) {
    __half2 h = __float22half2_rn(make_float2(x, y));
    return *reinterpret_cast<uint32_t*>(&h);
}
__device__ __forceinline__ void split_pair_h(float x, float y, uint32_t& hi, uint32_t& lo) {
    __half2 h = __float22half2_rn(make_float2(x, y));
    float hx = __low2float(h), hy = __high2float(h);
    __half2 l = __float22half2_rn(make_float2(x - hx, y - hy));
    hi = *reinterpret_cast<uint32_t*>(&h);
    lo = *reinterpret_cast<uint32_t*>(&l);
}

// ----------------------------- fused conversions ---------------------------
struct SplitJob { const float* src; __half* hi; __half* lo; };
__global__ void split3_kernel(SplitJob j0, SplitJob j1, SplitJob j2, int n4)
{
    const SplitJob j = (blockIdx.y == 0) ? j0 : (blockIdx.y == 1) ? j1 : j2;
    int i = blockIdx.x * blockDim.x + threadIdx.x;
    if (i >= n4) return;
    float4 v = ((const float4*)j.src)[i];
    uint32_t h0, l0, h1, l1;
    split_pair_h(v.x, v.y, h0, l0);
    split_pair_h(v.z, v.w, h1, l1);
    ((uint32_t*)j.hi)[2*i] = h0; ((uint32_t*)j.hi)[2*i+1] = h1;
    ((uint32_t*)j.lo)[2*i] = l0; ((uint32_t*)j.lo)[2*i+1] = l1;
}
struct ConvJob { const float* src; __half* dst; };
__global__ void conv4_kernel(ConvJob j0, ConvJob j1, ConvJob j2, ConvJob j3, int n4)
{
    const ConvJob j = (blockIdx.y == 0) ? j0 : (blockIdx.y == 1) ? j1
                    : (blockIdx.y == 2) ? j2 : j3;
    int i = blockIdx.x * blockDim.x + threadIdx.x;
    if (i >= n4) return;
    float4 v = ((const float4*)j.src)[i];
    ((uint32_t*)j.dst)[2*i]   = pack_h2(v.x, v.y);
    ((uint32_t*)j.dst)[2*i+1] = pack_h2(v.z, v.w);
}

// ----------------------------- HMMA GEMM (128x128 block, 64x32 warp) -------
// C = (Ah+Al) @ Wh^T + bias (then *scale). 2 CTAs/SM for bubble coverage.
struct GemmArgs {
    const __half *Ah, *Al, *Bh;
    const float* bias;
    float* Cf;                 // fp32 out (or null)
    __half *Ch, *Cl;           // fp16 out: Ch plain, or Ch+Cl split
    float scale;
};

#define GB_AOFF  0
#define GB_ALOFF 16384
#define GB_BOFF  32768
#define GB_STAGE 49152        // Ah 16K + Al 16K + B 16K
#define GB_SMEM  (2*GB_STAGE) // 98304 -> 2 CTAs/SM

__global__ void __launch_bounds__(256, 2) gemm_mma_kernel(
    GemmArgs ga0, GemmArgs ga1, GemmArgs ga2)
{
    const GemmArgs g = (blockIdx.z == 0) ? ga0 : (blockIdx.z == 1) ? ga1 : ga2;

    extern __shared__ char sm[];
    const uint32_t sbase = smem_u32(sm);
    const int tid = threadIdx.x;
    const int lane = tid & 31, wid = tid >> 5;
    const int wm = wid & 1, wn = wid >> 1;          // 2x4 warps, 64x32 tiles
    const int m0 = blockIdx.y * 128, n0 = blockIdx.x * 128;

    float acc[4][4][4];
#pragma unroll
    for (int i = 0; i < 4; i++)
#pragma unroll
        for (int j = 0; j < 4; j++)
#pragma unroll
            for (int k = 0; k < 4; k++) acc[i][j][k] = 0.f;

#define ISSUE_STAGE(buf, k0)                                                   \
    do {                                                                       \
        const uint32_t st = sbase + (buf) * GB_STAGE;                          \
        _Pragma("unroll")                                                      \
        for (int c = 0; c < 4; c++) {                                          \
            const int idx = c * 256 + tid;                                     \
            const int row = idx >> 3, seg = idx & 7;                           \
            uint32_t off = (uint32_t)(row * 128 + seg * 16);                   \
            off ^= ((off >> 3) & 0x70);                                        \
            const size_t gaa = (size_t)(m0 + row) * 1024 + (k0) + seg * 8;     \
            const size_t gbb = (size_t)(n0 + row) * 1024 + (k0) + seg * 8;     \
            CP_ASYNC16(st + GB_AOFF + off,  (const char*)(g.Ah + gaa));        \
            CP_ASYNC16(st + GB_ALOFF + off, (const char*)(g.Al + gaa));        \
            CP_ASYNC16(st + GB_BOFF + off,  (const char*)(g.Bh + gbb));        \
        }                                                                      \
    } while (0)

    ISSUE_STAGE(0, 0);
    CP_COMMIT();

    for (int s = 0; s < 16; s++) {
        if (s < 15) {
            ISSUE_STAGE((s + 1) & 1, (s + 1) * 64);
            CP_COMMIT();
            CP_WAIT(1);
        } else {
            CP_WAIT(0);
        }
        __syncthreads();

        const uint32_t st = sbase + (s & 1) * GB_STAGE;
#pragma unroll
        for (int ks = 0; ks < 4; ks++) {
            uint32_t ah[4][4], al[4][4], bh[2][4];
            const int ar = (lane & 7) + ((lane >> 3) & 1) * 8;
            const int ak = ks * 16 + ((lane >> 4) & 1) * 8;
#pragma unroll
            for (int mt = 0; mt < 4; mt++) {
                uint32_t off = (uint32_t)((wm * 64 + mt * 16 + ar) * 128 + ak * 2);
                off ^= ((off >> 3) & 0x70);
                ldsm_x4(ah[mt], st + GB_AOFF + off);
                ldsm_x4(al[mt], st + GB_ALOFF + off);
            }
            const int bn = (lane & 7) + ((lane >> 4) & 1) * 8;
            const int bk = ks * 16 + ((lane >> 3) & 1) * 8;
#pragma unroll
            for (int np = 0; np < 2; np++) {
                uint32_t off = (uint32_t)((wn * 32 + np * 16 + bn) * 128 + bk * 2);
                off ^= ((off >> 3) & 0x70);
                ldsm_x4(bh[np], st + GB_BOFF + off);
            }
#pragma unroll
            for (int mt = 0; mt < 4; mt++) {
#pragma unroll
                for (int nt = 0; nt < 4; nt++) {
                    const uint32_t* bhf = &bh[nt >> 1][(nt & 1) * 2];
                    mma_f16(acc[mt][nt], ah[mt], bhf);
                    mma_f16(acc[mt][nt], al[mt], bhf);
                }
            }
        }
        __syncthreads();
    }
#undef ISSUE_STAGE

#pragma unroll
    for (int mt = 0; mt < 4; mt++) {
        const int row = m0 + wm * 64 + mt * 16 + (lane >> 2);
#pragma unroll
        for (int nt = 0; nt < 4; nt++) {
            const int col = n0 + wn * 32 + nt * 8 + (lane & 3) * 2;
            const float bx = __ldg(g.bias + col), by = __ldg(g.bias + col + 1);
            float v0 = (acc[mt][nt][0] + bx) * g.scale;
            float v1 = (acc[mt][nt][1] + by) * g.scale;
            float v2 = (acc[mt][nt][2] + bx) * g.scale;
            float v3 = (acc[mt][nt][3] + by) * g.scale;
            if (g.Cf) {
                *(float2*)(g.Cf + (size_t)row * 1024 + col)       = make_float2(v0, v1);
                *(float2*)(g.Cf + (size_t)(row + 8) * 1024 + col) = make_float2(v2, v3);
            } else if (g.Cl) {
                uint32_t h0, l0, h1, l1;
                split_pair_h(v0, v1, h0, l0);
                split_pair_h(v2, v3, h1, l1);
                *(uint32_t*)(g.Ch + (size_t)row * 1024 + col)       = h0;
                *(uint32_t*)(g.Cl + (size_t)row * 1024 + col)       = l0;
                *(uint32_t*)(g.Ch + (size_t)(row + 8) * 1024 + col) = h1;
                *(uint32_t*)(g.Cl + (size_t)(row + 8) * 1024 + col) = l1;
            } else {
                *(uint32_t*)(g.Ch + (size_t)row * 1024 + col)       = pack_h2(v0, v1);
                *(uint32_t*)(g.Ch + (size_t)(row + 8) * 1024 + col) = pack_h2(v2, v3);
            }
        }
    }
}

// ----------------------------- MMA flash attention (fp16, proven) ----------
#define ATT_KOFF  0
#define ATT_VHOFF 8192
#define ATT_VLOFF 16384
#define ATT_STAGE 24576
#define ATT_QOFF  (2*ATT_STAGE)          // 49152
#define ATT_SMEM  (ATT_QOFF + 16384)     // 65536

__global__ void __launch_bounds__(256, 1) attn_mma_kernel(
    const __half* __restrict__ Q,
    const __half* __restrict__ K,
    const __half* __restrict__ VH, const __half* __restrict__ VL,
    __half* __restrict__ AH, __half* __restrict__ AL)
{
    extern __shared__ char sm[];
    const uint32_t sb = smem_u32(sm);
    const int tid = threadIdx.x;
    const int lane = tid & 31, wid = tid >> 5;
    const int b = blockIdx.z, h = blockIdx.y;
    const int q0 = blockIdx.x * 128;

    const size_t qbase = ((size_t)(b * SEQQ + q0)) * EMBED + h * HDIM;
#pragma unroll
    for (int c = 0; c < 4; c++) {
        const int idx = c * 256 + tid;
        const int row = idx >> 3, seg = idx & 7;
        uint32_t off = (uint32_t)(row * 128 + seg * 16);
        off ^= ((off >> 3) & 0x70);
        CP_ASYNC16(sb + ATT_QOFF + off,
                   (const char*)(Q + qbase + (size_t)row * 1024 + seg * 8));
    }
    CP_COMMIT();

#define ISSUE_KV(buf, kt)                                                      \
    do {                                                                       \
        const uint32_t st_ = sb + (buf) * ATT_STAGE;                           \
        const size_t kb = ((size_t)(b * SEQK + (kt) * 64)) * EMBED + h * HDIM; \
        _Pragma("unroll")                                                      \
        for (int c = 0; c < 2; c++) {                                          \
            const int idx = c * 256 + tid;                                     \
            const int row = idx >> 3, seg = idx & 7;                           \
            uint32_t off = (uint32_t)(row * 128 + seg * 16);                   \
            off ^= ((off >> 3) & 0x70);                                        \
            const size_t g = kb + (size_t)row * 1024 + seg * 8;                \
            CP_ASYNC16(st_ + ATT_KOFF + off,  (const char*)(K + g));           \
            CP_ASYNC16(st_ + ATT_VHOFF + off, (const char*)(VH + g));          \
            CP_ASYNC16(st_ + ATT_VLOFF + off, (const char*)(VL + g));          \
        }                                                                      \
    } while (0)

    ISSUE_KV(0, 0);
    CP_COMMIT();
    CP_WAIT(1);
    __syncthreads();

    uint32_t qh[4][4];
    {
        const int ar = (lane & 7) + ((lane >> 3) & 1) * 8;
#pragma unroll
        for (int ks = 0; ks < 4; ks++) {
            const int ak = ks * 16 + ((lane >> 4) & 1) * 8;
            uint32_t off = (uint32_t)((wid * 16 + ar) * 128 + ak * 2);
            off ^= ((off >> 3) & 0x70);
            ldsm_x4(qh[ks], sb + ATT_QOFF + off);
        }
    }

    float m0 = -1e30f, m1 = -1e30f, l0 = 0.f, l1 = 0.f;
    float oacc[8][4];
#pragma unroll
    for (int nt = 0; nt < 8; nt++)
#pragma unroll
        for (int k = 0; k < 4; k++) oacc[nt][k] = 0.f;

    for (int kt = 0; kt < 32; kt++) {
        if (kt < 31) {
            ISSUE_KV((kt + 1) & 1, kt + 1);
            CP_COMMIT();
            CP_WAIT(1);
        } else {
            CP_WAIT(0);
        }
        __syncthreads();
        const uint32_t st = sb + (kt & 1) * ATT_STAGE;

        float sacc[8][4];
#pragma unroll
        for (int nt = 0; nt < 8; nt++)
#pragma unroll
            for (int k = 0; k < 4; k++) sacc[nt][k] = 0.f;

#pragma unroll
        for (int ks = 0; ks < 4; ks++) {
            uint32_t kh[4][4];
            const int bn = (lane & 7) + ((lane >> 4) & 1) * 8;
            const int bk = ks * 16 + ((lane >> 3) & 1) * 8;
#pragma unroll
            for (int g = 0; g < 4; g++) {
                uint32_t off = (uint32_t)((g * 16 + bn) * 128 + bk * 2);
                off ^= ((off >> 3) & 0x70);
                ldsm_x4(kh[g], st + ATT_KOFF + off);
            }
#pragma unroll
            for (int nt = 0; nt < 8; nt++)
                mma_f16(sacc[nt], qh[ks], &kh[nt >> 1][(nt & 1) * 2]);
        }

        float mx0 = sacc[0][0], mx1 = sacc[0][2];
#pragma unroll
        for (int nt = 0; nt < 8; nt++) {
            mx0 = fmaxf(mx0, fmaxf(sacc[nt][0], sacc[nt][1]));
            mx1 = fmaxf(mx1, fmaxf(sacc[nt][2], sacc[nt][3]));
        }
        mx0 = fmaxf(mx0, __shfl_xor_sync(0xffffffffu, mx0, 1));
        mx0 = fmaxf(mx0, __shfl_xor_sync(0xffffffffu, mx0, 2));
        mx1 = fmaxf(mx1, __shfl_xor_sync(0xffffffffu, mx1, 1));
        mx1 = fmaxf(mx1, __shfl_xor_sync(0xffffffffu, mx1, 2));
        const float mn0 = fmaxf(m0, mx0), mn1 = fmaxf(m1, mx1);
        const float a0 = ex2f(m0 - mn0), a1 = ex2f(m1 - mn1);
        m0 = mn0; m1 = mn1;
        float s0 = 0.f, s1 = 0.f;
#pragma unroll
        for (int nt = 0; nt < 8; nt++) {
            sacc[nt][0] = ex2f(sacc[nt][0] - m0);
            sacc[nt][1] = ex2f(sacc[nt][1] - m0);
            sacc[nt][2] = ex2f(sacc[nt][2] - m1);
            sacc[nt][3] = ex2f(sacc[nt][3] - m1);
            s0 += sacc[nt][0] + sacc[nt][1];
            s1 += sacc[nt][2] + sacc[nt][3];
        }
        l0 = l0 * a0 + s0;
        l1 = l1 * a1 + s1;
#pragma unroll
        for (int nt = 0; nt < 8; nt++) {
            oacc[nt][0] *= a0; oacc[nt][1] *= a0;
            oacc[nt][2] *= a1; oacc[nt][3] *= a1;
        }

        uint32_t ph[4][4];
#pragma unroll
        for (int kf = 0; kf < 4; kf++) {
            ph[kf][0] = pack_h2(sacc[2*kf][0],   sacc[2*kf][1]);
            ph[kf][1] = pack_h2(sacc[2*kf][2],   sacc[2*kf][3]);
            ph[kf][2] = pack_h2(sacc[2*kf+1][0], sacc[2*kf+1][1]);
            ph[kf][3] = pack_h2(sacc[2*kf+1][2], sacc[2*kf+1][3]);
        }

#pragma unroll
        for (int ks = 0; ks < 4; ks++) {
            uint32_t vh[4][4], vl[4][4];
            const int vk = ((lane >> 3) & 1) * 8 + (lane & 7);
            const int vd = ((lane >> 4) & 1) * 8;
#pragma unroll
            for (int dp = 0; dp < 4; dp++) {
                uint32_t off = (uint32_t)((ks * 16 + vk) * 128 + (dp * 16 + vd) * 2);
                off ^= ((off >> 3) & 0x70);
                ldsm_x4_t(vh[dp], st + ATT_VHOFF + off);
                ldsm_x4_t(vl[dp], st + ATT_VLOFF + off);
            }
#pragma unroll
            for (int nt = 0; nt < 8; nt++) {
                mma_f16(oacc[nt], ph[ks], &vh[nt >> 1][(nt & 1) * 2]);
                mma_f16(oacc[nt], ph[ks], &vl[nt >> 1][(nt & 1) * 2]);
            }
        }
        __syncthreads();
    }
#undef ISSUE_KV

    l0 += __shfl_xor_sync(0xffffffffu, l0, 1);
    l0 += __shfl_xor_sync(0xffffffffu, l0, 2);
    l1 += __shfl_xor_sync(0xffffffffu, l1, 1);
    l1 += __shfl_xor_sync(0xffffffffu, l1, 2);

    const float inv0 = 1.f / l0, inv1 = 1.f / l1;
    const size_t row0 = (size_t)(b * SEQQ + q0 + wid * 16 + (lane >> 2));
    const size_t row1 = row0 + 8;
    const int colb = h * HDIM + (lane & 3) * 2;
#pragma unroll
    for (int nt = 0; nt < 8; nt++) {
        const int col = colb + nt * 8;
        uint32_t h0, l0u, h1, l1u;
        split_pair_h(oacc[nt][0] * inv0, oacc[nt][1] * inv0, h0, l0u);
        split_pair_h(oacc[nt][2] * inv1, oacc[nt][3] * inv1, h1, l1u);
        *(uint32_t*)(AH + row0 * 1024 + col) = h0;
        *(uint32_t*)(AL + row0 * 1024 + col) = l0u;
        *(uint32_t*)(AH + row1 * 1024 + col) = h1;
        *(uint32_t*)(AL + row1 * 1024 + col) = l1u;
    }
}

// ---------------------------------------------------------------------------
extern "C" void kernel_launch(void* const* d_in, const int* in_sizes, int n_in,
                              void* d_out, int out_size)
{
    const float* Qin = (const float*)d_in[0];
    const float* Kin = (const float*)d_in[1];
    const float* Vin = (const float*)d_in[2];
    const float* Wq  = (const float*)d_in[3];
    const float* bq  = (const float*)d_in[4];
    const float* Wk  = (const float*)d_in[5];
    const float* bk  = (const float*)d_in[6];
    const float* Wv  = (const float*)d_in[7];
    const float* bv  = (const float*)d_in[8];
    const float* Wo  = (const float*)d_in[9];
    const float* bo  = (const float*)d_in[10];
    float* out = (float*)d_out;

    __half *xqH,*xqL,*xkH,*xkL,*xvH,*xvL;
    __half *wq,*wk,*wv,*wo;
    __half *q,*k,*vH,*vL,*aH,*aL;
    cudaGetSymbolAddress((void**)&xqH, g_XqH); cudaGetSymbolAddress((void**)&xqL, g_XqL);
    cudaGetSymbolAddress((void**)&xkH, g_XkH); cudaGetSymbolAddress((void**)&xkL, g_XkL);
    cudaGetSymbolAddress((void**)&xvH, g_XvH); cudaGetSymbolAddress((void**)&xvL, g_XvL);
    cudaGetSymbolAddress((void**)&wq, g_Wq); cudaGetSymbolAddress((void**)&wk, g_Wk);
    cudaGetSymbolAddress((void**)&wv, g_Wv); cudaGetSymbolAddress((void**)&wo, g_Wo);
    cudaGetSymbolAddress((void**)&q,  g_Q);  cudaGetSymbolAddress((void**)&k,  g_K);
    cudaGetSymbolAddress((void**)&vH, g_VH); cudaGetSymbolAddress((void**)&vL, g_VL);
    cudaGetSymbolAddress((void**)&aH, g_AH); cudaGetSymbolAddress((void**)&aL, g_AL);

    cudaFuncSetAttribute(gemm_mma_kernel, cudaFuncAttributeMaxDynamicSharedMemorySize, GB_SMEM);
    cudaFuncSetAttribute(attn_mma_kernel, cudaFuncAttributeMaxDynamicSharedMemorySize, ATT_SMEM);

    const int nAct4 = MROWS * EMBED / 4;
    const int nW4   = EMBED * EMBED / 4;

    SplitJob sq = { Qin, xqH, xqL }, sk = { Kin, xkH, xkL }, sv = { Vin, xvH, xvL };
    dim3 split_grid((nAct4 + 255) / 256, 3);
    split3_kernel<<<split_grid, 256>>>(sq, sk, sv, nAct4);

    ConvJob cq = { Wq, wq }, ck = { Wk, wk }, cv = { Wv, wv }, co = { Wo, wo };
    dim3 conv_grid((nW4 + 255) / 256, 4);
    conv4_kernel<<<conv_grid, 256>>>(cq, ck, cv, co, nW4);

    const float qscale = 0.125f * 1.4426950408889634f;   // 1/sqrt(64) * log2(e)

    GemmArgs argQ = { xqH, xqL, wq, bq, nullptr, q,  nullptr, qscale };
    GemmArgs argK = { xkH, xkL, wk, bk, nullptr, k,  nullptr, 1.0f };
    GemmArgs argV = { xvH, xvL, wv, bv, nullptr, vH, vL,      1.0f };
    GemmArgs argO = { aH,  aL,  wo, bo, out,     nullptr, nullptr, 1.0f };

    dim3 qkv_grid(EMBED / 128, MROWS / 128, 3);   // (8, 32, 3) = 768 blocks
    gemm_mma_kernel<<<qkv_grid, 256, GB_SMEM>>>(argQ, argK, argV);

    dim3 attn_grid(SEQQ / 128, NHEAD, BATCH);     // (16, 16, 2)
    attn_mma_kernel<<<attn_grid, 256, ATT_SMEM>>>(q, k, vH, vL, aH, aL);

    dim3 o_grid(EMBED / 128, MROWS / 128, 1);
    gemm_mma_kernel<<<o_grid, 256, GB_SMEM>>>(argO, argO, argO);
}

// round 10
// speedup vs baseline: 7.1650x; 1.1118x over previous
#include <cuda_runtime.h>
#include <cuda_fp16.h>
#include <cstdint>
#include <math.h>

#define EMBED 1024
#define NHEAD 16
#define HDIM  64
#define BATCH 2
#define SEQQ  2048
#define SEQK  2048
#define MROWS (BATCH*SEQQ)   // 4096

// ----------------------------- scratch (no allocs allowed) -----------------
__device__ __half g_XqH[MROWS*EMBED], g_XqL[MROWS*EMBED];   // input splits
__device__ __half g_XkH[MROWS*EMBED], g_XkL[MROWS*EMBED];
__device__ __half g_XvH[MROWS*EMBED], g_XvL[MROWS*EMBED];
__device__ __half g_Wq[EMBED*EMBED], g_Wk[EMBED*EMBED];     // plain fp16 weights
__device__ __half g_Wv[EMBED*EMBED], g_Wo[EMBED*EMBED];
__device__ __half g_Q [MROWS*EMBED];                        // plain fp16 activations
__device__ __half g_K [MROWS*EMBED];
__device__ __half g_VH[MROWS*EMBED], g_VL[MROWS*EMBED];     // V split
__device__ __half g_AH[MROWS*EMBED], g_AL[MROWS*EMBED];     // attn out split

// ----------------------------- helpers -------------------------------------
__device__ __forceinline__ uint32_t smem_u32(const void* p) {
    uint32_t a;
    asm("{ .reg .u64 t; cvta.to.shared.u64 t, %1; cvt.u32.u64 %0, t; }" : "=r"(a) : "l"(p));
    return a;
}
#define CP_ASYNC16(dst, src) \
    asm volatile("cp.async.cg.shared.global [%0], [%1], 16;" :: "r"(dst), "l"(src))
#define CP_COMMIT() asm volatile("cp.async.commit_group;" ::: "memory")
#define CP_WAIT(n)  asm volatile("cp.async.wait_group %0;" :: "n"(n) : "memory")

__device__ __forceinline__ void ldsm_x4(uint32_t* r, uint32_t addr) {
    asm volatile("ldmatrix.sync.aligned.m8n8.x4.shared.b16 {%0,%1,%2,%3}, [%4];"
        : "=r"(r[0]), "=r"(r[1]), "=r"(r[2]), "=r"(r[3]) : "r"(addr));
}
__device__ __forceinline__ void ldsm_x4_t(uint32_t* r, uint32_t addr) {
    asm volatile("ldmatrix.sync.aligned.m8n8.x4.trans.shared.b16 {%0,%1,%2,%3}, [%4];"
        : "=r"(r[0]), "=r"(r[1]), "=r"(r[2]), "=r"(r[3]) : "r"(addr));
}
__device__ __forceinline__ void mma_f16(float* c, const uint32_t* a, const uint32_t* b) {
    asm volatile(
        "mma.sync.aligned.m16n8k16.row.col.f32.f16.f16.f32 "
        "{%0,%1,%2,%3}, {%4,%5,%6,%7}, {%8,%9}, {%0,%1,%2,%3};"
        : "+f"(c[0]), "+f"(c[1]), "+f"(c[2]), "+f"(c[3])
        : "r"(a[0]), "r"(a[1]), "r"(a[2]), "r"(a[3]), "r"(b[0]), "r"(b[1]));
}
__device__ __forceinline__ float ex2f(float x) {
    float y; asm("ex2.approx.f32 %0, %1;" : "=f"(y) : "f"(x)); return y;
}
// p = 2^(x,y) computed as fp16x2 in one MUFU op
__device__ __forceinline__ uint32_t ex2_h2(float x, float y) {
    uint32_t h;
    asm("{\n\t.reg .b32 t;\n\t"
        "cvt.rn.f16x2.f32 t, %2, %1;\n\t"
        "ex2.approx.f16x2 %0, t;\n\t}"
        : "=r"(h) : "f"(x), "f"(y));
    return h;
}
__device__ __forceinline__ uint32_t pack_h2(float x, float y) {
    __half2 h = __float22half2_rn(make_float2(x, y));
    return *reinterpret_cast<uint32_t*>(&h);
}
__device__ __forceinline__ void split_pair_h(float x, float y, uint32_t& hi, uint32_t& lo) {
    __half2 h = __float22half2_rn(make_float2(x, y));
    float hx = __low2float(h), hy = __high2float(h);
    __half2 l = __float22half2_rn(make_float2(x - hx, y - hy));
    hi = *reinterpret_cast<uint32_t*>(&h);
    lo = *reinterpret_cast<uint32_t*>(&l);
}

// ----------------------------- fused conversions ---------------------------
struct SplitJob { const float* src; __half* hi; __half* lo; };
__global__ void split3_kernel(SplitJob j0, SplitJob j1, SplitJob j2, int n4)
{
    const SplitJob j = (blockIdx.y == 0) ? j0 : (blockIdx.y == 1) ? j1 : j2;
    int i = blockIdx.x * blockDim.x + threadIdx.x;
    if (i >= n4) return;
    float4 v = ((const float4*)j.src)[i];
    uint32_t h0, l0, h1, l1;
    split_pair_h(v.x, v.y, h0, l0);
    split_pair_h(v.z, v.w, h1, l1);
    ((uint32_t*)j.hi)[2*i] = h0; ((uint32_t*)j.hi)[2*i+1] = h1;
    ((uint32_t*)j.lo)[2*i] = l0; ((uint32_t*)j.lo)[2*i+1] = l1;
}
struct ConvJob { const float* src; __half* dst; };
__global__ void conv4_kernel(ConvJob j0, ConvJob j1, ConvJob j2, ConvJob j3, int n4)
{
    const ConvJob j = (blockIdx.y == 0) ? j0 : (blockIdx.y == 1) ? j1
                    : (blockIdx.y == 2) ? j2 : j3;
    int i = blockIdx.x * blockDim.x + threadIdx.x;
    if (i >= n4) return;
    float4 v = ((const float4*)j.src)[i];
    ((uint32_t*)j.dst)[2*i]   = pack_h2(v.x, v.y);
    ((uint32_t*)j.dst)[2*i+1] = pack_h2(v.z, v.w);
}

// ----------------------------- HMMA GEMM (128x128 block, 64x32 warp) -------
struct GemmArgs {
    const __half *Ah, *Al, *Bh;
    const float* bias;
    float* Cf;
    __half *Ch, *Cl;
    float scale;
};

#define GB_AOFF  0
#define GB_ALOFF 16384
#define GB_BOFF  32768
#define GB_STAGE 49152
#define GB_SMEM  (2*GB_STAGE) // 98304

__global__ void __launch_bounds__(256, 2) gemm_mma_kernel(
    GemmArgs ga0, GemmArgs ga1, GemmArgs ga2)
{
    const GemmArgs g = (blockIdx.z == 0) ? ga0 : (blockIdx.z == 1) ? ga1 : ga2;

    extern __shared__ char sm[];
    const uint32_t sbase = smem_u32(sm);
    const int tid = threadIdx.x;
    const int lane = tid & 31, wid = tid >> 5;
    const int wm = wid & 1, wn = wid >> 1;
    const int m0 = blockIdx.y * 128, n0 = blockIdx.x * 128;

    float acc[4][4][4];
#pragma unroll
    for (int i = 0; i < 4; i++)
#pragma unroll
        for (int j = 0; j < 4; j++)
#pragma unroll
            for (int k = 0; k < 4; k++) acc[i][j][k] = 0.f;

#define ISSUE_STAGE(buf, k0)                                                   \
    do {                                                                       \
        const uint32_t st = sbase + (buf) * GB_STAGE;                          \
        _Pragma("unroll")                                                      \
        for (int c = 0; c < 4; c++) {                                          \
            const int idx = c * 256 + tid;                                     \
            const int row = idx >> 3, seg = idx & 7;                           \
            uint32_t off = (uint32_t)(row * 128 + seg * 16);                   \
            off ^= ((off >> 3) & 0x70);                                        \
            const size_t gaa = (size_t)(m0 + row) * 1024 + (k0) + seg * 8;     \
            const size_t gbb = (size_t)(n0 + row) * 1024 + (k0) + seg * 8;     \
            CP_ASYNC16(st + GB_AOFF + off,  (const char*)(g.Ah + gaa));        \
            CP_ASYNC16(st + GB_ALOFF + off, (const char*)(g.Al + gaa));        \
            CP_ASYNC16(st + GB_BOFF + off,  (const char*)(g.Bh + gbb));        \
        }                                                                      \
    } while (0)

    ISSUE_STAGE(0, 0);
    CP_COMMIT();

    for (int s = 0; s < 16; s++) {
        if (s < 15) {
            ISSUE_STAGE((s + 1) & 1, (s + 1) * 64);
            CP_COMMIT();
            CP_WAIT(1);
        } else {
            CP_WAIT(0);
        }
        __syncthreads();

        const uint32_t st = sbase + (s & 1) * GB_STAGE;
#pragma unroll
        for (int ks = 0; ks < 4; ks++) {
            uint32_t ah[4][4], al[4][4], bh[2][4];
            const int ar = (lane & 7) + ((lane >> 3) & 1) * 8;
            const int ak = ks * 16 + ((lane >> 4) & 1) * 8;
#pragma unroll
            for (int mt = 0; mt < 4; mt++) {
                uint32_t off = (uint32_t)((wm * 64 + mt * 16 + ar) * 128 + ak * 2);
                off ^= ((off >> 3) & 0x70);
                ldsm_x4(ah[mt], st + GB_AOFF + off);
                ldsm_x4(al[mt], st + GB_ALOFF + off);
            }
            const int bn = (lane & 7) + ((lane >> 4) & 1) * 8;
            const int bk = ks * 16 + ((lane >> 3) & 1) * 8;
#pragma unroll
            for (int np = 0; np < 2; np++) {
                uint32_t off = (uint32_t)((wn * 32 + np * 16 + bn) * 128 + bk * 2);
                off ^= ((off >> 3) & 0x70);
                ldsm_x4(bh[np], st + GB_BOFF + off);
            }
#pragma unroll
            for (int mt = 0; mt < 4; mt++) {
#pragma unroll
                for (int nt = 0; nt < 4; nt++) {
                    const uint32_t* bhf = &bh[nt >> 1][(nt & 1) * 2];
                    mma_f16(acc[mt][nt], ah[mt], bhf);
                    mma_f16(acc[mt][nt], al[mt], bhf);
                }
            }
        }
        __syncthreads();
    }
#undef ISSUE_STAGE

#pragma unroll
    for (int mt = 0; mt < 4; mt++) {
        const int row = m0 + wm * 64 + mt * 16 + (lane >> 2);
#pragma unroll
        for (int nt = 0; nt < 4; nt++) {
            const int col = n0 + wn * 32 + nt * 8 + (lane & 3) * 2;
            const float bx = __ldg(g.bias + col), by = __ldg(g.bias + col + 1);
            float v0 = (acc[mt][nt][0] + bx) * g.scale;
            float v1 = (acc[mt][nt][1] + by) * g.scale;
            float v2 = (acc[mt][nt][2] + bx) * g.scale;
            float v3 = (acc[mt][nt][3] + by) * g.scale;
            if (g.Cf) {
                *(float2*)(g.Cf + (size_t)row * 1024 + col)       = make_float2(v0, v1);
                *(float2*)(g.Cf + (size_t)(row + 8) * 1024 + col) = make_float2(v2, v3);
            } else if (g.Cl) {
                uint32_t h0, l0, h1, l1;
                split_pair_h(v0, v1, h0, l0);
                split_pair_h(v2, v3, h1, l1);
                *(uint32_t*)(g.Ch + (size_t)row * 1024 + col)       = h0;
                *(uint32_t*)(g.Cl + (size_t)row * 1024 + col)       = l0;
                *(uint32_t*)(g.Ch + (size_t)(row + 8) * 1024 + col) = h1;
                *(uint32_t*)(g.Cl + (size_t)(row + 8) * 1024 + col) = l1;
            } else {
                *(uint32_t*)(g.Ch + (size_t)row * 1024 + col)       = pack_h2(v0, v1);
                *(uint32_t*)(g.Ch + (size_t)(row + 8) * 1024 + col) = pack_h2(v2, v3);
            }
        }
    }
}

// ----------------------------- MMA flash attention (fp16) ------------------
// Block: 64 q rows, 128 threads (4 warps x 16 rows) -> 3 CTAs/SM.
// l computed by MMA against a constant ones-column fragment (oacc[8]).
#define ATT_KOFF  0
#define ATT_VHOFF 8192
#define ATT_VLOFF 16384
#define ATT_STAGE 24576
#define ATT_QOFF  (2*ATT_STAGE)          // 49152
#define ATT_SMEM  (ATT_QOFF + 8192)      // 57344

__global__ void __launch_bounds__(128) attn_mma_kernel(
    const __half* __restrict__ Q,
    const __half* __restrict__ K,
    const __half* __restrict__ VH, const __half* __restrict__ VL,
    __half* __restrict__ AH, __half* __restrict__ AL)
{
    extern __shared__ char sm[];
    const uint32_t sb = smem_u32(sm);
    const int tid = threadIdx.x;
    const int lane = tid & 31, wid = tid >> 5;
    const int b = blockIdx.z, h = blockIdx.y;
    const int q0 = blockIdx.x * 64;

    // stage Q tile (64 x 64 fp16 = 8KB)
    const size_t qbase = ((size_t)(b * SEQQ + q0)) * EMBED + h * HDIM;
#pragma unroll
    for (int c = 0; c < 4; c++) {
        const int idx = c * 128 + tid;
        const int row = idx >> 3, seg = idx & 7;
        uint32_t off = (uint32_t)(row * 128 + seg * 16);
        off ^= ((off >> 3) & 0x70);
        CP_ASYNC16(sb + ATT_QOFF + off,
                   (const char*)(Q + qbase + (size_t)row * 1024 + seg * 8));
    }
    CP_COMMIT();

#define ISSUE_KV(buf, kt)                                                      \
    do {                                                                       \
        const uint32_t st_ = sb + (buf) * ATT_STAGE;                           \
        const size_t kb = ((size_t)(b * SEQK + (kt) * 64)) * EMBED + h * HDIM; \
        _Pragma("unroll")                                                      \
        for (int c = 0; c < 4; c++) {                                          \
            const int idx = c * 128 + tid;                                     \
            const int row = idx >> 3, seg = idx & 7;                           \
            uint32_t off = (uint32_t)(row * 128 + seg * 16);                   \
            off ^= ((off >> 3) & 0x70);                                        \
            const size_t g = kb + (size_t)row * 1024 + seg * 8;                \
            CP_ASYNC16(st_ + ATT_KOFF + off,  (const char*)(K + g));           \
            CP_ASYNC16(st_ + ATT_VHOFF + off, (const char*)(VH + g));          \
            CP_ASYNC16(st_ + ATT_VLOFF + off, (const char*)(VL + g));          \
        }                                                                      \
    } while (0)

    ISSUE_KV(0, 0);
    CP_COMMIT();
    CP_WAIT(1);
    __syncthreads();

    // Q fragments
    uint32_t qh[4][4];
    {
        const int ar = (lane & 7) + ((lane >> 3) & 1) * 8;
#pragma unroll
        for (int ks = 0; ks < 4; ks++) {
            const int ak = ks * 16 + ((lane >> 4) & 1) * 8;
            uint32_t off = (uint32_t)((wid * 16 + ar) * 128 + ak * 2);
            off ^= ((off >> 3) & 0x70);
            ldsm_x4(qh[ks], sb + ATT_QOFF + off);
        }
    }

    // constant B-fragment of the ones column (n==0 lanes hold 1.0h pairs)
    const uint32_t onefrag = ((lane >> 2) == 0) ? 0x3C003C00u : 0u;
    const uint32_t ones2[2] = { onefrag, onefrag };

    float m0 = -1e30f, m1 = -1e30f;
    float oacc[9][4];                       // [8] = P @ ones (softmax denom)
#pragma unroll
    for (int nt = 0; nt < 9; nt++)
#pragma unroll
        for (int k = 0; k < 4; k++) oacc[nt][k] = 0.f;

    for (int kt = 0; kt < 32; kt++) {
        if (kt < 31) {
            ISSUE_KV((kt + 1) & 1, kt + 1);
            CP_COMMIT();
            CP_WAIT(1);
        } else {
            CP_WAIT(0);
        }
        __syncthreads();
        const uint32_t st = sb + (kt & 1) * ATT_STAGE;

        // ---- S = Q K^T (1 pass) ----
        float sacc[8][4];
#pragma unroll
        for (int nt = 0; nt < 8; nt++)
#pragma unroll
            for (int k = 0; k < 4; k++) sacc[nt][k] = 0.f;

#pragma unroll
        for (int ks = 0; ks < 4; ks++) {
            uint32_t kh[4][4];
            const int bn = (lane & 7) + ((lane >> 4) & 1) * 8;
            const int bk = ks * 16 + ((lane >> 3) & 1) * 8;
#pragma unroll
            for (int g = 0; g < 4; g++) {
                uint32_t off = (uint32_t)((g * 16 + bn) * 128 + bk * 2);
                off ^= ((off >> 3) & 0x70);
                ldsm_x4(kh[g], st + ATT_KOFF + off);
            }
#pragma unroll
            for (int nt = 0; nt < 8; nt++)
                mma_f16(sacc[nt], qh[ks], &kh[nt >> 1][(nt & 1) * 2]);
        }

        // ---- online softmax (base 2), P emitted directly as fp16x2 ----
        float mx0 = sacc[0][0], mx1 = sacc[0][2];
#pragma unroll
        for (int nt = 0; nt < 8; nt++) {
            mx0 = fmaxf(mx0, fmaxf(sacc[nt][0], sacc[nt][1]));
            mx1 = fmaxf(mx1, fmaxf(sacc[nt][2], sacc[nt][3]));
        }
        mx0 = fmaxf(mx0, __shfl_xor_sync(0xffffffffu, mx0, 1));
        mx0 = fmaxf(mx0, __shfl_xor_sync(0xffffffffu, mx0, 2));
        mx1 = fmaxf(mx1, __shfl_xor_sync(0xffffffffu, mx1, 1));
        mx1 = fmaxf(mx1, __shfl_xor_sync(0xffffffffu, mx1, 2));
        const float mn0 = fmaxf(m0, mx0), mn1 = fmaxf(m1, mx1);
        const float a0 = ex2f(m0 - mn0), a1 = ex2f(m1 - mn1);
        m0 = mn0; m1 = mn1;

        uint32_t ph[4][4];
#pragma unroll
        for (int kf = 0; kf < 4; kf++) {
            ph[kf][0] = ex2_h2(sacc[2*kf][0]   - m0, sacc[2*kf][1]   - m0);
            ph[kf][1] = ex2_h2(sacc[2*kf][2]   - m1, sacc[2*kf][3]   - m1);
            ph[kf][2] = ex2_h2(sacc[2*kf+1][0] - m0, sacc[2*kf+1][1] - m0);
            ph[kf][3] = ex2_h2(sacc[2*kf+1][2] - m1, sacc[2*kf+1][3] - m1);
        }

#pragma unroll
        for (int nt = 0; nt < 9; nt++) {
            oacc[nt][0] *= a0; oacc[nt][1] *= a0;
            oacc[nt][2] *= a1; oacc[nt][3] *= a1;
        }

        // ---- O += P (Vh + Vl); denom += P @ ones ----
#pragma unroll
        for (int ks = 0; ks < 4; ks++) {
            uint32_t vh[4][4], vl[4][4];
            const int vk = ((lane >> 3) & 1) * 8 + (lane & 7);
            const int vd = ((lane >> 4) & 1) * 8;
#pragma unroll
            for (int dp = 0; dp < 4; dp++) {
                uint32_t off = (uint32_t)((ks * 16 + vk) * 128 + (dp * 16 + vd) * 2);
                off ^= ((off >> 3) & 0x70);
                ldsm_x4_t(vh[dp], st + ATT_VHOFF + off);
                ldsm_x4_t(vl[dp], st + ATT_VLOFF + off);
            }
#pragma unroll
            for (int nt = 0; nt < 8; nt++) {
                mma_f16(oacc[nt], ph[ks], &vh[nt >> 1][(nt & 1) * 2]);
                mma_f16(oacc[nt], ph[ks], &vl[nt >> 1][(nt & 1) * 2]);
            }
            mma_f16(oacc[8], ph[ks], ones2);
        }
        __syncthreads();
    }
#undef ISSUE_KV

    // softmax denominators: col 0 of the ones-tile, held by lane&3==0
    const int src = lane & ~3;
    const float l0 = __shfl_sync(0xffffffffu, oacc[8][0], src);
    const float l1 = __shfl_sync(0xffffffffu, oacc[8][2], src);

    const float inv0 = 1.f / l0, inv1 = 1.f / l1;
    const size_t row0 = (size_t)(b * SEQQ + q0 + wid * 16 + (lane >> 2));
    const size_t row1 = row0 + 8;
    const int colb = h * HDIM + (lane & 3) * 2;
#pragma unroll
    for (int nt = 0; nt < 8; nt++) {
        const int col = colb + nt * 8;
        uint32_t h0, l0u, h1, l1u;
        split_pair_h(oacc[nt][0] * inv0, oacc[nt][1] * inv0, h0, l0u);
        split_pair_h(oacc[nt][2] * inv1, oacc[nt][3] * inv1, h1, l1u);
        *(uint32_t*)(AH + row0 * 1024 + col) = h0;
        *(uint32_t*)(AL + row0 * 1024 + col) = l0u;
        *(uint32_t*)(AH + row1 * 1024 + col) = h1;
        *(uint32_t*)(AL + row1 * 1024 + col) = l1u;
    }
}

// ---------------------------------------------------------------------------
extern "C" void kernel_launch(void* const* d_in, const int* in_sizes, int n_in,
                              void* d_out, int out_size)
{
    const float* Qin = (const float*)d_in[0];
    const float* Kin = (const float*)d_in[1];
    const float* Vin = (const float*)d_in[2];
    const float* Wq  = (const float*)d_in[3];
    const float* bq  = (const float*)d_in[4];
    const float* Wk  = (const float*)d_in[5];
    const float* bk  = (const float*)d_in[6];
    const float* Wv  = (const float*)d_in[7];
    const float* bv  = (const float*)d_in[8];
    const float* Wo  = (const float*)d_in[9];
    const float* bo  = (const float*)d_in[10];
    float* out = (float*)d_out;

    __half *xqH,*xqL,*xkH,*xkL,*xvH,*xvL;
    __half *wq,*wk,*wv,*wo;
    __half *q,*k,*vH,*vL,*aH,*aL;
    cudaGetSymbolAddress((void**)&xqH, g_XqH); cudaGetSymbolAddress((void**)&xqL, g_XqL);
    cudaGetSymbolAddress((void**)&xkH, g_XkH); cudaGetSymbolAddress((void**)&xkL, g_XkL);
    cudaGetSymbolAddress((void**)&xvH, g_XvH); cudaGetSymbolAddress((void**)&xvL, g_XvL);
    cudaGetSymbolAddress((void**)&wq, g_Wq); cudaGetSymbolAddress((void**)&wk, g_Wk);
    cudaGetSymbolAddress((void**)&wv, g_Wv); cudaGetSymbolAddress((void**)&wo, g_Wo);
    cudaGetSymbolAddress((void**)&q,  g_Q);  cudaGetSymbolAddress((void**)&k,  g_K);
    cudaGetSymbolAddress((void**)&vH, g_VH); cudaGetSymbolAddress((void**)&vL, g_VL);
    cudaGetSymbolAddress((void**)&aH, g_AH); cudaGetSymbolAddress((void**)&aL, g_AL);

    cudaFuncSetAttribute(gemm_mma_kernel, cudaFuncAttributeMaxDynamicSharedMemorySize, GB_SMEM);
    cudaFuncSetAttribute(attn_mma_kernel, cudaFuncAttributeMaxDynamicSharedMemorySize, ATT_SMEM);

    const int nAct4 = MROWS * EMBED / 4;
    const int nW4   = EMBED * EMBED / 4;

    SplitJob sq = { Qin, xqH, xqL }, sk = { Kin, xkH, xkL }, sv = { Vin, xvH, xvL };
    dim3 split_grid((nAct4 + 255) / 256, 3);
    split3_kernel<<<split_grid, 256>>>(sq, sk, sv, nAct4);

    ConvJob cq = { Wq, wq }, ck = { Wk, wk }, cv = { Wv, wv }, co = { Wo, wo };
    dim3 conv_grid((nW4 + 255) / 256, 4);
    conv4_kernel<<<conv_grid, 256>>>(cq, ck, cv, co, nW4);

    const float qscale = 0.125f * 1.4426950408889634f;   // 1/sqrt(64) * log2(e)

    GemmArgs argQ = { xqH, xqL, wq, bq, nullptr, q,  nullptr, qscale };
    GemmArgs argK = { xkH, xkL, wk, bk, nullptr, k,  nullptr, 1.0f };
    GemmArgs argV = { xvH, xvL, wv, bv, nullptr, vH, vL,      1.0f };
    GemmArgs argO = { aH,  aL,  wo, bo, out,     nullptr, nullptr, 1.0f };

    dim3 qkv_grid(EMBED / 128, MROWS / 128, 3);   // (8, 32, 3)
    gemm_mma_kernel<<<qkv_grid, 256, GB_SMEM>>>(argQ, argK, argV);

    dim3 attn_grid(SEQQ / 64, NHEAD, BATCH);      // (32, 16, 2) = 1024 blocks
    attn_mma_kernel<<<attn_grid, 128, ATT_SMEM>>>(q, k, vH, vL, aH, aL);

    dim3 o_grid(EMBED / 128, MROWS / 128, 1);
    gemm_mma_kernel<<<o_grid, 256, GB_SMEM>>>(argO, argO, argO);
}

// round 11
// speedup vs baseline: 7.9711x; 1.1125x over previous
#include <cuda_runtime.h>
#include <cuda_fp16.h>
#include <cstdint>
#include <math.h>

#define EMBED 1024
#define NHEAD 16
#define HDIM  64
#define BATCH 2
#define SEQQ  2048
#define SEQK  2048
#define MROWS (BATCH*SEQQ)   // 4096

// ----------------------------- scratch (no allocs allowed) -----------------
__device__ __half g_XqH[MROWS*EMBED], g_XqL[MROWS*EMBED];   // input splits
__device__ __half g_XkH[MROWS*EMBED], g_XkL[MROWS*EMBED];
__device__ __half g_XvH[MROWS*EMBED], g_XvL[MROWS*EMBED];
__device__ __half g_Wq[EMBED*EMBED], g_Wk[EMBED*EMBED];     // plain fp16 weights
__device__ __half g_Wv[EMBED*EMBED], g_Wo[EMBED*EMBED];
__device__ __half g_Q [MROWS*EMBED];                        // plain fp16 activations
__device__ __half g_K [MROWS*EMBED];
__device__ __half g_V [MROWS*EMBED];                        // V plain fp16 now
__device__ __half g_AH[MROWS*EMBED], g_AL[MROWS*EMBED];     // attn out split

// ----------------------------- helpers -------------------------------------
__device__ __forceinline__ uint32_t smem_u32(const void* p) {
    uint32_t a;
    asm("{ .reg .u64 t; cvta.to.shared.u64 t, %1; cvt.u32.u64 %0, t; }" : "=r"(a) : "l"(p));
    return a;
}
#define CP_ASYNC16(dst, src) \
    asm volatile("cp.async.cg.shared.global [%0], [%1], 16;" :: "r"(dst), "l"(src))
#define CP_COMMIT() asm volatile("cp.async.commit_group;" ::: "memory")
#define CP_WAIT(n)  asm volatile("cp.async.wait_group %0;" :: "n"(n) : "memory")

__device__ __forceinline__ void ldsm_x4(uint32_t* r, uint32_t addr) {
    asm volatile("ldmatrix.sync.aligned.m8n8.x4.shared.b16 {%0,%1,%2,%3}, [%4];"
        : "=r"(r[0]), "=r"(r[1]), "=r"(r[2]), "=r"(r[3]) : "r"(addr));
}
__device__ __forceinline__ void ldsm_x4_t(uint32_t* r, uint32_t addr) {
    asm volatile("ldmatrix.sync.aligned.m8n8.x4.trans.shared.b16 {%0,%1,%2,%3}, [%4];"
        : "=r"(r[0]), "=r"(r[1]), "=r"(r[2]), "=r"(r[3]) : "r"(addr));
}
__device__ __forceinline__ void mma_f16(float* c, const uint32_t* a, const uint32_t* b) {
    asm volatile(
        "mma.sync.aligned.m16n8k16.row.col.f32.f16.f16.f32 "
        "{%0,%1,%2,%3}, {%4,%5,%6,%7}, {%8,%9}, {%0,%1,%2,%3};"
        : "+f"(c[0]), "+f"(c[1]), "+f"(c[2]), "+f"(c[3])
        : "r"(a[0]), "r"(a[1]), "r"(a[2]), "r"(a[3]), "r"(b[0]), "r"(b[1]));
}
__device__ __forceinline__ float ex2f(float x) {
    float y; asm("ex2.approx.f32 %0, %1;" : "=f"(y) : "f"(x)); return y;
}
// p = 2^(x,y) computed as fp16x2 in one MUFU op
__device__ __forceinline__ uint32_t ex2_h2(float x, float y) {
    uint32_t h;
    asm("{\n\t.reg .b32 t;\n\t"
        "cvt.rn.f16x2.f32 t, %2, %1;\n\t"
        "ex2.approx.f16x2 %0, t;\n\t}"
        : "=r"(h) : "f"(x), "f"(y));
    return h;
}
__device__ __forceinline__ uint32_t pack_h2(float x, float y) {
    __half2 h = __float22half2_rn(make_float2(x, y));
    return *reinterpret_cast<uint32_t*>(&h);
}
__device__ __forceinline__ void split_pair_h(float x, float y, uint32_t& hi, uint32_t& lo) {
    __half2 h = __float22half2_rn(make_float2(x, y));
    float hx = __low2float(h), hy = __high2float(h);
    __half2 l = __float22half2_rn(make_float2(x - hx, y - hy));
    hi = *reinterpret_cast<uint32_t*>(&h);
    lo = *reinterpret_cast<uint32_t*>(&l);
}

// ----------------------------- fused conversions ---------------------------
struct SplitJob { const float* src; __half* hi; __half* lo; };
__global__ void split3_kernel(SplitJob j0, SplitJob j1, SplitJob j2, int n4)
{
    const SplitJob j = (blockIdx.y == 0) ? j0 : (blockIdx.y == 1) ? j1 : j2;
    int i = blockIdx.x * blockDim.x + threadIdx.x;
    if (i >= n4) return;
    float4 v = ((const float4*)j.src)[i];
    uint32_t h0, l0, h1, l1;
    split_pair_h(v.x, v.y, h0, l0);
    split_pair_h(v.z, v.w, h1, l1);
    ((uint32_t*)j.hi)[2*i] = h0; ((uint32_t*)j.hi)[2*i+1] = h1;
    ((uint32_t*)j.lo)[2*i] = l0; ((uint32_t*)j.lo)[2*i+1] = l1;
}
struct ConvJob { const float* src; __half* dst; };
__global__ void conv4_kernel(ConvJob j0, ConvJob j1, ConvJob j2, ConvJob j3, int n4)
{
    const ConvJob j = (blockIdx.y == 0) ? j0 : (blockIdx.y == 1) ? j1
                    : (blockIdx.y == 2) ? j2 : j3;
    int i = blockIdx.x * blockDim.x + threadIdx.x;
    if (i >= n4) return;
    float4 v = ((const float4*)j.src)[i];
    ((uint32_t*)j.dst)[2*i]   = pack_h2(v.x, v.y);
    ((uint32_t*)j.dst)[2*i+1] = pack_h2(v.z, v.w);
}

// ----------------------------- HMMA GEMM (128x128 block, 64x32 warp) -------
struct GemmArgs {
    const __half *Ah, *Al, *Bh;
    const float* bias;
    float* Cf;
    __half *Ch, *Cl;
    float scale;
};

#define GB_AOFF  0
#define GB_ALOFF 16384
#define GB_BOFF  32768
#define GB_STAGE 49152
#define GB_SMEM  (2*GB_STAGE) // 98304

__global__ void __launch_bounds__(256, 2) gemm_mma_kernel(
    GemmArgs ga0, GemmArgs ga1, GemmArgs ga2)
{
    const GemmArgs g = (blockIdx.z == 0) ? ga0 : (blockIdx.z == 1) ? ga1 : ga2;

    extern __shared__ char sm[];
    const uint32_t sbase = smem_u32(sm);
    const int tid = threadIdx.x;
    const int lane = tid & 31, wid = tid >> 5;
    const int wm = wid & 1, wn = wid >> 1;
    const int m0 = blockIdx.y * 128, n0 = blockIdx.x * 128;

    float acc[4][4][4];
#pragma unroll
    for (int i = 0; i < 4; i++)
#pragma unroll
        for (int j = 0; j < 4; j++)
#pragma unroll
            for (int k = 0; k < 4; k++) acc[i][j][k] = 0.f;

#define ISSUE_STAGE(buf, k0)                                                   \
    do {                                                                       \
        const uint32_t st = sbase + (buf) * GB_STAGE;                          \
        _Pragma("unroll")                                                      \
        for (int c = 0; c < 4; c++) {                                          \
            const int idx = c * 256 + tid;                                     \
            const int row = idx >> 3, seg = idx & 7;                           \
            uint32_t off = (uint32_t)(row * 128 + seg * 16);                   \
            off ^= ((off >> 3) & 0x70);                                        \
            const size_t gaa = (size_t)(m0 + row) * 1024 + (k0) + seg * 8;     \
            const size_t gbb = (size_t)(n0 + row) * 1024 + (k0) + seg * 8;     \
            CP_ASYNC16(st + GB_AOFF + off,  (const char*)(g.Ah + gaa));        \
            CP_ASYNC16(st + GB_ALOFF + off, (const char*)(g.Al + gaa));        \
            CP_ASYNC16(st + GB_BOFF + off,  (const char*)(g.Bh + gbb));        \
        }                                                                      \
    } while (0)

    ISSUE_STAGE(0, 0);
    CP_COMMIT();

    for (int s = 0; s < 16; s++) {
        if (s < 15) {
            ISSUE_STAGE((s + 1) & 1, (s + 1) * 64);
            CP_COMMIT();
            CP_WAIT(1);
        } else {
            CP_WAIT(0);
        }
        __syncthreads();

        const uint32_t st = sbase + (s & 1) * GB_STAGE;
#pragma unroll
        for (int ks = 0; ks < 4; ks++) {
            uint32_t ah[4][4], al[4][4], bh[2][4];
            const int ar = (lane & 7) + ((lane >> 3) & 1) * 8;
            const int ak = ks * 16 + ((lane >> 4) & 1) * 8;
#pragma unroll
            for (int mt = 0; mt < 4; mt++) {
                uint32_t off = (uint32_t)((wm * 64 + mt * 16 + ar) * 128 + ak * 2);
                off ^= ((off >> 3) & 0x70);
                ldsm_x4(ah[mt], st + GB_AOFF + off);
                ldsm_x4(al[mt], st + GB_ALOFF + off);
            }
            const int bn = (lane & 7) + ((lane >> 4) & 1) * 8;
            const int bk = ks * 16 + ((lane >> 3) & 1) * 8;
#pragma unroll
            for (int np = 0; np < 2; np++) {
                uint32_t off = (uint32_t)((wn * 32 + np * 16 + bn) * 128 + bk * 2);
                off ^= ((off >> 3) & 0x70);
                ldsm_x4(bh[np], st + GB_BOFF + off);
            }
#pragma unroll
            for (int mt = 0; mt < 4; mt++) {
#pragma unroll
                for (int nt = 0; nt < 4; nt++) {
                    const uint32_t* bhf = &bh[nt >> 1][(nt & 1) * 2];
                    mma_f16(acc[mt][nt], ah[mt], bhf);
                    mma_f16(acc[mt][nt], al[mt], bhf);
                }
            }
        }
        __syncthreads();
    }
#undef ISSUE_STAGE

#pragma unroll
    for (int mt = 0; mt < 4; mt++) {
        const int row = m0 + wm * 64 + mt * 16 + (lane >> 2);
#pragma unroll
        for (int nt = 0; nt < 4; nt++) {
            const int col = n0 + wn * 32 + nt * 8 + (lane & 3) * 2;
            const float bx = __ldg(g.bias + col), by = __ldg(g.bias + col + 1);
            float v0 = (acc[mt][nt][0] + bx) * g.scale;
            float v1 = (acc[mt][nt][1] + by) * g.scale;
            float v2 = (acc[mt][nt][2] + bx) * g.scale;
            float v3 = (acc[mt][nt][3] + by) * g.scale;
            if (g.Cf) {
                *(float2*)(g.Cf + (size_t)row * 1024 + col)       = make_float2(v0, v1);
                *(float2*)(g.Cf + (size_t)(row + 8) * 1024 + col) = make_float2(v2, v3);
            } else if (g.Cl) {
                uint32_t h0, l0, h1, l1;
                split_pair_h(v0, v1, h0, l0);
                split_pair_h(v2, v3, h1, l1);
                *(uint32_t*)(g.Ch + (size_t)row * 1024 + col)       = h0;
                *(uint32_t*)(g.Cl + (size_t)row * 1024 + col)       = l0;
                *(uint32_t*)(g.Ch + (size_t)(row + 8) * 1024 + col) = h1;
                *(uint32_t*)(g.Cl + (size_t)(row + 8) * 1024 + col) = l1;
            } else {
                *(uint32_t*)(g.Ch + (size_t)row * 1024 + col)       = pack_h2(v0, v1);
                *(uint32_t*)(g.Ch + (size_t)(row + 8) * 1024 + col) = pack_h2(v2, v3);
            }
        }
    }
}

// ----------------------------- MMA flash attention (fp16) ------------------
// Block: 64 q rows, 128 threads. Q,K,V all plain fp16; PV single pass.
// l via MMA against constant ones-column fragment (oacc[8]).
#define ATT_KOFF  0
#define ATT_VOFF  8192
#define ATT_STAGE 16384
#define ATT_QOFF  (2*ATT_STAGE)          // 32768
#define ATT_SMEM  (ATT_QOFF + 8192)      // 40960

__global__ void __launch_bounds__(128) attn_mma_kernel(
    const __half* __restrict__ Q,
    const __half* __restrict__ K,
    const __half* __restrict__ V,
    __half* __restrict__ AH, __half* __restrict__ AL)
{
    extern __shared__ char sm[];
    const uint32_t sb = smem_u32(sm);
    const int tid = threadIdx.x;
    const int lane = tid & 31, wid = tid >> 5;
    const int b = blockIdx.z, h = blockIdx.y;
    const int q0 = blockIdx.x * 64;

    // stage Q tile (64 x 64 fp16 = 8KB)
    const size_t qbase = ((size_t)(b * SEQQ + q0)) * EMBED + h * HDIM;
#pragma unroll
    for (int c = 0; c < 4; c++) {
        const int idx = c * 128 + tid;
        const int row = idx >> 3, seg = idx & 7;
        uint32_t off = (uint32_t)(row * 128 + seg * 16);
        off ^= ((off >> 3) & 0x70);
        CP_ASYNC16(sb + ATT_QOFF + off,
                   (const char*)(Q + qbase + (size_t)row * 1024 + seg * 8));
    }
    CP_COMMIT();

#define ISSUE_KV(buf, kt)                                                      \
    do {                                                                       \
        const uint32_t st_ = sb + (buf) * ATT_STAGE;                           \
        const size_t kb = ((size_t)(b * SEQK + (kt) * 64)) * EMBED + h * HDIM; \
        _Pragma("unroll")                                                      \
        for (int c = 0; c < 4; c++) {                                          \
            const int idx = c * 128 + tid;                                     \
            const int row = idx >> 3, seg = idx & 7;                           \
            uint32_t off = (uint32_t)(row * 128 + seg * 16);                   \
            off ^= ((off >> 3) & 0x70);                                        \
            const size_t g = kb + (size_t)row * 1024 + seg * 8;                \
            CP_ASYNC16(st_ + ATT_KOFF + off, (const char*)(K + g));            \
            CP_ASYNC16(st_ + ATT_VOFF + off, (const char*)(V + g));            \
        }                                                                      \
    } while (0)

    ISSUE_KV(0, 0);
    CP_COMMIT();
    CP_WAIT(1);
    __syncthreads();

    // Q fragments
    uint32_t qh[4][4];
    {
        const int ar = (lane & 7) + ((lane >> 3) & 1) * 8;
#pragma unroll
        for (int ks = 0; ks < 4; ks++) {
            const int ak = ks * 16 + ((lane >> 4) & 1) * 8;
            uint32_t off = (uint32_t)((wid * 16 + ar) * 128 + ak * 2);
            off ^= ((off >> 3) & 0x70);
            ldsm_x4(qh[ks], sb + ATT_QOFF + off);
        }
    }

    // constant B-fragment of the ones column
    const uint32_t onefrag = ((lane >> 2) == 0) ? 0x3C003C00u : 0u;
    const uint32_t ones2[2] = { onefrag, onefrag };

    float m0 = -1e30f, m1 = -1e30f;
    float oacc[9][4];                       // [8] = P @ ones (softmax denom)
#pragma unroll
    for (int nt = 0; nt < 9; nt++)
#pragma unroll
        for (int k = 0; k < 4; k++) oacc[nt][k] = 0.f;

    for (int kt = 0; kt < 32; kt++) {
        if (kt < 31) {
            ISSUE_KV((kt + 1) & 1, kt + 1);
            CP_COMMIT();
            CP_WAIT(1);
        } else {
            CP_WAIT(0);
        }
        __syncthreads();
        const uint32_t st = sb + (kt & 1) * ATT_STAGE;

        // ---- S = Q K^T (1 pass) ----
        float sacc[8][4];
#pragma unroll
        for (int nt = 0; nt < 8; nt++)
#pragma unroll
            for (int k = 0; k < 4; k++) sacc[nt][k] = 0.f;

#pragma unroll
        for (int ks = 0; ks < 4; ks++) {
            uint32_t kh[4][4];
            const int bn = (lane & 7) + ((lane >> 4) & 1) * 8;
            const int bk = ks * 16 + ((lane >> 3) & 1) * 8;
#pragma unroll
            for (int g = 0; g < 4; g++) {
                uint32_t off = (uint32_t)((g * 16 + bn) * 128 + bk * 2);
                off ^= ((off >> 3) & 0x70);
                ldsm_x4(kh[g], st + ATT_KOFF + off);
            }
#pragma unroll
            for (int nt = 0; nt < 8; nt++)
                mma_f16(sacc[nt], qh[ks], &kh[nt >> 1][(nt & 1) * 2]);
        }

        // ---- online softmax (base 2), P emitted directly as fp16x2 ----
        float mx0 = sacc[0][0], mx1 = sacc[0][2];
#pragma unroll
        for (int nt = 0; nt < 8; nt++) {
            mx0 = fmaxf(mx0, fmaxf(sacc[nt][0], sacc[nt][1]));
            mx1 = fmaxf(mx1, fmaxf(sacc[nt][2], sacc[nt][3]));
        }
        mx0 = fmaxf(mx0, __shfl_xor_sync(0xffffffffu, mx0, 1));
        mx0 = fmaxf(mx0, __shfl_xor_sync(0xffffffffu, mx0, 2));
        mx1 = fmaxf(mx1, __shfl_xor_sync(0xffffffffu, mx1, 1));
        mx1 = fmaxf(mx1, __shfl_xor_sync(0xffffffffu, mx1, 2));
        const float mn0 = fmaxf(m0, mx0), mn1 = fmaxf(m1, mx1);
        const float a0 = ex2f(m0 - mn0), a1 = ex2f(m1 - mn1);
        m0 = mn0; m1 = mn1;

        uint32_t ph[4][4];
#pragma unroll
        for (int kf = 0; kf < 4; kf++) {
            ph[kf][0] = ex2_h2(sacc[2*kf][0]   - m0, sacc[2*kf][1]   - m0);
            ph[kf][1] = ex2_h2(sacc[2*kf][2]   - m1, sacc[2*kf][3]   - m1);
            ph[kf][2] = ex2_h2(sacc[2*kf+1][0] - m0, sacc[2*kf+1][1] - m0);
            ph[kf][3] = ex2_h2(sacc[2*kf+1][2] - m1, sacc[2*kf+1][3] - m1);
        }

#pragma unroll
        for (int nt = 0; nt < 9; nt++) {
            oacc[nt][0] *= a0; oacc[nt][1] *= a0;
            oacc[nt][2] *= a1; oacc[nt][3] *= a1;
        }

        // ---- O += P V (1 pass); denom += P @ ones ----
#pragma unroll
        for (int ks = 0; ks < 4; ks++) {
            uint32_t vh[4][4];
            const int vk = ((lane >> 3) & 1) * 8 + (lane & 7);
            const int vd = ((lane >> 4) & 1) * 8;
#pragma unroll
            for (int dp = 0; dp < 4; dp++) {
                uint32_t off = (uint32_t)((ks * 16 + vk) * 128 + (dp * 16 + vd) * 2);
                off ^= ((off >> 3) & 0x70);
                ldsm_x4_t(vh[dp], st + ATT_VOFF + off);
            }
#pragma unroll
            for (int nt = 0; nt < 8; nt++)
                mma_f16(oacc[nt], ph[ks], &vh[nt >> 1][(nt & 1) * 2]);
            mma_f16(oacc[8], ph[ks], ones2);
        }
        __syncthreads();
    }
#undef ISSUE_KV

    // softmax denominators: col 0 of the ones-tile, held by lane&3==0
    const int src = lane & ~3;
    const float l0 = __shfl_sync(0xffffffffu, oacc[8][0], src);
    const float l1 = __shfl_sync(0xffffffffu, oacc[8][2], src);

    const float inv0 = 1.f / l0, inv1 = 1.f / l1;
    const size_t row0 = (size_t)(b * SEQQ + q0 + wid * 16 + (lane >> 2));
    const size_t row1 = row0 + 8;
    const int colb = h * HDIM + (lane & 3) * 2;
#pragma unroll
    for (int nt = 0; nt < 8; nt++) {
        const int col = colb + nt * 8;
        uint32_t h0, l0u, h1, l1u;
        split_pair_h(oacc[nt][0] * inv0, oacc[nt][1] * inv0, h0, l0u);
        split_pair_h(oacc[nt][2] * inv1, oacc[nt][3] * inv1, h1, l1u);
        *(uint32_t*)(AH + row0 * 1024 + col) = h0;
        *(uint32_t*)(AL + row0 * 1024 + col) = l0u;
        *(uint32_t*)(AH + row1 * 1024 + col) = h1;
        *(uint32_t*)(AL + row1 * 1024 + col) = l1u;
    }
}

// ---------------------------------------------------------------------------
extern "C" void kernel_launch(void* const* d_in, const int* in_sizes, int n_in,
                              void* d_out, int out_size)
{
    const float* Qin = (const float*)d_in[0];
    const float* Kin = (const float*)d_in[1];
    const float* Vin = (const float*)d_in[2];
    const float* Wq  = (const float*)d_in[3];
    const float* bq  = (const float*)d_in[4];
    const float* Wk  = (const float*)d_in[5];
    const float* bk  = (const float*)d_in[6];
    const float* Wv  = (const float*)d_in[7];
    const float* bv  = (const float*)d_in[8];
    const float* Wo  = (const float*)d_in[9];
    const float* bo  = (const float*)d_in[10];
    float* out = (float*)d_out;

    __half *xqH,*xqL,*xkH,*xkL,*xvH,*xvL;
    __half *wq,*wk,*wv,*wo;
    __half *q,*k,*v,*aH,*aL;
    cudaGetSymbolAddress((void**)&xqH, g_XqH); cudaGetSymbolAddress((void**)&xqL, g_XqL);
    cudaGetSymbolAddress((void**)&xkH, g_XkH); cudaGetSymbolAddress((void**)&xkL, g_XkL);
    cudaGetSymbolAddress((void**)&xvH, g_XvH); cudaGetSymbolAddress((void**)&xvL, g_XvL);
    cudaGetSymbolAddress((void**)&wq, g_Wq); cudaGetSymbolAddress((void**)&wk, g_Wk);
    cudaGetSymbolAddress((void**)&wv, g_Wv); cudaGetSymbolAddress((void**)&wo, g_Wo);
    cudaGetSymbolAddress((void**)&q,  g_Q);  cudaGetSymbolAddress((void**)&k,  g_K);
    cudaGetSymbolAddress((void**)&v,  g_V);
    cudaGetSymbolAddress((void**)&aH, g_AH); cudaGetSymbolAddress((void**)&aL, g_AL);

    cudaFuncSetAttribute(gemm_mma_kernel, cudaFuncAttributeMaxDynamicSharedMemorySize, GB_SMEM);
    cudaFuncSetAttribute(attn_mma_kernel, cudaFuncAttributeMaxDynamicSharedMemorySize, ATT_SMEM);

    const int nAct4 = MROWS * EMBED / 4;
    const int nW4   = EMBED * EMBED / 4;

    SplitJob sq = { Qin, xqH, xqL }, sk = { Kin, xkH, xkL }, sv = { Vin, xvH, xvL };
    dim3 split_grid((nAct4 + 255) / 256, 3);
    split3_kernel<<<split_grid, 256>>>(sq, sk, sv, nAct4);

    ConvJob cq = { Wq, wq }, ck = { Wk, wk }, cv = { Wv, wv }, co = { Wo, wo };
    dim3 conv_grid((nW4 + 255) / 256, 4);
    conv4_kernel<<<conv_grid, 256>>>(cq, ck, cv, co, nW4);

    const float qscale = 0.125f * 1.4426950408889634f;   // 1/sqrt(64) * log2(e)

    GemmArgs argQ = { xqH, xqL, wq, bq, nullptr, q, nullptr, qscale };
    GemmArgs argK = { xkH, xkL, wk, bk, nullptr, k, nullptr, 1.0f };
    GemmArgs argV = { xvH, xvL, wv, bv, nullptr, v, nullptr, 1.0f };  // plain out
    GemmArgs argO = { aH,  aL,  wo, bo, out,     nullptr, nullptr, 1.0f };

    dim3 qkv_grid(EMBED / 128, MROWS / 128, 3);   // (8, 32, 3)
    gemm_mma_kernel<<<qkv_grid, 256, GB_SMEM>>>(argQ, argK, argV);

    dim3 attn_grid(SEQQ / 64, NHEAD, BATCH);      // (32, 16, 2) = 1024 blocks
    attn_mma_kernel<<<attn_grid, 128, ATT_SMEM>>>(q, k, v, aH, aL);

    dim3 o_grid(EMBED / 128, MROWS / 128, 1);
    gemm_mma_kernel<<<o_grid, 256, GB_SMEM>>>(argO, argO, argO);
}

// round 12
// speedup vs baseline: 8.5861x; 1.0771x over previous
#include <cuda_runtime.h>
#include <cuda_fp16.h>
#include <cstdint>
#include <math.h>

#define EMBED 1024
#define NHEAD 16
#define HDIM  64
#define BATCH 2
#define SEQQ  2048
#define SEQK  2048
#define MROWS (BATCH*SEQQ)   // 4096

// ----------------------------- scratch (no allocs allowed) -----------------
__device__ __half g_XqH[MROWS*EMBED], g_XqL[MROWS*EMBED];   // input splits
__device__ __half g_XkH[MROWS*EMBED], g_XkL[MROWS*EMBED];
__device__ __half g_XvH[MROWS*EMBED], g_XvL[MROWS*EMBED];
__device__ __half g_Wq[EMBED*EMBED], g_Wk[EMBED*EMBED];     // plain fp16 weights
__device__ __half g_Wv[EMBED*EMBED], g_Wo[EMBED*EMBED];
__device__ __half g_Q [MROWS*EMBED];                        // plain fp16 activations
__device__ __half g_K [MROWS*EMBED];
__device__ __half g_V [MROWS*EMBED];
__device__ __half g_A [MROWS*EMBED];                        // attn out, plain fp16

// ----------------------------- helpers -------------------------------------
__device__ __forceinline__ uint32_t smem_u32(const void* p) {
    uint32_t a;
    asm("{ .reg .u64 t; cvta.to.shared.u64 t, %1; cvt.u32.u64 %0, t; }" : "=r"(a) : "l"(p));
    return a;
}
#define CP_ASYNC16(dst, src) \
    asm volatile("cp.async.cg.shared.global [%0], [%1], 16;" :: "r"(dst), "l"(src))
#define CP_COMMIT() asm volatile("cp.async.commit_group;" ::: "memory")
#define CP_WAIT(n)  asm volatile("cp.async.wait_group %0;" :: "n"(n) : "memory")

__device__ __forceinline__ void ldsm_x4(uint32_t* r, uint32_t addr) {
    asm volatile("ldmatrix.sync.aligned.m8n8.x4.shared.b16 {%0,%1,%2,%3}, [%4];"
        : "=r"(r[0]), "=r"(r[1]), "=r"(r[2]), "=r"(r[3]) : "r"(addr));
}
__device__ __forceinline__ void ldsm_x4_t(uint32_t* r, uint32_t addr) {
    asm volatile("ldmatrix.sync.aligned.m8n8.x4.trans.shared.b16 {%0,%1,%2,%3}, [%4];"
        : "=r"(r[0]), "=r"(r[1]), "=r"(r[2]), "=r"(r[3]) : "r"(addr));
}
__device__ __forceinline__ void mma_f16(float* c, const uint32_t* a, const uint32_t* b) {
    asm volatile(
        "mma.sync.aligned.m16n8k16.row.col.f32.f16.f16.f32 "
        "{%0,%1,%2,%3}, {%4,%5,%6,%7}, {%8,%9}, {%0,%1,%2,%3};"
        : "+f"(c[0]), "+f"(c[1]), "+f"(c[2]), "+f"(c[3])
        : "r"(a[0]), "r"(a[1]), "r"(a[2]), "r"(a[3]), "r"(b[0]), "r"(b[1]));
}
__device__ __forceinline__ float ex2f(float x) {
    float y; asm("ex2.approx.f32 %0, %1;" : "=f"(y) : "f"(x)); return y;
}
__device__ __forceinline__ uint32_t ex2_h2(float x, float y) {
    uint32_t h;
    asm("{\n\t.reg .b32 t;\n\t"
        "cvt.rn.f16x2.f32 t, %2, %1;\n\t"
        "ex2.approx.f16x2 %0, t;\n\t}"
        : "=r"(h) : "f"(x), "f"(y));
    return h;
}
__device__ __forceinline__ uint32_t pack_h2(float x, float y) {
    __half2 h = __float22half2_rn(make_float2(x, y));
    return *reinterpret_cast<uint32_t*>(&h);
}
__device__ __forceinline__ void split_pair_h(float x, float y, uint32_t& hi, uint32_t& lo) {
    __half2 h = __float22half2_rn(make_float2(x, y));
    float hx = __low2float(h), hy = __high2float(h);
    __half2 l = __float22half2_rn(make_float2(x - hx, y - hy));
    hi = *reinterpret_cast<uint32_t*>(&h);
    lo = *reinterpret_cast<uint32_t*>(&l);
}

// ----------------------------- fused conversions (one launch) --------------
// jobs 0..2: split fp32 -> (hi,lo), n4 = nAct4.  jobs 3..6: conv fp32 -> fp16.
struct PrepJob { const float* src; __half* hi; __half* lo; int n4; };
__global__ void prep_kernel(PrepJob j0, PrepJob j1, PrepJob j2, PrepJob j3,
                            PrepJob j4, PrepJob j5, PrepJob j6)
{
    PrepJob j;
    switch (blockIdx.y) {
        case 0: j = j0; break; case 1: j = j1; break; case 2: j = j2; break;
        case 3: j = j3; break; case 4: j = j4; break; case 5: j = j5; break;
        default: j = j6; break;
    }
    int i = blockIdx.x * blockDim.x + threadIdx.x;
    if (i >= j.n4) return;
    float4 v = ((const float4*)j.src)[i];
    if (j.lo) {
        uint32_t h0, l0, h1, l1;
        split_pair_h(v.x, v.y, h0, l0);
        split_pair_h(v.z, v.w, h1, l1);
        ((uint32_t*)j.hi)[2*i] = h0; ((uint32_t*)j.hi)[2*i+1] = h1;
        ((uint32_t*)j.lo)[2*i] = l0; ((uint32_t*)j.lo)[2*i+1] = l1;
    } else {
        ((uint32_t*)j.hi)[2*i]   = pack_h2(v.x, v.y);
        ((uint32_t*)j.hi)[2*i+1] = pack_h2(v.z, v.w);
    }
}

// ----------------------------- HMMA GEMM, 2-term A (QKV) -------------------
struct GemmArgs {
    const __half *Ah, *Al, *Bh;
    const float* bias;
    float* Cf;
    __half *Ch;
    float scale;
};

#define GB_AOFF  0
#define GB_ALOFF 16384
#define GB_BOFF  32768
#define GB_STAGE 49152
#define GB_SMEM  (2*GB_STAGE) // 98304

__global__ void __launch_bounds__(256, 2) gemm_mma_kernel(
    GemmArgs ga0, GemmArgs ga1, GemmArgs ga2)
{
    const GemmArgs g = (blockIdx.z == 0) ? ga0 : (blockIdx.z == 1) ? ga1 : ga2;

    extern __shared__ char sm[];
    const uint32_t sbase = smem_u32(sm);
    const int tid = threadIdx.x;
    const int lane = tid & 31, wid = tid >> 5;
    const int wm = wid & 1, wn = wid >> 1;
    const int m0 = blockIdx.y * 128, n0 = blockIdx.x * 128;

    float acc[4][4][4];
#pragma unroll
    for (int i = 0; i < 4; i++)
#pragma unroll
        for (int j = 0; j < 4; j++)
#pragma unroll
            for (int k = 0; k < 4; k++) acc[i][j][k] = 0.f;

#define ISSUE_STAGE(buf, k0)                                                   \
    do {                                                                       \
        const uint32_t st = sbase + (buf) * GB_STAGE;                          \
        _Pragma("unroll")                                                      \
        for (int c = 0; c < 4; c++) {                                          \
            const int idx = c * 256 + tid;                                     \
            const int row = idx >> 3, seg = idx & 7;                           \
            uint32_t off = (uint32_t)(row * 128 + seg * 16);                   \
            off ^= ((off >> 3) & 0x70);                                        \
            const size_t gaa = (size_t)(m0 + row) * 1024 + (k0) + seg * 8;     \
            const size_t gbb = (size_t)(n0 + row) * 1024 + (k0) + seg * 8;     \
            CP_ASYNC16(st + GB_AOFF + off,  (const char*)(g.Ah + gaa));        \
            CP_ASYNC16(st + GB_ALOFF + off, (const char*)(g.Al + gaa));        \
            CP_ASYNC16(st + GB_BOFF + off,  (const char*)(g.Bh + gbb));        \
        }                                                                      \
    } while (0)

    ISSUE_STAGE(0, 0);
    CP_COMMIT();

    for (int s = 0; s < 16; s++) {
        if (s < 15) {
            ISSUE_STAGE((s + 1) & 1, (s + 1) * 64);
            CP_COMMIT();
            CP_WAIT(1);
        } else {
            CP_WAIT(0);
        }
        __syncthreads();

        const uint32_t st = sbase + (s & 1) * GB_STAGE;
#pragma unroll
        for (int ks = 0; ks < 4; ks++) {
            uint32_t ah[4][4], al[4][4], bh[2][4];
            const int ar = (lane & 7) + ((lane >> 3) & 1) * 8;
            const int ak = ks * 16 + ((lane >> 4) & 1) * 8;
#pragma unroll
            for (int mt = 0; mt < 4; mt++) {
                uint32_t off = (uint32_t)((wm * 64 + mt * 16 + ar) * 128 + ak * 2);
                off ^= ((off >> 3) & 0x70);
                ldsm_x4(ah[mt], st + GB_AOFF + off);
                ldsm_x4(al[mt], st + GB_ALOFF + off);
            }
            const int bn = (lane & 7) + ((lane >> 4) & 1) * 8;
            const int bk = ks * 16 + ((lane >> 3) & 1) * 8;
#pragma unroll
            for (int np = 0; np < 2; np++) {
                uint32_t off = (uint32_t)((wn * 32 + np * 16 + bn) * 128 + bk * 2);
                off ^= ((off >> 3) & 0x70);
                ldsm_x4(bh[np], st + GB_BOFF + off);
            }
#pragma unroll
            for (int mt = 0; mt < 4; mt++) {
#pragma unroll
                for (int nt = 0; nt < 4; nt++) {
                    const uint32_t* bhf = &bh[nt >> 1][(nt & 1) * 2];
                    mma_f16(acc[mt][nt], ah[mt], bhf);
                    mma_f16(acc[mt][nt], al[mt], bhf);
                }
            }
        }
        __syncthreads();
    }
#undef ISSUE_STAGE

#pragma unroll
    for (int mt = 0; mt < 4; mt++) {
        const int row = m0 + wm * 64 + mt * 16 + (lane >> 2);
#pragma unroll
        for (int nt = 0; nt < 4; nt++) {
            const int col = n0 + wn * 32 + nt * 8 + (lane & 3) * 2;
            const float bx = __ldg(g.bias + col), by = __ldg(g.bias + col + 1);
            float v0 = (acc[mt][nt][0] + bx) * g.scale;
            float v1 = (acc[mt][nt][1] + by) * g.scale;
            float v2 = (acc[mt][nt][2] + bx) * g.scale;
            float v3 = (acc[mt][nt][3] + by) * g.scale;
            if (g.Cf) {
                *(float2*)(g.Cf + (size_t)row * 1024 + col)       = make_float2(v0, v1);
                *(float2*)(g.Cf + (size_t)(row + 8) * 1024 + col) = make_float2(v2, v3);
            } else {
                *(uint32_t*)(g.Ch + (size_t)row * 1024 + col)       = pack_h2(v0, v1);
                *(uint32_t*)(g.Ch + (size_t)(row + 8) * 1024 + col) = pack_h2(v2, v3);
            }
        }
    }
}

// ----------------------------- HMMA GEMM, 1-term A (Wo) --------------------
#define G1_AOFF  0
#define G1_BOFF  16384
#define G1_STAGE 32768
#define G1_SMEM  (2*G1_STAGE) // 65536

__global__ void __launch_bounds__(256, 2) gemm1_mma_kernel(
    const __half* __restrict__ Ah, const __half* __restrict__ Bh,
    const float* __restrict__ bias, float* __restrict__ Cf)
{
    extern __shared__ char sm[];
    const uint32_t sbase = smem_u32(sm);
    const int tid = threadIdx.x;
    const int lane = tid & 31, wid = tid >> 5;
    const int wm = wid & 1, wn = wid >> 1;
    const int m0 = blockIdx.y * 128, n0 = blockIdx.x * 128;

    float acc[4][4][4];
#pragma unroll
    for (int i = 0; i < 4; i++)
#pragma unroll
        for (int j = 0; j < 4; j++)
#pragma unroll
            for (int k = 0; k < 4; k++) acc[i][j][k] = 0.f;

#define ISSUE_STAGE1(buf, k0)                                                  \
    do {                                                                       \
        const uint32_t st = sbase + (buf) * G1_STAGE;                          \
        _Pragma("unroll")                                                      \
        for (int c = 0; c < 4; c++) {                                          \
            const int idx = c * 256 + tid;                                     \
            const int row = idx >> 3, seg = idx & 7;                           \
            uint32_t off = (uint32_t)(row * 128 + seg * 16);                   \
            off ^= ((off >> 3) & 0x70);                                        \
            const size_t gaa = (size_t)(m0 + row) * 1024 + (k0) + seg * 8;     \
            const size_t gbb = (size_t)(n0 + row) * 1024 + (k0) + seg * 8;     \
            CP_ASYNC16(st + G1_AOFF + off, (const char*)(Ah + gaa));           \
            CP_ASYNC16(st + G1_BOFF + off, (const char*)(Bh + gbb));           \
        }                                                                      \
    } while (0)

    ISSUE_STAGE1(0, 0);
    CP_COMMIT();

    for (int s = 0; s < 16; s++) {
        if (s < 15) {
            ISSUE_STAGE1((s + 1) & 1, (s + 1) * 64);
            CP_COMMIT();
            CP_WAIT(1);
        } else {
            CP_WAIT(0);
        }
        __syncthreads();

        const uint32_t st = sbase + (s & 1) * G1_STAGE;
#pragma unroll
        for (int ks = 0; ks < 4; ks++) {
            uint32_t ah[4][4], bh[2][4];
            const int ar = (lane & 7) + ((lane >> 3) & 1) * 8;
            const int ak = ks * 16 + ((lane >> 4) & 1) * 8;
#pragma unroll
            for (int mt = 0; mt < 4; mt++) {
                uint32_t off = (uint32_t)((wm * 64 + mt * 16 + ar) * 128 + ak * 2);
                off ^= ((off >> 3) & 0x70);
                ldsm_x4(ah[mt], st + G1_AOFF + off);
            }
            const int bn = (lane & 7) + ((lane >> 4) & 1) * 8;
            const int bk = ks * 16 + ((lane >> 3) & 1) * 8;
#pragma unroll
            for (int np = 0; np < 2; np++) {
                uint32_t off = (uint32_t)((wn * 32 + np * 16 + bn) * 128 + bk * 2);
                off ^= ((off >> 3) & 0x70);
                ldsm_x4(bh[np], st + G1_BOFF + off);
            }
#pragma unroll
            for (int mt = 0; mt < 4; mt++)
#pragma unroll
                for (int nt = 0; nt < 4; nt++)
                    mma_f16(acc[mt][nt], ah[mt], &bh[nt >> 1][(nt & 1) * 2]);
        }
        __syncthreads();
    }
#undef ISSUE_STAGE1

#pragma unroll
    for (int mt = 0; mt < 4; mt++) {
        const int row = m0 + wm * 64 + mt * 16 + (lane >> 2);
#pragma unroll
        for (int nt = 0; nt < 4; nt++) {
            const int col = n0 + wn * 32 + nt * 8 + (lane & 3) * 2;
            const float bx = __ldg(bias + col), by = __ldg(bias + col + 1);
            *(float2*)(Cf + (size_t)row * 1024 + col) =
                make_float2(acc[mt][nt][0] + bx, acc[mt][nt][1] + by);
            *(float2*)(Cf + (size_t)(row + 8) * 1024 + col) =
                make_float2(acc[mt][nt][2] + bx, acc[mt][nt][3] + by);
        }
    }
}

// ----------------------------- MMA flash attention (fp16, proven) ----------
#define ATT_KOFF  0
#define ATT_VOFF  8192
#define ATT_STAGE 16384
#define ATT_QOFF  (2*ATT_STAGE)          // 32768
#define ATT_SMEM  (ATT_QOFF + 8192)      // 40960

__global__ void __launch_bounds__(128) attn_mma_kernel(
    const __half* __restrict__ Q,
    const __half* __restrict__ K,
    const __half* __restrict__ V,
    __half* __restrict__ A)
{
    extern __shared__ char sm[];
    const uint32_t sb = smem_u32(sm);
    const int tid = threadIdx.x;
    const int lane = tid & 31, wid = tid >> 5;
    const int b = blockIdx.z, h = blockIdx.y;
    const int q0 = blockIdx.x * 64;

    const size_t qbase = ((size_t)(b * SEQQ + q0)) * EMBED + h * HDIM;
#pragma unroll
    for (int c = 0; c < 4; c++) {
        const int idx = c * 128 + tid;
        const int row = idx >> 3, seg = idx & 7;
        uint32_t off = (uint32_t)(row * 128 + seg * 16);
        off ^= ((off >> 3) & 0x70);
        CP_ASYNC16(sb + ATT_QOFF + off,
                   (const char*)(Q + qbase + (size_t)row * 1024 + seg * 8));
    }
    CP_COMMIT();

#define ISSUE_KV(buf, kt)                                                      \
    do {                                                                       \
        const uint32_t st_ = sb + (buf) * ATT_STAGE;                           \
        const size_t kb = ((size_t)(b * SEQK + (kt) * 64)) * EMBED + h * HDIM; \
        _Pragma("unroll")                                                      \
        for (int c = 0; c < 4; c++) {                                          \
            const int idx = c * 128 + tid;                                     \
            const int row = idx >> 3, seg = idx & 7;                           \
            uint32_t off = (uint32_t)(row * 128 + seg * 16);                   \
            off ^= ((off >> 3) & 0x70);                                        \
            const size_t g = kb + (size_t)row * 1024 + seg * 8;                \
            CP_ASYNC16(st_ + ATT_KOFF + off, (const char*)(K + g));            \
            CP_ASYNC16(st_ + ATT_VOFF + off, (const char*)(V + g));            \
        }                                                                      \
    } while (0)

    ISSUE_KV(0, 0);
    CP_COMMIT();
    CP_WAIT(1);
    __syncthreads();

    uint32_t qh[4][4];
    {
        const int ar = (lane & 7) + ((lane >> 3) & 1) * 8;
#pragma unroll
        for (int ks = 0; ks < 4; ks++) {
            const int ak = ks * 16 + ((lane >> 4) & 1) * 8;
            uint32_t off = (uint32_t)((wid * 16 + ar) * 128 + ak * 2);
            off ^= ((off >> 3) & 0x70);
            ldsm_x4(qh[ks], sb + ATT_QOFF + off);
        }
    }

    const uint32_t onefrag = ((lane >> 2) == 0) ? 0x3C003C00u : 0u;
    const uint32_t ones2[2] = { onefrag, onefrag };

    float m0 = -1e30f, m1 = -1e30f;
    float oacc[9][4];
#pragma unroll
    for (int nt = 0; nt < 9; nt++)
#pragma unroll
        for (int k = 0; k < 4; k++) oacc[nt][k] = 0.f;

    for (int kt = 0; kt < 32; kt++) {
        if (kt < 31) {
            ISSUE_KV((kt + 1) & 1, kt + 1);
            CP_COMMIT();
            CP_WAIT(1);
        } else {
            CP_WAIT(0);
        }
        __syncthreads();
        const uint32_t st = sb + (kt & 1) * ATT_STAGE;

        float sacc[8][4];
#pragma unroll
        for (int nt = 0; nt < 8; nt++)
#pragma unroll
            for (int k = 0; k < 4; k++) sacc[nt][k] = 0.f;

#pragma unroll
        for (int ks = 0; ks < 4; ks++) {
            uint32_t kh[4][4];
            const int bn = (lane & 7) + ((lane >> 4) & 1) * 8;
            const int bk = ks * 16 + ((lane >> 3) & 1) * 8;
#pragma unroll
            for (int g = 0; g < 4; g++) {
                uint32_t off = (uint32_t)((g * 16 + bn) * 128 + bk * 2);
                off ^= ((off >> 3) & 0x70);
                ldsm_x4(kh[g], st + ATT_KOFF + off);
            }
#pragma unroll
            for (int nt = 0; nt < 8; nt++)
                mma_f16(sacc[nt], qh[ks], &kh[nt >> 1][(nt & 1) * 2]);
        }

        float mx0 = sacc[0][0], mx1 = sacc[0][2];
#pragma unroll
        for (int nt = 0; nt < 8; nt++) {
            mx0 = fmaxf(mx0, fmaxf(sacc[nt][0], sacc[nt][1]));
            mx1 = fmaxf(mx1, fmaxf(sacc[nt][2], sacc[nt][3]));
        }
        mx0 = fmaxf(mx0, __shfl_xor_sync(0xffffffffu, mx0, 1));
        mx0 = fmaxf(mx0, __shfl_xor_sync(0xffffffffu, mx0, 2));
        mx1 = fmaxf(mx1, __shfl_xor_sync(0xffffffffu, mx1, 1));
        mx1 = fmaxf(mx1, __shfl_xor_sync(0xffffffffu, mx1, 2));
        const float mn0 = fmaxf(m0, mx0), mn1 = fmaxf(m1, mx1);
        const float a0 = ex2f(m0 - mn0), a1 = ex2f(m1 - mn1);
        m0 = mn0; m1 = mn1;

        uint32_t ph[4][4];
#pragma unroll
        for (int kf = 0; kf < 4; kf++) {
            ph[kf][0] = ex2_h2(sacc[2*kf][0]   - m0, sacc[2*kf][1]   - m0);
            ph[kf][1] = ex2_h2(sacc[2*kf][2]   - m1, sacc[2*kf][3]   - m1);
            ph[kf][2] = ex2_h2(sacc[2*kf+1][0] - m0, sacc[2*kf+1][1] - m0);
            ph[kf][3] = ex2_h2(sacc[2*kf+1][2] - m1, sacc[2*kf+1][3] - m1);
        }

#pragma unroll
        for (int nt = 0; nt < 9; nt++) {
            oacc[nt][0] *= a0; oacc[nt][1] *= a0;
            oacc[nt][2] *= a1; oacc[nt][3] *= a1;
        }

#pragma unroll
        for (int ks = 0; ks < 4; ks++) {
            uint32_t vh[4][4];
            const int vk = ((lane >> 3) & 1) * 8 + (lane & 7);
            const int vd = ((lane >> 4) & 1) * 8;
#pragma unroll
            for (int dp = 0; dp < 4; dp++) {
                uint32_t off = (uint32_t)((ks * 16 + vk) * 128 + (dp * 16 + vd) * 2);
                off ^= ((off >> 3) & 0x70);
                ldsm_x4_t(vh[dp], st + ATT_VOFF + off);
            }
#pragma unroll
            for (int nt = 0; nt < 8; nt++)
                mma_f16(oacc[nt], ph[ks], &vh[nt >> 1][(nt & 1) * 2]);
            mma_f16(oacc[8], ph[ks], ones2);
        }
        __syncthreads();
    }
#undef ISSUE_KV

    const int src = lane & ~3;
    const float l0 = __shfl_sync(0xffffffffu, oacc[8][0], src);
    const float l1 = __shfl_sync(0xffffffffu, oacc[8][2], src);

    const float inv0 = 1.f / l0, inv1 = 1.f / l1;
    const size_t row0 = (size_t)(b * SEQQ + q0 + wid * 16 + (lane >> 2));
    const size_t row1 = row0 + 8;
    const int colb = h * HDIM + (lane & 3) * 2;
#pragma unroll
    for (int nt = 0; nt < 8; nt++) {
        const int col = colb + nt * 8;
        *(uint32_t*)(A + row0 * 1024 + col) = pack_h2(oacc[nt][0] * inv0, oacc[nt][1] * inv0);
        *(uint32_t*)(A + row1 * 1024 + col) = pack_h2(oacc[nt][2] * inv1, oacc[nt][3] * inv1);
    }
}

// ---------------------------------------------------------------------------
extern "C" void kernel_launch(void* const* d_in, const int* in_sizes, int n_in,
                              void* d_out, int out_size)
{
    const float* Qin = (const float*)d_in[0];
    const float* Kin = (const float*)d_in[1];
    const float* Vin = (const float*)d_in[2];
    const float* Wq  = (const float*)d_in[3];
    const float* bq  = (const float*)d_in[4];
    const float* Wk  = (const float*)d_in[5];
    const float* bk  = (const float*)d_in[6];
    const float* Wv  = (const float*)d_in[7];
    const float* bv  = (const float*)d_in[8];
    const float* Wo  = (const float*)d_in[9];
    const float* bo  = (const float*)d_in[10];
    float* out = (float*)d_out;

    __half *xqH,*xqL,*xkH,*xkL,*xvH,*xvL;
    __half *wq,*wk,*wv,*wo;
    __half *q,*k,*v,*a;
    cudaGetSymbolAddress((void**)&xqH, g_XqH); cudaGetSymbolAddress((void**)&xqL, g_XqL);
    cudaGetSymbolAddress((void**)&xkH, g_XkH); cudaGetSymbolAddress((void**)&xkL, g_XkL);
    cudaGetSymbolAddress((void**)&xvH, g_XvH); cudaGetSymbolAddress((void**)&xvL, g_XvL);
    cudaGetSymbolAddress((void**)&wq, g_Wq); cudaGetSymbolAddress((void**)&wk, g_Wk);
    cudaGetSymbolAddress((void**)&wv, g_Wv); cudaGetSymbolAddress((void**)&wo, g_Wo);
    cudaGetSymbolAddress((void**)&q,  g_Q);  cudaGetSymbolAddress((void**)&k,  g_K);
    cudaGetSymbolAddress((void**)&v,  g_V);  cudaGetSymbolAddress((void**)&a,  g_A);

    cudaFuncSetAttribute(gemm_mma_kernel,  cudaFuncAttributeMaxDynamicSharedMemorySize, GB_SMEM);
    cudaFuncSetAttribute(gemm1_mma_kernel, cudaFuncAttributeMaxDynamicSharedMemorySize, G1_SMEM);
    cudaFuncSetAttribute(attn_mma_kernel,  cudaFuncAttributeMaxDynamicSharedMemorySize, ATT_SMEM);

    const int nAct4 = MROWS * EMBED / 4;   // 1048576
    const int nW4   = EMBED * EMBED / 4;   // 262144

    PrepJob p0 = { Qin, xqH, xqL, nAct4 };
    PrepJob p1 = { Kin, xkH, xkL, nAct4 };
    PrepJob p2 = { Vin, xvH, xvL, nAct4 };
    PrepJob p3 = { Wq, wq, nullptr, nW4 };
    PrepJob p4 = { Wk, wk, nullptr, nW4 };
    PrepJob p5 = { Wv, wv, nullptr, nW4 };
    PrepJob p6 = { Wo, wo, nullptr, nW4 };
    dim3 prep_grid((nAct4 + 255) / 256, 7);
    prep_kernel<<<prep_grid, 256>>>(p0, p1, p2, p3, p4, p5, p6);

    const float qscale = 0.125f * 1.4426950408889634f;   // 1/sqrt(64) * log2(e)

    GemmArgs argQ = { xqH, xqL, wq, bq, nullptr, q, qscale };
    GemmArgs argK = { xkH, xkL, wk, bk, nullptr, k, 1.0f };
    GemmArgs argV = { xvH, xvL, wv, bv, nullptr, v, 1.0f };

    dim3 qkv_grid(EMBED / 128, MROWS / 128, 3);   // (8, 32, 3)
    gemm_mma_kernel<<<qkv_grid, 256, GB_SMEM>>>(argQ, argK, argV);

    dim3 attn_grid(SEQQ / 64, NHEAD, BATCH);      // (32, 16, 2)
    attn_mma_kernel<<<attn_grid, 128, ATT_SMEM>>>(q, k, v, a);

    dim3 o_grid(EMBED / 128, MROWS / 128);        // (8, 32)
    gemm1_mma_kernel<<<o_grid, 256, G1_SMEM>>>(a, wo, bo, out);
}

// round 13
// speedup vs baseline: 8.8314x; 1.0286x over previous
#include <cuda_runtime.h>
#include <cuda_fp16.h>
#include <cstdint>
#include <math.h>

#define EMBED 1024
#define NHEAD 16
#define HDIM  64
#define BATCH 2
#define SEQQ  2048
#define SEQK  2048
#define MROWS (BATCH*SEQQ)   // 4096

// ----------------------------- scratch (no allocs allowed) -----------------
__device__ __half g_XqH[MROWS*EMBED], g_XqL[MROWS*EMBED];   // input splits (Q,K)
__device__ __half g_XkH[MROWS*EMBED], g_XkL[MROWS*EMBED];
__device__ __half g_Xv [MROWS*EMBED];                       // V input plain fp16
__device__ __half g_Wq[EMBED*EMBED], g_Wk[EMBED*EMBED];     // plain fp16 weights
__device__ __half g_Wv[EMBED*EMBED], g_Wo[EMBED*EMBED];
__device__ __half g_Q [MROWS*EMBED];                        // plain fp16 activations
__device__ __half g_K [MROWS*EMBED];
__device__ __half g_V [MROWS*EMBED];
__device__ __half g_A [MROWS*EMBED];                        // attn out, plain fp16

// ----------------------------- helpers -------------------------------------
__device__ __forceinline__ uint32_t smem_u32(const void* p) {
    uint32_t a;
    asm("{ .reg .u64 t; cvta.to.shared.u64 t, %1; cvt.u32.u64 %0, t; }" : "=r"(a) : "l"(p));
    return a;
}
#define CP_ASYNC16(dst, src) \
    asm volatile("cp.async.cg.shared.global [%0], [%1], 16;" :: "r"(dst), "l"(src))
#define CP_COMMIT() asm volatile("cp.async.commit_group;" ::: "memory")
#define CP_WAIT(n)  asm volatile("cp.async.wait_group %0;" :: "n"(n) : "memory")

__device__ __forceinline__ void ldsm_x4(uint32_t* r, uint32_t addr) {
    asm volatile("ldmatrix.sync.aligned.m8n8.x4.shared.b16 {%0,%1,%2,%3}, [%4];"
        : "=r"(r[0]), "=r"(r[1]), "=r"(r[2]), "=r"(r[3]) : "r"(addr));
}
__device__ __forceinline__ void ldsm_x4_t(uint32_t* r, uint32_t addr) {
    asm volatile("ldmatrix.sync.aligned.m8n8.x4.trans.shared.b16 {%0,%1,%2,%3}, [%4];"
        : "=r"(r[0]), "=r"(r[1]), "=r"(r[2]), "=r"(r[3]) : "r"(addr));
}
__device__ __forceinline__ void mma_f16(float* c, const uint32_t* a, const uint32_t* b) {
    asm volatile(
        "mma.sync.aligned.m16n8k16.row.col.f32.f16.f16.f32 "
        "{%0,%1,%2,%3}, {%4,%5,%6,%7}, {%8,%9}, {%0,%1,%2,%3};"
        : "+f"(c[0]), "+f"(c[1]), "+f"(c[2]), "+f"(c[3])
        : "r"(a[0]), "r"(a[1]), "r"(a[2]), "r"(a[3]), "r"(b[0]), "r"(b[1]));
}
__device__ __forceinline__ float ex2f(float x) {
    float y; asm("ex2.approx.f32 %0, %1;" : "=f"(y) : "f"(x)); return y;
}
__device__ __forceinline__ uint32_t ex2_h2(float x, float y) {
    uint32_t h;
    asm("{\n\t.reg .b32 t;\n\t"
        "cvt.rn.f16x2.f32 t, %2, %1;\n\t"
        "ex2.approx.f16x2 %0, t;\n\t}"
        : "=r"(h) : "f"(x), "f"(y));
    return h;
}
__device__ __forceinline__ uint32_t pack_h2(float x, float y) {
    __half2 h = __float22half2_rn(make_float2(x, y));
    return *reinterpret_cast<uint32_t*>(&h);
}
__device__ __forceinline__ void split_pair_h(float x, float y, uint32_t& hi, uint32_t& lo) {
    __half2 h = __float22half2_rn(make_float2(x, y));
    float hx = __low2float(h), hy = __high2float(h);
    __half2 l = __float22half2_rn(make_float2(x - hx, y - hy));
    hi = *reinterpret_cast<uint32_t*>(&h);
    lo = *reinterpret_cast<uint32_t*>(&l);
}

// ----------------------------- fused conversions (one launch) --------------
struct PrepJob { const float* src; __half* hi; __half* lo; int n4; };
__global__ void prep_kernel(PrepJob j0, PrepJob j1, PrepJob j2, PrepJob j3,
                            PrepJob j4, PrepJob j5, PrepJob j6)
{
    PrepJob j;
    switch (blockIdx.y) {
        case 0: j = j0; break; case 1: j = j1; break; case 2: j = j2; break;
        case 3: j = j3; break; case 4: j = j4; break; case 5: j = j5; break;
        default: j = j6; break;
    }
    int i = blockIdx.x * blockDim.x + threadIdx.x;
    if (i >= j.n4) return;
    float4 v = ((const float4*)j.src)[i];
    if (j.lo) {
        uint32_t h0, l0, h1, l1;
        split_pair_h(v.x, v.y, h0, l0);
        split_pair_h(v.z, v.w, h1, l1);
        ((uint32_t*)j.hi)[2*i] = h0; ((uint32_t*)j.hi)[2*i+1] = h1;
        ((uint32_t*)j.lo)[2*i] = l0; ((uint32_t*)j.lo)[2*i+1] = l1;
    } else {
        ((uint32_t*)j.hi)[2*i]   = pack_h2(v.x, v.y);
        ((uint32_t*)j.hi)[2*i+1] = pack_h2(v.z, v.w);
    }
}

// ----------------------------- HMMA GEMM (QKV batched) ---------------------
// 2-term A if Al != nullptr, else 1-term. Branches are block-uniform.
struct GemmArgs {
    const __half *Ah, *Al, *Bh;
    const float* bias;
    float* Cf;
    __half *Ch;
    float scale;
};

#define GB_AOFF  0
#define GB_ALOFF 16384
#define GB_BOFF  32768
#define GB_STAGE 49152
#define GB_SMEM  (2*GB_STAGE) // 98304

__global__ void __launch_bounds__(256, 2) gemm_mma_kernel(
    GemmArgs ga0, GemmArgs ga1, GemmArgs ga2)
{
    const GemmArgs g = (blockIdx.z == 0) ? ga0 : (blockIdx.z == 1) ? ga1 : ga2;
    const bool two = (g.Al != nullptr);

    extern __shared__ char sm[];
    const uint32_t sbase = smem_u32(sm);
    const int tid = threadIdx.x;
    const int lane = tid & 31, wid = tid >> 5;
    const int wm = wid & 1, wn = wid >> 1;
    const int m0 = blockIdx.y * 128, n0 = blockIdx.x * 128;

    float acc[4][4][4];
#pragma unroll
    for (int i = 0; i < 4; i++)
#pragma unroll
        for (int j = 0; j < 4; j++)
#pragma unroll
            for (int k = 0; k < 4; k++) acc[i][j][k] = 0.f;

#define ISSUE_STAGE(buf, k0)                                                   \
    do {                                                                       \
        const uint32_t st = sbase + (buf) * GB_STAGE;                          \
        _Pragma("unroll")                                                      \
        for (int c = 0; c < 4; c++) {                                          \
            const int idx = c * 256 + tid;                                     \
            const int row = idx >> 3, seg = idx & 7;                           \
            uint32_t off = (uint32_t)(row * 128 + seg * 16);                   \
            off ^= ((off >> 3) & 0x70);                                        \
            const size_t gaa = (size_t)(m0 + row) * 1024 + (k0) + seg * 8;     \
            const size_t gbb = (size_t)(n0 + row) * 1024 + (k0) + seg * 8;     \
            CP_ASYNC16(st + GB_AOFF + off,  (const char*)(g.Ah + gaa));        \
            if (two) CP_ASYNC16(st + GB_ALOFF + off, (const char*)(g.Al + gaa)); \
            CP_ASYNC16(st + GB_BOFF + off,  (const char*)(g.Bh + gbb));        \
        }                                                                      \
    } while (0)

    ISSUE_STAGE(0, 0);
    CP_COMMIT();

    for (int s = 0; s < 16; s++) {
        if (s < 15) {
            ISSUE_STAGE((s + 1) & 1, (s + 1) * 64);
            CP_COMMIT();
            CP_WAIT(1);
        } else {
            CP_WAIT(0);
        }
        __syncthreads();

        const uint32_t st = sbase + (s & 1) * GB_STAGE;
#pragma unroll
        for (int ks = 0; ks < 4; ks++) {
            uint32_t ah[4][4], al[4][4], bh[2][4];
            const int ar = (lane & 7) + ((lane >> 3) & 1) * 8;
            const int ak = ks * 16 + ((lane >> 4) & 1) * 8;
#pragma unroll
            for (int mt = 0; mt < 4; mt++) {
                uint32_t off = (uint32_t)((wm * 64 + mt * 16 + ar) * 128 + ak * 2);
                off ^= ((off >> 3) & 0x70);
                ldsm_x4(ah[mt], st + GB_AOFF + off);
                if (two) ldsm_x4(al[mt], st + GB_ALOFF + off);
            }
            const int bn = (lane & 7) + ((lane >> 4) & 1) * 8;
            const int bk = ks * 16 + ((lane >> 3) & 1) * 8;
#pragma unroll
            for (int np = 0; np < 2; np++) {
                uint32_t off = (uint32_t)((wn * 32 + np * 16 + bn) * 128 + bk * 2);
                off ^= ((off >> 3) & 0x70);
                ldsm_x4(bh[np], st + GB_BOFF + off);
            }
#pragma unroll
            for (int mt = 0; mt < 4; mt++) {
#pragma unroll
                for (int nt = 0; nt < 4; nt++) {
                    const uint32_t* bhf = &bh[nt >> 1][(nt & 1) * 2];
                    mma_f16(acc[mt][nt], ah[mt], bhf);
                    if (two) mma_f16(acc[mt][nt], al[mt], bhf);
                }
            }
        }
        __syncthreads();
    }
#undef ISSUE_STAGE

#pragma unroll
    for (int mt = 0; mt < 4; mt++) {
        const int row = m0 + wm * 64 + mt * 16 + (lane >> 2);
#pragma unroll
        for (int nt = 0; nt < 4; nt++) {
            const int col = n0 + wn * 32 + nt * 8 + (lane & 3) * 2;
            const float bx = __ldg(g.bias + col), by = __ldg(g.bias + col + 1);
            float v0 = (acc[mt][nt][0] + bx) * g.scale;
            float v1 = (acc[mt][nt][1] + by) * g.scale;
            float v2 = (acc[mt][nt][2] + bx) * g.scale;
            float v3 = (acc[mt][nt][3] + by) * g.scale;
            if (g.Cf) {
                *(float2*)(g.Cf + (size_t)row * 1024 + col)       = make_float2(v0, v1);
                *(float2*)(g.Cf + (size_t)(row + 8) * 1024 + col) = make_float2(v2, v3);
            } else {
                *(uint32_t*)(g.Ch + (size_t)row * 1024 + col)       = pack_h2(v0, v1);
                *(uint32_t*)(g.Ch + (size_t)(row + 8) * 1024 + col) = pack_h2(v2, v3);
            }
        }
    }
}

// ----------------------------- HMMA GEMM, 1-term A (Wo) --------------------
#define G1_AOFF  0
#define G1_BOFF  16384
#define G1_STAGE 32768
#define G1_SMEM  (2*G1_STAGE) // 65536

__global__ void __launch_bounds__(256, 2) gemm1_mma_kernel(
    const __half* __restrict__ Ah, const __half* __restrict__ Bh,
    const float* __restrict__ bias, float* __restrict__ Cf)
{
    extern __shared__ char sm[];
    const uint32_t sbase = smem_u32(sm);
    const int tid = threadIdx.x;
    const int lane = tid & 31, wid = tid >> 5;
    const int wm = wid & 1, wn = wid >> 1;
    const int m0 = blockIdx.y * 128, n0 = blockIdx.x * 128;

    float acc[4][4][4];
#pragma unroll
    for (int i = 0; i < 4; i++)
#pragma unroll
        for (int j = 0; j < 4; j++)
#pragma unroll
            for (int k = 0; k < 4; k++) acc[i][j][k] = 0.f;

#define ISSUE_STAGE1(buf, k0)                                                  \
    do {                                                                       \
        const uint32_t st = sbase + (buf) * G1_STAGE;                          \
        _Pragma("unroll")                                                      \
        for (int c = 0; c < 4; c++) {                                          \
            const int idx = c * 256 + tid;                                     \
            const int row = idx >> 3, seg = idx & 7;                           \
            uint32_t off = (uint32_t)(row * 128 + seg * 16);                   \
            off ^= ((off >> 3) & 0x70);                                        \
            const size_t gaa = (size_t)(m0 + row) * 1024 + (k0) + seg * 8;     \
            const size_t gbb = (size_t)(n0 + row) * 1024 + (k0) + seg * 8;     \
            CP_ASYNC16(st + G1_AOFF + off, (const char*)(Ah + gaa));           \
            CP_ASYNC16(st + G1_BOFF + off, (const char*)(Bh + gbb));           \
        }                                                                      \
    } while (0)

    ISSUE_STAGE1(0, 0);
    CP_COMMIT();

    for (int s = 0; s < 16; s++) {
        if (s < 15) {
            ISSUE_STAGE1((s + 1) & 1, (s + 1) * 64);
            CP_COMMIT();
            CP_WAIT(1);
        } else {
            CP_WAIT(0);
        }
        __syncthreads();

        const uint32_t st = sbase + (s & 1) * G1_STAGE;
#pragma unroll
        for (int ks = 0; ks < 4; ks++) {
            uint32_t ah[4][4], bh[2][4];
            const int ar = (lane & 7) + ((lane >> 3) & 1) * 8;
            const int ak = ks * 16 + ((lane >> 4) & 1) * 8;
#pragma unroll
            for (int mt = 0; mt < 4; mt++) {
                uint32_t off = (uint32_t)((wm * 64 + mt * 16 + ar) * 128 + ak * 2);
                off ^= ((off >> 3) & 0x70);
                ldsm_x4(ah[mt], st + G1_AOFF + off);
            }
            const int bn = (lane & 7) + ((lane >> 4) & 1) * 8;
            const int bk = ks * 16 + ((lane >> 3) & 1) * 8;
#pragma unroll
            for (int np = 0; np < 2; np++) {
                uint32_t off = (uint32_t)((wn * 32 + np * 16 + bn) * 128 + bk * 2);
                off ^= ((off >> 3) & 0x70);
                ldsm_x4(bh[np], st + G1_BOFF + off);
            }
#pragma unroll
            for (int mt = 0; mt < 4; mt++)
#pragma unroll
                for (int nt = 0; nt < 4; nt++)
                    mma_f16(acc[mt][nt], ah[mt], &bh[nt >> 1][(nt & 1) * 2]);
        }
        __syncthreads();
    }
#undef ISSUE_STAGE1

#pragma unroll
    for (int mt = 0; mt < 4; mt++) {
        const int row = m0 + wm * 64 + mt * 16 + (lane >> 2);
#pragma unroll
        for (int nt = 0; nt < 4; nt++) {
            const int col = n0 + wn * 32 + nt * 8 + (lane & 3) * 2;
            const float bx = __ldg(bias + col), by = __ldg(bias + col + 1);
            *(float2*)(Cf + (size_t)row * 1024 + col) =
                make_float2(acc[mt][nt][0] + bx, acc[mt][nt][1] + by);
            *(float2*)(Cf + (size_t)(row + 8) * 1024 + col) =
                make_float2(acc[mt][nt][2] + bx, acc[mt][nt][3] + by);
        }
    }
}

// ----------------------------- MMA flash attention (fp16) ------------------
#define ATT_KOFF  0
#define ATT_VOFF  8192
#define ATT_STAGE 16384
#define ATT_QOFF  (2*ATT_STAGE)          // 32768
#define ATT_SMEM  (ATT_QOFF + 8192)      // 40960

__global__ void __launch_bounds__(128) attn_mma_kernel(
    const __half* __restrict__ Q,
    const __half* __restrict__ K,
    const __half* __restrict__ V,
    __half* __restrict__ A)
{
    extern __shared__ char sm[];
    const uint32_t sb = smem_u32(sm);
    const int tid = threadIdx.x;
    const int lane = tid & 31, wid = tid >> 5;
    const int b = blockIdx.z, h = blockIdx.y;
    const int q0 = blockIdx.x * 64;

    const size_t qbase = ((size_t)(b * SEQQ + q0)) * EMBED + h * HDIM;
#pragma unroll
    for (int c = 0; c < 4; c++) {
        const int idx = c * 128 + tid;
        const int row = idx >> 3, seg = idx & 7;
        uint32_t off = (uint32_t)(row * 128 + seg * 16);
        off ^= ((off >> 3) & 0x70);
        CP_ASYNC16(sb + ATT_QOFF + off,
                   (const char*)(Q + qbase + (size_t)row * 1024 + seg * 8));
    }
    CP_COMMIT();

#define ISSUE_KV(buf, kt)                                                      \
    do {                                                                       \
        const uint32_t st_ = sb + (buf) * ATT_STAGE;                           \
        const size_t kb = ((size_t)(b * SEQK + (kt) * 64)) * EMBED + h * HDIM; \
        _Pragma("unroll")                                                      \
        for (int c = 0; c < 4; c++) {                                          \
            const int idx = c * 128 + tid;                                     \
            const int row = idx >> 3, seg = idx & 7;                           \
            uint32_t off = (uint32_t)(row * 128 + seg * 16);                   \
            off ^= ((off >> 3) & 0x70);                                        \
            const size_t g = kb + (size_t)row * 1024 + seg * 8;                \
            CP_ASYNC16(st_ + ATT_KOFF + off, (const char*)(K + g));            \
            CP_ASYNC16(st_ + ATT_VOFF + off, (const char*)(V + g));            \
        }                                                                      \
    } while (0)

    ISSUE_KV(0, 0);
    CP_COMMIT();
    CP_WAIT(1);
    __syncthreads();

    uint32_t qh[4][4];
    {
        const int ar = (lane & 7) + ((lane >> 3) & 1) * 8;
#pragma unroll
        for (int ks = 0; ks < 4; ks++) {
            const int ak = ks * 16 + ((lane >> 4) & 1) * 8;
            uint32_t off = (uint32_t)((wid * 16 + ar) * 128 + ak * 2);
            off ^= ((off >> 3) & 0x70);
            ldsm_x4(qh[ks], sb + ATT_QOFF + off);
        }
    }

    const uint32_t onefrag = ((lane >> 2) == 0) ? 0x3C003C00u : 0u;
    const uint32_t ones2[2] = { onefrag, onefrag };

    float m0 = -1e30f, m1 = -1e30f;
    float oacc[9][4];
#pragma unroll
    for (int nt = 0; nt < 9; nt++)
#pragma unroll
        for (int k = 0; k < 4; k++) oacc[nt][k] = 0.f;

    for (int kt = 0; kt < 32; kt++) {
        if (kt < 31) {
            ISSUE_KV((kt + 1) & 1, kt + 1);
            CP_COMMIT();
            CP_WAIT(1);
        } else {
            CP_WAIT(0);
        }
        __syncthreads();
        const uint32_t st = sb + (kt & 1) * ATT_STAGE;

        float sacc[8][4];
#pragma unroll
        for (int nt = 0; nt < 8; nt++)
#pragma unroll
            for (int k = 0; k < 4; k++) sacc[nt][k] = 0.f;

#pragma unroll
        for (int ks = 0; ks < 4; ks++) {
            uint32_t kh[4][4];
            const int bn = (lane & 7) + ((lane >> 4) & 1) * 8;
            const int bk = ks * 16 + ((lane >> 3) & 1) * 8;
#pragma unroll
            for (int g = 0; g < 4; g++) {
                uint32_t off = (uint32_t)((g * 16 + bn) * 128 + bk * 2);
                off ^= ((off >> 3) & 0x70);
                ldsm_x4(kh[g], st + ATT_KOFF + off);
            }
#pragma unroll
            for (int nt = 0; nt < 8; nt++)
                mma_f16(sacc[nt], qh[ks], &kh[nt >> 1][(nt & 1) * 2]);
        }

        float mx0 = sacc[0][0], mx1 = sacc[0][2];
#pragma unroll
        for (int nt = 0; nt < 8; nt++) {
            mx0 = fmaxf(mx0, fmaxf(sacc[nt][0], sacc[nt][1]));
            mx1 = fmaxf(mx1, fmaxf(sacc[nt][2], sacc[nt][3]));
        }
        mx0 = fmaxf(mx0, __shfl_xor_sync(0xffffffffu, mx0, 1));
        mx0 = fmaxf(mx0, __shfl_xor_sync(0xffffffffu, mx0, 2));
        mx1 = fmaxf(mx1, __shfl_xor_sync(0xffffffffu, mx1, 1));
        mx1 = fmaxf(mx1, __shfl_xor_sync(0xffffffffu, mx1, 2));
        const bool nochange = (mx0 <= m0) && (mx1 <= m1);
        const float mn0 = fmaxf(m0, mx0), mn1 = fmaxf(m1, mx1);

        if (__all_sync(0xffffffffu, nochange)) {
            // max unchanged for every row in the warp: skip rescale entirely
            m0 = mn0; m1 = mn1;
        } else {
            const float a0 = ex2f(m0 - mn0), a1 = ex2f(m1 - mn1);
            m0 = mn0; m1 = mn1;
#pragma unroll
            for (int nt = 0; nt < 9; nt++) {
                oacc[nt][0] *= a0; oacc[nt][1] *= a0;
                oacc[nt][2] *= a1; oacc[nt][3] *= a1;
            }
        }

        uint32_t ph[4][4];
#pragma unroll
        for (int kf = 0; kf < 4; kf++) {
            ph[kf][0] = ex2_h2(sacc[2*kf][0]   - m0, sacc[2*kf][1]   - m0);
            ph[kf][1] = ex2_h2(sacc[2*kf][2]   - m1, sacc[2*kf][3]   - m1);
            ph[kf][2] = ex2_h2(sacc[2*kf+1][0] - m0, sacc[2*kf+1][1] - m0);
            ph[kf][3] = ex2_h2(sacc[2*kf+1][2] - m1, sacc[2*kf+1][3] - m1);
        }

#pragma unroll
        for (int ks = 0; ks < 4; ks++) {
            uint32_t vh[4][4];
            const int vk = ((lane >> 3) & 1) * 8 + (lane & 7);
            const int vd = ((lane >> 4) & 1) * 8;
#pragma unroll
            for (int dp = 0; dp < 4; dp++) {
                uint32_t off = (uint32_t)((ks * 16 + vk) * 128 + (dp * 16 + vd) * 2);
                off ^= ((off >> 3) & 0x70);
                ldsm_x4_t(vh[dp], st + ATT_VOFF + off);
            }
#pragma unroll
            for (int nt = 0; nt < 8; nt++)
                mma_f16(oacc[nt], ph[ks], &vh[nt >> 1][(nt & 1) * 2]);
            mma_f16(oacc[8], ph[ks], ones2);
        }
        __syncthreads();
    }
#undef ISSUE_KV

    const int src = lane & ~3;
    const float l0 = __shfl_sync(0xffffffffu, oacc[8][0], src);
    const float l1 = __shfl_sync(0xffffffffu, oacc[8][2], src);

    const float inv0 = 1.f / l0, inv1 = 1.f / l1;
    const size_t row0 = (size_t)(b * SEQQ + q0 + wid * 16 + (lane >> 2));
    const size_t row1 = row0 + 8;
    const int colb = h * HDIM + (lane & 3) * 2;
#pragma unroll
    for (int nt = 0; nt < 8; nt++) {
        const int col = colb + nt * 8;
        *(uint32_t*)(A + row0 * 1024 + col) = pack_h2(oacc[nt][0] * inv0, oacc[nt][1] * inv0);
        *(uint32_t*)(A + row1 * 1024 + col) = pack_h2(oacc[nt][2] * inv1, oacc[nt][3] * inv1);
    }
}

// ---------------------------------------------------------------------------
extern "C" void kernel_launch(void* const* d_in, const int* in_sizes, int n_in,
                              void* d_out, int out_size)
{
    const float* Qin = (const float*)d_in[0];
    const float* Kin = (const float*)d_in[1];
    const float* Vin = (const float*)d_in[2];
    const float* Wq  = (const float*)d_in[3];
    const float* bq  = (const float*)d_in[4];
    const float* Wk  = (const float*)d_in[5];
    const float* bk  = (const float*)d_in[6];
    const float* Wv  = (const float*)d_in[7];
    const float* bv  = (const float*)d_in[8];
    const float* Wo  = (const float*)d_in[9];
    const float* bo  = (const float*)d_in[10];
    float* out = (float*)d_out;

    __half *xqH,*xqL,*xkH,*xkL,*xv;
    __half *wq,*wk,*wv,*wo;
    __half *q,*k,*v,*a;
    cudaGetSymbolAddress((void**)&xqH, g_XqH); cudaGetSymbolAddress((void**)&xqL, g_XqL);
    cudaGetSymbolAddress((void**)&xkH, g_XkH); cudaGetSymbolAddress((void**)&xkL, g_XkL);
    cudaGetSymbolAddress((void**)&xv,  g_Xv);
    cudaGetSymbolAddress((void**)&wq, g_Wq); cudaGetSymbolAddress((void**)&wk, g_Wk);
    cudaGetSymbolAddress((void**)&wv, g_Wv); cudaGetSymbolAddress((void**)&wo, g_Wo);
    cudaGetSymbolAddress((void**)&q,  g_Q);  cudaGetSymbolAddress((void**)&k,  g_K);
    cudaGetSymbolAddress((void**)&v,  g_V);  cudaGetSymbolAddress((void**)&a,  g_A);

    cudaFuncSetAttribute(gemm_mma_kernel,  cudaFuncAttributeMaxDynamicSharedMemorySize, GB_SMEM);
    cudaFuncSetAttribute(gemm1_mma_kernel, cudaFuncAttributeMaxDynamicSharedMemorySize, G1_SMEM);
    cudaFuncSetAttribute(attn_mma_kernel,  cudaFuncAttributeMaxDynamicSharedMemorySize, ATT_SMEM);

    const int nAct4 = MROWS * EMBED / 4;   // 1048576
    const int nW4   = EMBED * EMBED / 4;   // 262144

    PrepJob p0 = { Qin, xqH, xqL, nAct4 };
    PrepJob p1 = { Kin, xkH, xkL, nAct4 };
    PrepJob p2 = { Vin, xv, nullptr, nAct4 };   // V input plain fp16
    PrepJob p3 = { Wq, wq, nullptr, nW4 };
    PrepJob p4 = { Wk, wk, nullptr, nW4 };
    PrepJob p5 = { Wv, wv, nullptr, nW4 };
    PrepJob p6 = { Wo, wo, nullptr, nW4 };
    dim3 prep_grid((nAct4 + 255) / 256, 7);
    prep_kernel<<<prep_grid, 256>>>(p0, p1, p2, p3, p4, p5, p6);

    const float qscale = 0.125f * 1.4426950408889634f;   // 1/sqrt(64) * log2(e)

    GemmArgs argQ = { xqH, xqL, wq, bq, nullptr, q, qscale };
    GemmArgs argK = { xkH, xkL, wk, bk, nullptr, k, 1.0f };
    GemmArgs argV = { xv,  nullptr, wv, bv, nullptr, v, 1.0f };   // 1-term

    dim3 qkv_grid(EMBED / 128, MROWS / 128, 3);   // (8, 32, 3)
    gemm_mma_kernel<<<qkv_grid, 256, GB_SMEM>>>(argQ, argK, argV);

    dim3 attn_grid(SEQQ / 64, NHEAD, BATCH);      // (32, 16, 2)
    attn_mma_kernel<<<attn_grid, 128, ATT_SMEM>>>(q, k, v, a);

    dim3 o_grid(EMBED / 128, MROWS / 128);        // (8, 32)
    gemm1_mma_kernel<<<o_grid, 256, G1_SMEM>>>(a, wo, bo, out);
}